// round 7
// baseline (speedup 1.0000x reference)
#include <cuda_runtime.h>
#include <cuda_bf16.h>
#include <math_constants.h>
#include <cstdint>

// Problem constants
#define Bz  4
#define Tz  2048
#define Dz  2048
#define Hz  16
#define HDz 128
#define BHz (Bz*Hz)          // 64
#define Mz  (Bz*Tz)          // 8192

// ---------------------------------------------------------------------------
// Global scratch (device globals: allocation-free per harness rules)
// ---------------------------------------------------------------------------
__device__ __nv_bfloat16 g_qh[(size_t)BHz * Tz * HDz];  // post-rope, scaled
__device__ __nv_bfloat16 g_ql[(size_t)BHz * Tz * HDz];
__device__ __nv_bfloat16 g_kh[(size_t)BHz * Tz * HDz];
__device__ __nv_bfloat16 g_kl[(size_t)BHz * Tz * HDz];
__device__ __nv_bfloat16 g_vh[(size_t)BHz * Tz * HDz];
__device__ __nv_bfloat16 g_vl[(size_t)BHz * Tz * HDz];

__device__ __nv_bfloat16 g_xh [(size_t)Mz * Dz];
__device__ __nv_bfloat16 g_xl [(size_t)Mz * Dz];
__device__ __nv_bfloat16 g_wqh[(size_t)3 * Dz * Dz];
__device__ __nv_bfloat16 g_wql[(size_t)3 * Dz * Dz];
__device__ __nv_bfloat16 g_woh[(size_t)Dz * Dz];
__device__ __nv_bfloat16 g_wol[(size_t)Dz * Dz];
__device__ __nv_bfloat16 g_oh [(size_t)Mz * Dz];   // attention out hi/lo
__device__ __nv_bfloat16 g_ol [(size_t)Mz * Dz];

// ---------------------------------------------------------------------------
// PTX helpers (base sm_100 — NO 'a'-gated instructions)
// ---------------------------------------------------------------------------
__device__ __forceinline__ uint32_t smem_u32(const void* p) {
    uint32_t a;
    asm("{ .reg .u64 t; cvta.to.shared.u64 t, %1; cvt.u32.u64 %0, t; }"
        : "=r"(a) : "l"(p));
    return a;
}

#define CP16(saddr, gptr) \
    asm volatile("cp.async.cg.shared.global [%0], [%1], 16;" \
                 :: "r"(saddr), "l"(gptr) : "memory")
#define CP_COMMIT() asm volatile("cp.async.commit_group;" ::: "memory")
#define CP_WAIT(n)  asm volatile("cp.async.wait_group %0;" :: "n"(n) : "memory")

#define LDSM4(r0, r1, r2, r3, a) \
    asm volatile("ldmatrix.sync.aligned.m8n8.x4.shared.b16 {%0,%1,%2,%3}, [%4];" \
                 : "=r"(r0), "=r"(r1), "=r"(r2), "=r"(r3) : "r"(a))
#define LDSM4T(r0, r1, r2, r3, a) \
    asm volatile("ldmatrix.sync.aligned.m8n8.x4.trans.shared.b16 {%0,%1,%2,%3}, [%4];" \
                 : "=r"(r0), "=r"(r1), "=r"(r2), "=r"(r3) : "r"(a))

#define MMA_BF16(d, a, b) \
    asm volatile("mma.sync.aligned.m16n8k16.row.col.f32.bf16.bf16.f32 " \
                 "{%0,%1,%2,%3}, {%4,%5,%6,%7}, {%8,%9}, {%0,%1,%2,%3};" \
                 : "+f"((d)[0]), "+f"((d)[1]), "+f"((d)[2]), "+f"((d)[3]) \
                 : "r"((a)[0]), "r"((a)[1]), "r"((a)[2]), "r"((a)[3]), \
                   "r"((b)[0]), "r"((b)[1]))

#define MMA4(d, a0, a1, a2, a3, b0, b1) \
    asm volatile("mma.sync.aligned.m16n8k16.row.col.f32.bf16.bf16.f32 " \
                 "{%0,%1,%2,%3}, {%4,%5,%6,%7}, {%8,%9}, {%0,%1,%2,%3};" \
                 : "+f"((d)[0]), "+f"((d)[1]), "+f"((d)[2]), "+f"((d)[3]) \
                 : "r"(a0), "r"(a1), "r"(a2), "r"(a3), "r"(b0), "r"(b1))

// Split pair of floats into packed bf16 hi + bf16 lo (residual)
__device__ __forceinline__ void split2(float x, float y, uint32_t& hi, uint32_t& lo) {
    __nv_bfloat16 hx = __float2bfloat16_rn(x);
    __nv_bfloat16 hy = __float2bfloat16_rn(y);
    __nv_bfloat162 H; H.x = hx; H.y = hy;
    hi = *(uint32_t*)&H;
    __nv_bfloat162 L;
    L.x = __float2bfloat16_rn(x - __bfloat162float(hx));
    L.y = __float2bfloat16_rn(y - __bfloat162float(hy));
    lo = *(uint32_t*)&L;
}

// ---------------------------------------------------------------------------
// Split fp32 -> bf16 hi + lo.  W=0: x, W=1: w_qkv, W=2: w_out.
// ---------------------------------------------------------------------------
template<int W>
__global__ void split_kernel(const float* __restrict__ src)
{
    __nv_bfloat16* hi; __nv_bfloat16* lo;
    if (W == 0)      { hi = g_xh;  lo = g_xl;  }
    else if (W == 1) { hi = g_wqh; lo = g_wql; }
    else             { hi = g_woh; lo = g_wol; }

    size_t i = ((size_t)blockIdx.x * 256 + threadIdx.x) * 4;
    float4 v = *(const float4*)(src + i);
    uint32_t h0, l0, h1, l1;
    split2(v.x, v.y, h0, l0);
    split2(v.z, v.w, h1, l1);
    *(uint32_t*)(hi + i)     = h0;
    *(uint32_t*)(hi + i + 2) = h1;
    *(uint32_t*)(lo + i)     = l0;
    *(uint32_t*)(lo + i + 2) = l1;
}

// ---------------------------------------------------------------------------
// bf16x3 tensor-core GEMM.  C = A * B^T.  256x128 CTA tile, 8 warps (4x2),
// warp tile 64x64, K-chunk 32, 3-stage cp.async pipeline, 1 CTA/SM.
// RPITCH=80 (5x16B chunks/row: conflict-free ldmatrix without swizzle).
// MODE 0: A=x, B=w_qkv; epilogue: q,k -> fused RoPE + bf16 hi/lo split;
//         v -> bf16 hi/lo.
// MODE 1: A=g_oh/g_ol, B=w_out; epilogue writes C (fp32).
// ---------------------------------------------------------------------------
#define RPITCH   80
#define ABUF     (256 * RPITCH)          // 20480
#define BBUF     (128 * RPITCH)          // 10240
#define STAGEB   (2 * ABUF + 2 * BBUF)   // 61440
#define NSTAGE   3
#define GSMEM    (NSTAGE * STAGEB)       // 184320 (epilogue Sf needs 256*132*4=135168)

template<int MODE>
__global__ __launch_bounds__(256, 1)
void mma_gemm(float* __restrict__ C,
              const float* __restrict__ cosT,
              const float* __restrict__ sinT)
{
    extern __shared__ char smc[];
    const uint32_t sb = smem_u32(smc);
    const int tid = threadIdx.x;
    const int wid = tid >> 5;
    const int lid = tid & 31;
    const int wm  = wid >> 1;         // 0..3  (64 rows each)
    const int wn  = wid & 1;          // 0..1  (64 cols each)
    const int m0  = blockIdx.y * 256;
    const int n0  = blockIdx.x * 128;

    const __nv_bfloat16* Ah = ((MODE == 0) ? g_xh  : g_oh ) + (size_t)m0 * 2048;
    const __nv_bfloat16* Al = ((MODE == 0) ? g_xl  : g_ol ) + (size_t)m0 * 2048;
    const __nv_bfloat16* Bh = ((MODE == 0) ? g_wqh : g_woh) + (size_t)n0 * 2048;
    const __nv_bfloat16* Bl = ((MODE == 0) ? g_wql : g_wol) + (size_t)n0 * 2048;

    // cp.async mapping: A row = tid (256 rows, 4 chunks each);
    // B row = tid>>1 (128 rows, 2 chunks per thread).
    const int brw = tid >> 1;
    const int bc2 = (tid & 1) * 2;

    auto load_chunk = [&](uint32_t st, int kc) {
        const size_t gA = (size_t)tid * 2048 + kc * 32;
        const uint32_t sA = st + (uint32_t)tid * RPITCH;
#pragma unroll
        for (int ch = 0; ch < 4; ++ch) {
            CP16(sA + ch * 16,        Ah + gA + ch * 8);
            CP16(sA + ABUF + ch * 16, Al + gA + ch * 8);
        }
        const size_t gB = (size_t)brw * 2048 + kc * 32 + bc2 * 8;
        const uint32_t sB = st + 2 * ABUF + (uint32_t)brw * RPITCH + bc2 * 16;
        CP16(sB,             Bh + gB);
        CP16(sB + 16,        Bh + gB + 8);
        CP16(sB + BBUF,      Bl + gB);
        CP16(sB + BBUF + 16, Bl + gB + 8);
    };

    float d[4][8][4];
#pragma unroll
    for (int i = 0; i < 4; i++)
#pragma unroll
        for (int j = 0; j < 8; j++)
#pragma unroll
            for (int k = 0; k < 4; k++) d[i][j][k] = 0.f;

#pragma unroll
    for (int s = 0; s < NSTAGE; s++) {
        load_chunk(sb + s * STAGEB, s);
        CP_COMMIT();
    }

    const int q  = lid >> 3;
    const int r8 = lid & 7;
    const int arow  = wm * 64 + (q & 1) * 8 + r8;
    const int brow0 = wn * 64 + (q >> 1) * 8 + r8;

    for (int c = 0; c < 64; ++c) {
        CP_WAIT(2);
        __syncthreads();
        const uint32_t st  = sb + (c % NSTAGE) * STAGEB;
        const uint32_t sAh = st;
        const uint32_t sAl = st + ABUF;
        const uint32_t sBh = st + 2 * ABUF;
        const uint32_t sBl = st + 2 * ABUF + BBUF;

#pragma unroll
        for (int kk = 0; kk < 2; ++kk) {
            const uint32_t aoff = (uint32_t)(arow * RPITCH + (kk * 2 + (q >> 1)) * 16);
            const uint32_t boff = (uint32_t)(brow0 * RPITCH + (kk * 2 + (q & 1)) * 16);

            // hi A frags + hi B frags, then hi*hi
            uint32_t ah[4][4], bb[8][2];
#pragma unroll
            for (int mi = 0; mi < 4; ++mi)
                LDSM4(ah[mi][0], ah[mi][1], ah[mi][2], ah[mi][3],
                      sAh + aoff + mi * 16 * RPITCH);
#pragma unroll
            for (int nf = 0; nf < 4; ++nf) {
                uint32_t t0,t1,t2,t3;
                LDSM4(t0,t1,t2,t3, sBh + boff + nf * 16 * RPITCH);
                bb[2*nf][0]=t0; bb[2*nf][1]=t1; bb[2*nf+1][0]=t2; bb[2*nf+1][1]=t3;
            }
#pragma unroll
            for (int mi = 0; mi < 4; ++mi)
#pragma unroll
                for (int ni = 0; ni < 8; ++ni)
                    MMA_BF16(d[mi][ni], ah[mi], bb[ni]);

            // lo A frags, lo*hi (al scoped so it dies before bl loads)
            {
                uint32_t al[4][4];
#pragma unroll
                for (int mi = 0; mi < 4; ++mi)
                    LDSM4(al[mi][0], al[mi][1], al[mi][2], al[mi][3],
                          sAl + aoff + mi * 16 * RPITCH);
#pragma unroll
                for (int mi = 0; mi < 4; ++mi)
#pragma unroll
                    for (int ni = 0; ni < 8; ++ni)
                        MMA_BF16(d[mi][ni], al[mi], bb[ni]);
            }

            // lo B frags (reuse bb), hi*lo
#pragma unroll
            for (int nf = 0; nf < 4; ++nf) {
                uint32_t t0,t1,t2,t3;
                LDSM4(t0,t1,t2,t3, sBl + boff + nf * 16 * RPITCH);
                bb[2*nf][0]=t0; bb[2*nf][1]=t1; bb[2*nf+1][0]=t2; bb[2*nf+1][1]=t3;
            }
#pragma unroll
            for (int mi = 0; mi < 4; ++mi)
#pragma unroll
                for (int ni = 0; ni < 8; ++ni)
                    MMA_BF16(d[mi][ni], ah[mi], bb[ni]);
        }
        __syncthreads();

        const int nc = c + NSTAGE;
        if (nc < 64)
            load_chunk(sb + (c % NSTAGE) * STAGEB, nc);
        CP_COMMIT();
    }

    CP_WAIT(0);
    __syncthreads();

    // Stage fp32 tile in SMEM (pitch 132)
    float* Sf = (float*)smc;
#pragma unroll
    for (int mi = 0; mi < 4; ++mi) {
        const int r0 = wm * 64 + mi * 16 + (lid >> 2);
#pragma unroll
        for (int ni = 0; ni < 8; ++ni) {
            const int c0 = wn * 64 + ni * 8 + (lid & 3) * 2;
            Sf[r0 * 132 + c0]           = d[mi][ni][0];
            Sf[r0 * 132 + c0 + 1]       = d[mi][ni][1];
            Sf[(r0 + 8) * 132 + c0]     = d[mi][ni][2];
            Sf[(r0 + 8) * 132 + c0 + 1] = d[mi][ni][3];
        }
    }
    __syncthreads();

    if (MODE == 1) {
#pragma unroll
        for (int rr = 0; rr < 32; ++rr) {
            const int row = wid * 32 + rr;
            float4 v = *(const float4*)&Sf[row * 132 + lid * 4];
            *(float4*)(C + (size_t)(m0 + row) * 2048 + n0 + lid * 4) = v;
        }
    } else {
        const int qmode = n0 >> 11;              // 0:q 1:k 2:v
        const int h     = (n0 & 2047) >> 7;
        const int b     = m0 >> 11;
        const int t0    = m0 & 2047;
        const int bhx   = b * Hz + h;
        if (qmode == 2) {
            __nv_bfloat16* dh = g_vh + ((size_t)bhx * Tz + t0) * HDz;
            __nv_bfloat16* dl = g_vl + ((size_t)bhx * Tz + t0) * HDz;
#pragma unroll
            for (int rr = 0; rr < 32; ++rr) {
                const int row = wid * 32 + rr;
                float4 v = *(const float4*)&Sf[row * 132 + lid * 4];
                uint32_t h0, l0, h1, l1;
                split2(v.x, v.y, h0, l0);
                split2(v.z, v.w, h1, l1);
                *(uint32_t*)(dh + (size_t)row * HDz + lid * 4)     = h0;
                *(uint32_t*)(dh + (size_t)row * HDz + lid * 4 + 2) = h1;
                *(uint32_t*)(dl + (size_t)row * HDz + lid * 4)     = l0;
                *(uint32_t*)(dl + (size_t)row * HDz + lid * 4 + 2) = l1;
            }
        } else {
            // Fused RoPE: rotate pairs (d, d+64), scale q, split to bf16 hi/lo
            const bool isq = (qmode == 0);
            __nv_bfloat16* dh = (isq ? g_qh : g_kh) + ((size_t)bhx * Tz + t0) * HDz;
            __nv_bfloat16* dl = (isq ? g_ql : g_kl) + ((size_t)bhx * Tz + t0) * HDz;
            const int row = tid;                 // one row per thread (256 rows)
            const int t   = t0 + row;
            const float sc = isq ? 0.08838834764831845f : 1.0f;
            const float* crow_ = cosT + t * HDz;
            const float* srow_ = sinT + t * HDz;
            const float* Sr = Sf + row * 132;
            __nv_bfloat16* ph = dh + (size_t)row * HDz;
            __nv_bfloat16* pl = dl + (size_t)row * HDz;
#pragma unroll
            for (int dd = 0; dd < 64; dd += 2) {
                float c0 = crow_[dd], c1 = crow_[dd + 1];
                float s0 = srow_[dd], s1 = srow_[dd + 1];
                float x0 = Sr[dd],      x1 = Sr[dd + 1];
                float y0 = Sr[dd + 64], y1 = Sr[dd + 65];
                float r0 = (x0 * c0 - y0 * s0) * sc;
                float r1 = (x1 * c1 - y1 * s1) * sc;
                float u0 = (y0 * c0 + x0 * s0) * sc;
                float u1 = (y1 * c1 + x1 * s1) * sc;
                uint32_t hi, lo;
                split2(r0, r1, hi, lo);
                *(uint32_t*)(ph + dd)      = hi;
                *(uint32_t*)(pl + dd)      = lo;
                split2(u0, u1, hi, lo);
                *(uint32_t*)(ph + dd + 64) = hi;
                *(uint32_t*)(pl + dd + 64) = lo;
            }
        }
    }
}

// ---------------------------------------------------------------------------
// Causal flash attention on tensor cores (bf16x3).
// BM=128 (8 warps x 16 rows), BN=64, HD=128, 256 threads.
// Q hi/lo resident in SMEM; K/V hi/lo double-buffered cp.async.
// Row pitch 136 bf16 (272B = 17 x 16B chunks -> conflict-free ldmatrix).
// ---------------------------------------------------------------------------
#define AP    136
#define APB   272
#define QSZ   (128 * APB)       // 34816
#define KSZ   (64 * APB)        // 17408
#define ATTN_SMEM2 (2 * QSZ + 2 * 4 * KSZ)   // 208896

__global__ __launch_bounds__(256, 1)
void attn_mma()
{
    extern __shared__ char smc[];
    const uint32_t sb = smem_u32(smc);
    const int tid = threadIdx.x;
    const int wid = tid >> 5;
    const int lid = tid & 31;
    const int bh  = blockIdx.y;
    const int qb  = (int)gridDim.x - 1 - (int)blockIdx.x;  // big blocks first
    const int q0  = qb * 128;
    const int ntiles = 2 * qb + 2;

    const __nv_bfloat16* qh_g = g_qh + ((size_t)bh * Tz + q0) * HDz;
    const __nv_bfloat16* ql_g = g_ql + ((size_t)bh * Tz + q0) * HDz;
    const __nv_bfloat16* kh_g = g_kh + (size_t)bh * Tz * HDz;
    const __nv_bfloat16* kl_g = g_kl + (size_t)bh * Tz * HDz;
    const __nv_bfloat16* vh_g = g_vh + (size_t)bh * Tz * HDz;
    const __nv_bfloat16* vl_g = g_vl + (size_t)bh * Tz * HDz;

    const uint32_t sQh = sb;
    const uint32_t sQl = sb + QSZ;
    const uint32_t sStage = sb + 2 * QSZ;

#pragma unroll
    for (int i = 0; i < 8; ++i) {
        int cc = i * 256 + tid;
        int row = cc >> 4, col = cc & 15;
        CP16(sQh + row * APB + col * 16, qh_g + (size_t)row * HDz + col * 8);
    }
#pragma unroll
    for (int i = 0; i < 8; ++i) {
        int cc = i * 256 + tid;
        int row = cc >> 4, col = cc & 15;
        CP16(sQl + row * APB + col * 16, ql_g + (size_t)row * HDz + col * 8);
    }
    CP_COMMIT();

    auto load_stage = [&](int stage, int j0) {
        const uint32_t base = sStage + stage * (4 * KSZ);
        const __nv_bfloat16* gp0 = kh_g + (size_t)j0 * HDz;
        const __nv_bfloat16* gp1 = kl_g + (size_t)j0 * HDz;
        const __nv_bfloat16* gp2 = vh_g + (size_t)j0 * HDz;
        const __nv_bfloat16* gp3 = vl_g + (size_t)j0 * HDz;
#pragma unroll
        for (int i = 0; i < 4; ++i) {
            int cc = i * 256 + tid;
            int row = cc >> 4, col = cc & 15;
            uint32_t so = (uint32_t)(row * APB + col * 16);
            size_t go = (size_t)row * HDz + col * 8;
            CP16(base + so,           gp0 + go);
            CP16(base + KSZ + so,     gp1 + go);
            CP16(base + 2*KSZ + so,   gp2 + go);
            CP16(base + 3*KSZ + so,   gp3 + go);
        }
    };

    load_stage(0, 0);
    CP_COMMIT();

    const int qq = lid >> 3;
    const int r8 = lid & 7;
    const int g  = lid >> 2;
    const int t4 = lid & 3;
    const uint32_t qa_off  = (uint32_t)((wid * 16 + (qq & 1) * 8 + r8) * APB);
    const uint32_t ka_row  = (uint32_t)(((qq >> 1) * 8 + r8) * APB);
    const uint32_t va_off  = (uint32_t)((((lid >> 3) & 1) * 8 + (lid & 7)) * APB
                                        + (lid >> 4) * 16);

    float m0v = -1e30f, m1v = -1e30f, l0v = 0.f, l1v = 0.f;
    float o[16][4];
#pragma unroll
    for (int i = 0; i < 16; i++)
#pragma unroll
        for (int j = 0; j < 4; j++) o[i][j] = 0.f;

    for (int kt = 0; kt < ntiles; ++kt) {
        if (kt + 1 < ntiles) {
            load_stage((kt + 1) & 1, (kt + 1) * 64);
            CP_COMMIT();
            CP_WAIT(1);
        } else {
            CP_WAIT(0);
        }
        __syncthreads();

        const uint32_t sK  = sStage + (kt & 1) * (4 * KSZ);
        const uint32_t sKh = sK;
        const uint32_t sKl = sK + KSZ;
        const uint32_t sVh = sK + 2 * KSZ;
        const uint32_t sVl = sK + 3 * KSZ;

        const bool active = !(kt == ntiles - 1 && wid < 4);
        if (active) {
            float sf[8][4];
#pragma unroll
            for (int i = 0; i < 8; i++)
#pragma unroll
                for (int j = 0; j < 4; j++) sf[i][j] = 0.f;

#pragma unroll
            for (int kk = 0; kk < 8; ++kk) {
                const uint32_t acol = (uint32_t)((kk * 2 + (qq >> 1)) * 16);
                const uint32_t kcol = (uint32_t)((kk * 2 + (qq & 1)) * 16);
                uint32_t ah0,ah1,ah2,ah3, al0,al1,al2,al3;
                LDSM4(ah0,ah1,ah2,ah3, sQh + qa_off + acol);
                LDSM4(al0,al1,al2,al3, sQl + qa_off + acol);
#pragma unroll
                for (int h2 = 0; h2 < 2; ++h2) {
                    uint32_t b0h[4], b1h[4], b0l[4], b1l[4];
                    const uint32_t r0 = (uint32_t)((2*h2) * 16 * APB);
                    const uint32_t r1 = (uint32_t)((2*h2 + 1) * 16 * APB);
                    LDSM4(b0h[0],b0h[1],b0h[2],b0h[3], sKh + ka_row + r0 + kcol);
                    LDSM4(b1h[0],b1h[1],b1h[2],b1h[3], sKh + ka_row + r1 + kcol);
                    LDSM4(b0l[0],b0l[1],b0l[2],b0l[3], sKl + ka_row + r0 + kcol);
                    LDSM4(b1l[0],b1l[1],b1l[2],b1l[3], sKl + ka_row + r1 + kcol);
                    MMA4(sf[4*h2+0], ah0,ah1,ah2,ah3, b0h[0], b0h[1]);
                    MMA4(sf[4*h2+1], ah0,ah1,ah2,ah3, b0h[2], b0h[3]);
                    MMA4(sf[4*h2+2], ah0,ah1,ah2,ah3, b1h[0], b1h[1]);
                    MMA4(sf[4*h2+3], ah0,ah1,ah2,ah3, b1h[2], b1h[3]);
                    MMA4(sf[4*h2+0], al0,al1,al2,al3, b0h[0], b0h[1]);
                    MMA4(sf[4*h2+1], al0,al1,al2,al3, b0h[2], b0h[3]);
                    MMA4(sf[4*h2+2], al0,al1,al2,al3, b1h[0], b1h[1]);
                    MMA4(sf[4*h2+3], al0,al1,al2,al3, b1h[2], b1h[3]);
                    MMA4(sf[4*h2+0], ah0,ah1,ah2,ah3, b0l[0], b0l[1]);
                    MMA4(sf[4*h2+1], ah0,ah1,ah2,ah3, b0l[2], b0l[3]);
                    MMA4(sf[4*h2+2], ah0,ah1,ah2,ah3, b1l[0], b1l[1]);
                    MMA4(sf[4*h2+3], ah0,ah1,ah2,ah3, b1l[2], b1l[3]);
                }
            }

            if (kt == ntiles - 2) {
                if (wid < 4) {
                    const int i0 = wid * 16 + g;
                    const int i1 = i0 + 8;
#pragma unroll
                    for (int ns = 0; ns < 8; ++ns) {
                        const int jc = ns * 8 + t4 * 2;
                        if (jc     > i0) sf[ns][0] = -1e30f;
                        if (jc + 1 > i0) sf[ns][1] = -1e30f;
                        if (jc     > i1) sf[ns][2] = -1e30f;
                        if (jc + 1 > i1) sf[ns][3] = -1e30f;
                    }
                }
            } else if (kt == ntiles - 1) {
                const int i0 = wid * 16 + g - 64;
                const int i1 = i0 + 8;
#pragma unroll
                for (int ns = 0; ns < 8; ++ns) {
                    const int jc = ns * 8 + t4 * 2;
                    if (jc     > i0) sf[ns][0] = -1e30f;
                    if (jc + 1 > i0) sf[ns][1] = -1e30f;
                    if (jc     > i1) sf[ns][2] = -1e30f;
                    if (jc + 1 > i1) sf[ns][3] = -1e30f;
                }
            }

            float rm0 = -1e30f, rm1 = -1e30f;
#pragma unroll
            for (int ns = 0; ns < 8; ++ns) {
                rm0 = fmaxf(rm0, fmaxf(sf[ns][0], sf[ns][1]));
                rm1 = fmaxf(rm1, fmaxf(sf[ns][2], sf[ns][3]));
            }
            rm0 = fmaxf(rm0, __shfl_xor_sync(0xffffffffu, rm0, 1));
            rm0 = fmaxf(rm0, __shfl_xor_sync(0xffffffffu, rm0, 2));
            rm1 = fmaxf(rm1, __shfl_xor_sync(0xffffffffu, rm1, 1));
            rm1 = fmaxf(rm1, __shfl_xor_sync(0xffffffffu, rm1, 2));
            const float mn0 = fmaxf(m0v, rm0);
            const float mn1 = fmaxf(m1v, rm1);
            const float corr0 = __expf(m0v - mn0);
            const float corr1 = __expf(m1v - mn1);
            m0v = mn0; m1v = mn1;
            float rs0 = 0.f, rs1 = 0.f;
#pragma unroll
            for (int ns = 0; ns < 8; ++ns) {
                float p0 = __expf(sf[ns][0] - mn0);
                float p1 = __expf(sf[ns][1] - mn0);
                float p2 = __expf(sf[ns][2] - mn1);
                float p3 = __expf(sf[ns][3] - mn1);
                sf[ns][0] = p0; sf[ns][1] = p1; sf[ns][2] = p2; sf[ns][3] = p3;
                rs0 += p0 + p1; rs1 += p2 + p3;
            }
            rs0 += __shfl_xor_sync(0xffffffffu, rs0, 1);
            rs0 += __shfl_xor_sync(0xffffffffu, rs0, 2);
            rs1 += __shfl_xor_sync(0xffffffffu, rs1, 1);
            rs1 += __shfl_xor_sync(0xffffffffu, rs1, 2);
            l0v = l0v * corr0 + rs0;
            l1v = l1v * corr1 + rs1;
#pragma unroll
            for (int ns = 0; ns < 16; ++ns) {
                o[ns][0] *= corr0; o[ns][1] *= corr0;
                o[ns][2] *= corr1; o[ns][3] *= corr1;
            }

            uint32_t pah[4][4], pal[4][4];
#pragma unroll
            for (int kk = 0; kk < 4; ++kk) {
                split2(sf[2*kk][0],   sf[2*kk][1],   pah[kk][0], pal[kk][0]);
                split2(sf[2*kk][2],   sf[2*kk][3],   pah[kk][1], pal[kk][1]);
                split2(sf[2*kk+1][0], sf[2*kk+1][1], pah[kk][2], pal[kk][2]);
                split2(sf[2*kk+1][2], sf[2*kk+1][3], pah[kk][3], pal[kk][3]);
            }

#pragma unroll
            for (int kk = 0; kk < 4; ++kk) {
                const uint32_t vrow = (uint32_t)(kk * 16 * APB) + va_off;
#pragma unroll
                for (int dp = 0; dp < 4; ++dp) {
                    uint32_t v0h[4], v1h[4], v0l[4], v1l[4];
                    LDSM4T(v0h[0],v0h[1],v0h[2],v0h[3], sVh + vrow + dp*64);
                    LDSM4T(v1h[0],v1h[1],v1h[2],v1h[3], sVh + vrow + dp*64 + 32);
                    LDSM4T(v0l[0],v0l[1],v0l[2],v0l[3], sVl + vrow + dp*64);
                    LDSM4T(v1l[0],v1l[1],v1l[2],v1l[3], sVl + vrow + dp*64 + 32);
                    MMA4(o[4*dp+0], pah[kk][0],pah[kk][1],pah[kk][2],pah[kk][3], v0h[0], v0h[1]);
                    MMA4(o[4*dp+1], pah[kk][0],pah[kk][1],pah[kk][2],pah[kk][3], v0h[2], v0h[3]);
                    MMA4(o[4*dp+2], pah[kk][0],pah[kk][1],pah[kk][2],pah[kk][3], v1h[0], v1h[1]);
                    MMA4(o[4*dp+3], pah[kk][0],pah[kk][1],pah[kk][2],pah[kk][3], v1h[2], v1h[3]);
                    MMA4(o[4*dp+0], pal[kk][0],pal[kk][1],pal[kk][2],pal[kk][3], v0h[0], v0h[1]);
                    MMA4(o[4*dp+1], pal[kk][0],pal[kk][1],pal[kk][2],pal[kk][3], v0h[2], v0h[3]);
                    MMA4(o[4*dp+2], pal[kk][0],pal[kk][1],pal[kk][2],pal[kk][3], v1h[0], v1h[1]);
                    MMA4(o[4*dp+3], pal[kk][0],pal[kk][1],pal[kk][2],pal[kk][3], v1h[2], v1h[3]);
                    MMA4(o[4*dp+0], pah[kk][0],pah[kk][1],pah[kk][2],pah[kk][3], v0l[0], v0l[1]);
                    MMA4(o[4*dp+1], pah[kk][0],pah[kk][1],pah[kk][2],pah[kk][3], v0l[2], v0l[3]);
                    MMA4(o[4*dp+2], pah[kk][0],pah[kk][1],pah[kk][2],pah[kk][3], v1l[0], v1l[1]);
                    MMA4(o[4*dp+3], pah[kk][0],pah[kk][1],pah[kk][2],pah[kk][3], v1l[2], v1l[3]);
                }
            }
        }
        __syncthreads();
    }

    const int b  = bh >> 4;
    const int hh = bh & 15;
    const float inv0 = 1.f / l0v;
    const float inv1 = 1.f / l1v;
    const size_t rb0 = ((size_t)b * Tz + q0 + wid * 16 + g) * Dz + hh * HDz;
    const size_t rb1 = rb0 + (size_t)8 * Dz;
#pragma unroll
    for (int ns = 0; ns < 16; ++ns) {
        const int dcol = ns * 8 + t4 * 2;
        uint32_t hi, lo;
        split2(o[ns][0] * inv0, o[ns][1] * inv0, hi, lo);
        *(uint32_t*)(g_oh + rb0 + dcol) = hi;
        *(uint32_t*)(g_ol + rb0 + dcol) = lo;
        split2(o[ns][2] * inv1, o[ns][3] * inv1, hi, lo);
        *(uint32_t*)(g_oh + rb1 + dcol) = hi;
        *(uint32_t*)(g_ol + rb1 + dcol) = lo;
    }
}

// ---------------------------------------------------------------------------
extern "C" void kernel_launch(void* const* d_in, const int* in_sizes, int n_in,
                              void* d_out, int out_size)
{
    const float* x     = (const float*)d_in[0];
    const float* cosT  = (const float*)d_in[1];
    const float* sinT  = (const float*)d_in[2];
    const float* w_qkv = (const float*)d_in[3];
    const float* w_out = (const float*)d_in[4];
    float* out = (float*)d_out;

    cudaFuncSetAttribute(mma_gemm<0>,
                         cudaFuncAttributeMaxDynamicSharedMemorySize, GSMEM);
    cudaFuncSetAttribute(mma_gemm<1>,
                         cudaFuncAttributeMaxDynamicSharedMemorySize, GSMEM);
    cudaFuncSetAttribute(attn_mma,
                         cudaFuncAttributeMaxDynamicSharedMemorySize, ATTN_SMEM2);

    // 0. Split inputs to bf16 hi/lo
    split_kernel<0><<<(Mz * Dz) / 1024, 256>>>(x);
    split_kernel<1><<<(3 * Dz * Dz) / 1024, 256>>>(w_qkv);
    split_kernel<2><<<(Dz * Dz) / 1024, 256>>>(w_out);

    // 1. QKV projection (bf16x3, 256x128 tiles) + fused RoPE/scale/split
    mma_gemm<0><<<dim3(48, 32), 256, GSMEM>>>(nullptr, cosT, sinT);

    // 2. Causal flash attention (bf16x3 tensor cores) -> o bf16 hi/lo
    attn_mma<<<dim3(Tz / 128, BHz), 256, ATTN_SMEM2>>>();

    // 3. Output projection (bf16x3, 256x128 tiles)
    mma_gemm<1><<<dim3(16, 32), 256, GSMEM>>>(out, nullptr, nullptr);
}

// round 8
// speedup vs baseline: 1.0935x; 1.0935x over previous
#include <cuda_runtime.h>
#include <cuda_bf16.h>
#include <math_constants.h>
#include <cstdint>

// Problem constants
#define Bz  4
#define Tz  2048
#define Dz  2048
#define Hz  16
#define HDz 128
#define BHz (Bz*Hz)          // 64
#define Mz  (Bz*Tz)          // 8192

// ---------------------------------------------------------------------------
// Global scratch (device globals: allocation-free per harness rules)
// ---------------------------------------------------------------------------
__device__ __nv_bfloat16 g_qh[(size_t)BHz * Tz * HDz];  // post-rope, scaled
__device__ __nv_bfloat16 g_ql[(size_t)BHz * Tz * HDz];
__device__ __nv_bfloat16 g_kh[(size_t)BHz * Tz * HDz];
__device__ __nv_bfloat16 g_kl[(size_t)BHz * Tz * HDz];
__device__ __nv_bfloat16 g_vh[(size_t)BHz * Tz * HDz];
__device__ __nv_bfloat16 g_vl[(size_t)BHz * Tz * HDz];

__device__ __nv_bfloat16 g_xh [(size_t)Mz * Dz];
__device__ __nv_bfloat16 g_xl [(size_t)Mz * Dz];
__device__ __nv_bfloat16 g_wqh[(size_t)3 * Dz * Dz];
__device__ __nv_bfloat16 g_wql[(size_t)3 * Dz * Dz];
__device__ __nv_bfloat16 g_woh[(size_t)Dz * Dz];
__device__ __nv_bfloat16 g_wol[(size_t)Dz * Dz];
__device__ __nv_bfloat16 g_oh [(size_t)Mz * Dz];   // attention out hi/lo
__device__ __nv_bfloat16 g_ol [(size_t)Mz * Dz];

// ---------------------------------------------------------------------------
// PTX helpers (base sm_100 — NO 'a'-gated instructions)
// ---------------------------------------------------------------------------
__device__ __forceinline__ uint32_t smem_u32(const void* p) {
    uint32_t a;
    asm("{ .reg .u64 t; cvta.to.shared.u64 t, %1; cvt.u32.u64 %0, t; }"
        : "=r"(a) : "l"(p));
    return a;
}

#define CP16(saddr, gptr) \
    asm volatile("cp.async.cg.shared.global [%0], [%1], 16;" \
                 :: "r"(saddr), "l"(gptr) : "memory")
#define CP_COMMIT() asm volatile("cp.async.commit_group;" ::: "memory")
#define CP_WAIT(n)  asm volatile("cp.async.wait_group %0;" :: "n"(n) : "memory")

#define LDSM4(r0, r1, r2, r3, a) \
    asm volatile("ldmatrix.sync.aligned.m8n8.x4.shared.b16 {%0,%1,%2,%3}, [%4];" \
                 : "=r"(r0), "=r"(r1), "=r"(r2), "=r"(r3) : "r"(a))
#define LDSM4T(r0, r1, r2, r3, a) \
    asm volatile("ldmatrix.sync.aligned.m8n8.x4.trans.shared.b16 {%0,%1,%2,%3}, [%4];" \
                 : "=r"(r0), "=r"(r1), "=r"(r2), "=r"(r3) : "r"(a))

#define MMA_BF16(d, a, b) \
    asm volatile("mma.sync.aligned.m16n8k16.row.col.f32.bf16.bf16.f32 " \
                 "{%0,%1,%2,%3}, {%4,%5,%6,%7}, {%8,%9}, {%0,%1,%2,%3};" \
                 : "+f"((d)[0]), "+f"((d)[1]), "+f"((d)[2]), "+f"((d)[3]) \
                 : "r"((a)[0]), "r"((a)[1]), "r"((a)[2]), "r"((a)[3]), \
                   "r"((b)[0]), "r"((b)[1]))

#define MMA4(d, a0, a1, a2, a3, b0, b1) \
    asm volatile("mma.sync.aligned.m16n8k16.row.col.f32.bf16.bf16.f32 " \
                 "{%0,%1,%2,%3}, {%4,%5,%6,%7}, {%8,%9}, {%0,%1,%2,%3};" \
                 : "+f"((d)[0]), "+f"((d)[1]), "+f"((d)[2]), "+f"((d)[3]) \
                 : "r"(a0), "r"(a1), "r"(a2), "r"(a3), "r"(b0), "r"(b1))

// Split pair of floats into packed bf16 hi + bf16 lo (residual)
__device__ __forceinline__ void split2(float x, float y, uint32_t& hi, uint32_t& lo) {
    __nv_bfloat16 hx = __float2bfloat16_rn(x);
    __nv_bfloat16 hy = __float2bfloat16_rn(y);
    __nv_bfloat162 H; H.x = hx; H.y = hy;
    hi = *(uint32_t*)&H;
    __nv_bfloat162 L;
    L.x = __float2bfloat16_rn(x - __bfloat162float(hx));
    L.y = __float2bfloat16_rn(y - __bfloat162float(hy));
    lo = *(uint32_t*)&L;
}

// ---------------------------------------------------------------------------
// Split fp32 -> bf16 hi + lo.  W=0: x, W=1: w_qkv, W=2: w_out.
// ---------------------------------------------------------------------------
template<int W>
__global__ void split_kernel(const float* __restrict__ src)
{
    __nv_bfloat16* hi; __nv_bfloat16* lo;
    if (W == 0)      { hi = g_xh;  lo = g_xl;  }
    else if (W == 1) { hi = g_wqh; lo = g_wql; }
    else             { hi = g_woh; lo = g_wol; }

    size_t i = ((size_t)blockIdx.x * 256 + threadIdx.x) * 4;
    float4 v = *(const float4*)(src + i);
    uint32_t h0, l0, h1, l1;
    split2(v.x, v.y, h0, l0);
    split2(v.z, v.w, h1, l1);
    *(uint32_t*)(hi + i)     = h0;
    *(uint32_t*)(hi + i + 2) = h1;
    *(uint32_t*)(lo + i)     = l0;
    *(uint32_t*)(lo + i + 2) = l1;
}

// ---------------------------------------------------------------------------
// bf16x3 tensor-core GEMM.  C = A * B^T.  128x128 CTA tile, 8 warps (2x4),
// warp tile 64x32, K-chunk 32, 4-stage cp.async pipeline (CUTLASS pattern:
// ONE __syncthreads per chunk; loads for chunk c+3 issued at top of iter c
// into the buffer consumed at iter c-1).  1 CTA/SM.
// RPITCH=80 (5x16B chunks/row: conflict-free ldmatrix without swizzle).
// MODE 0: A=x, B=w_qkv; epilogue: q,k -> fused RoPE + bf16 hi/lo split;
//         v -> bf16 hi/lo.
// MODE 1: A=g_oh/g_ol, B=w_out; epilogue writes C (fp32).
// ---------------------------------------------------------------------------
#define RPITCH   80
#define SBUF     (128 * RPITCH)          // 10240
#define STAGEB   (4 * SBUF)              // 40960
#define NSTAGE   4
#define GSMEM    (NSTAGE * STAGEB)       // 163840 (epilogue Sf needs 67584)

template<int MODE>
__global__ __launch_bounds__(256, 1)
void mma_gemm(float* __restrict__ C,
              const float* __restrict__ cosT,
              const float* __restrict__ sinT)
{
    extern __shared__ char smc[];
    const uint32_t sb = smem_u32(smc);
    const int tid = threadIdx.x;
    const int wid = tid >> 5;
    const int lid = tid & 31;
    const int wm  = wid & 1;          // 0..1  (64 rows each)
    const int wn  = wid >> 1;         // 0..3  (32 cols each)
    const int m0  = blockIdx.y * 128;
    const int n0  = blockIdx.x * 128;

    const __nv_bfloat16* Ah = ((MODE == 0) ? g_xh  : g_oh ) + (size_t)m0 * 2048;
    const __nv_bfloat16* Al = ((MODE == 0) ? g_xl  : g_ol ) + (size_t)m0 * 2048;
    const __nv_bfloat16* Bh = ((MODE == 0) ? g_wqh : g_woh) + (size_t)n0 * 2048;
    const __nv_bfloat16* Bl = ((MODE == 0) ? g_wql : g_wol) + (size_t)n0 * 2048;

    // cp.async thread mapping: row = tid>>1, two 16B chunks per thread
    const int crow = tid >> 1;
    const int cc0  = (tid & 1) * 2;
    const uint32_t soff = (uint32_t)(crow * RPITCH + cc0 * 16);

    auto load_chunk = [&](uint32_t st, int kc) {
        const size_t gi = (size_t)crow * 2048 + kc * 32 + cc0 * 8;
        CP16(st + soff,                Ah + gi);
        CP16(st + soff + 16,           Ah + gi + 8);
        CP16(st + SBUF + soff,         Al + gi);
        CP16(st + SBUF + soff + 16,    Al + gi + 8);
        CP16(st + 2*SBUF + soff,       Bh + gi);
        CP16(st + 2*SBUF + soff + 16,  Bh + gi + 8);
        CP16(st + 3*SBUF + soff,       Bl + gi);
        CP16(st + 3*SBUF + soff + 16,  Bl + gi + 8);
    };

    float d[4][4][4];
#pragma unroll
    for (int i = 0; i < 4; i++)
#pragma unroll
        for (int j = 0; j < 4; j++)
#pragma unroll
            for (int k = 0; k < 4; k++) d[i][j][k] = 0.f;

    // Prologue: NSTAGE-1 = 3 chunks in flight
#pragma unroll
    for (int s = 0; s < NSTAGE - 1; s++) {
        load_chunk(sb + s * STAGEB, s);
        CP_COMMIT();
    }

    const int q  = lid >> 3;
    const int r8 = lid & 7;
    const int arow = wm * 64 + (q & 1) * 8 + r8;
    const int bfr  = q >> 1;
    const int bch  = q & 1;
    const int brow0 = wn * 32 + bfr * 8 + r8;

    for (int c = 0; c < 64; ++c) {
        CP_WAIT(2);
        __syncthreads();

        // Issue loads for chunk c+3 into buffer (c+3)&3 == (c-1)&3, which all
        // warps finished consuming at iteration c-1 (guarded by the sync above).
        const int nc = c + NSTAGE - 1;
        if (nc < 64)
            load_chunk(sb + (nc & 3) * STAGEB, nc);
        CP_COMMIT();

        const uint32_t st  = sb + (c & 3) * STAGEB;
        const uint32_t sA  = st;
        const uint32_t sAl = st + SBUF;
        const uint32_t sB  = st + 2 * SBUF;
        const uint32_t sBl = st + 3 * SBUF;

#pragma unroll
        for (int kk = 0; kk < 2; ++kk) {
            const int ck = kk * 2;
            uint32_t ah[4][4], al[4][4], bh[4][2], bl[4][2];
            const uint32_t aoff = (uint32_t)(arow * RPITCH + (ck + (q >> 1)) * 16);
#pragma unroll
            for (int mi = 0; mi < 4; ++mi)
                LDSM4(ah[mi][0], ah[mi][1], ah[mi][2], ah[mi][3],
                      sA + aoff + mi * 16 * RPITCH);
#pragma unroll
            for (int mi = 0; mi < 4; ++mi)
                LDSM4(al[mi][0], al[mi][1], al[mi][2], al[mi][3],
                      sAl + aoff + mi * 16 * RPITCH);

            const uint32_t boff = (uint32_t)(brow0 * RPITCH + (ck + bch) * 16);
            {
                uint32_t t0,t1,t2,t3;
                LDSM4(t0,t1,t2,t3, sB + boff);
                bh[0][0]=t0; bh[0][1]=t1; bh[1][0]=t2; bh[1][1]=t3;
                LDSM4(t0,t1,t2,t3, sB + boff + 16 * RPITCH);
                bh[2][0]=t0; bh[2][1]=t1; bh[3][0]=t2; bh[3][1]=t3;
                LDSM4(t0,t1,t2,t3, sBl + boff);
                bl[0][0]=t0; bl[0][1]=t1; bl[1][0]=t2; bl[1][1]=t3;
                LDSM4(t0,t1,t2,t3, sBl + boff + 16 * RPITCH);
                bl[2][0]=t0; bl[2][1]=t1; bl[3][0]=t2; bl[3][1]=t3;
            }
#pragma unroll
            for (int mi = 0; mi < 4; ++mi)
#pragma unroll
                for (int ni = 0; ni < 4; ++ni)
                    MMA_BF16(d[mi][ni], ah[mi], bh[ni]);
#pragma unroll
            for (int mi = 0; mi < 4; ++mi)
#pragma unroll
                for (int ni = 0; ni < 4; ++ni)
                    MMA_BF16(d[mi][ni], al[mi], bh[ni]);
#pragma unroll
            for (int mi = 0; mi < 4; ++mi)
#pragma unroll
                for (int ni = 0; ni < 4; ++ni)
                    MMA_BF16(d[mi][ni], ah[mi], bl[ni]);
        }
    }

    __syncthreads();   // all warps done with final chunks before Sf overwrite

    // Stage fp32 tile in SMEM (pitch 132), then coalesced writers
    float* Sf = (float*)smc;
#pragma unroll
    for (int mi = 0; mi < 4; ++mi) {
        const int r0 = wm * 64 + mi * 16 + (lid >> 2);
#pragma unroll
        for (int ni = 0; ni < 4; ++ni) {
            const int c0 = wn * 32 + ni * 8 + (lid & 3) * 2;
            Sf[r0 * 132 + c0]           = d[mi][ni][0];
            Sf[r0 * 132 + c0 + 1]       = d[mi][ni][1];
            Sf[(r0 + 8) * 132 + c0]     = d[mi][ni][2];
            Sf[(r0 + 8) * 132 + c0 + 1] = d[mi][ni][3];
        }
    }
    __syncthreads();

    if (MODE == 1) {
#pragma unroll
        for (int rr = 0; rr < 16; ++rr) {
            const int row = wid * 16 + rr;
            float4 v = *(const float4*)&Sf[row * 132 + lid * 4];
            *(float4*)(C + (size_t)(m0 + row) * 2048 + n0 + lid * 4) = v;
        }
    } else {
        const int qmode = n0 >> 11;              // 0:q 1:k 2:v
        const int h     = (n0 & 2047) >> 7;
        const int b     = m0 >> 11;
        const int t0    = m0 & 2047;
        const int bhx   = b * Hz + h;
        if (qmode == 2) {
            __nv_bfloat16* dh = g_vh + ((size_t)bhx * Tz + t0) * HDz;
            __nv_bfloat16* dl = g_vl + ((size_t)bhx * Tz + t0) * HDz;
#pragma unroll
            for (int rr = 0; rr < 16; ++rr) {
                const int row = wid * 16 + rr;
                float4 v = *(const float4*)&Sf[row * 132 + lid * 4];
                uint32_t h0, l0, h1, l1;
                split2(v.x, v.y, h0, l0);
                split2(v.z, v.w, h1, l1);
                *(uint32_t*)(dh + (size_t)row * HDz + lid * 4)     = h0;
                *(uint32_t*)(dh + (size_t)row * HDz + lid * 4 + 2) = h1;
                *(uint32_t*)(dl + (size_t)row * HDz + lid * 4)     = l0;
                *(uint32_t*)(dl + (size_t)row * HDz + lid * 4 + 2) = l1;
            }
        } else {
            // Fused RoPE: rotate pairs (d, d+64), scale q, split to bf16 hi/lo
            const bool isq = (qmode == 0);
            __nv_bfloat16* dh = (isq ? g_qh : g_kh) + ((size_t)bhx * Tz + t0) * HDz;
            __nv_bfloat16* dl = (isq ? g_ql : g_kl) + ((size_t)bhx * Tz + t0) * HDz;
            const int row = tid >> 1;
            const int db  = (tid & 1) * 32;
            const int t   = t0 + row;
            const float sc = isq ? 0.08838834764831845f : 1.0f;
            const float* crow_ = cosT + t * HDz + db;
            const float* srow_ = sinT + t * HDz + db;
            const float* Sr = Sf + row * 132 + db;
            __nv_bfloat16* ph = dh + (size_t)row * HDz + db;
            __nv_bfloat16* pl = dl + (size_t)row * HDz + db;
#pragma unroll
            for (int dd = 0; dd < 32; dd += 2) {
                float c0 = crow_[dd], c1 = crow_[dd + 1];
                float s0 = srow_[dd], s1 = srow_[dd + 1];
                float x0 = Sr[dd],      x1 = Sr[dd + 1];
                float y0 = Sr[dd + 64], y1 = Sr[dd + 65];
                float r0 = (x0 * c0 - y0 * s0) * sc;
                float r1 = (x1 * c1 - y1 * s1) * sc;
                float u0 = (y0 * c0 + x0 * s0) * sc;
                float u1 = (y1 * c1 + x1 * s1) * sc;
                uint32_t hi, lo;
                split2(r0, r1, hi, lo);
                *(uint32_t*)(ph + dd)      = hi;
                *(uint32_t*)(pl + dd)      = lo;
                split2(u0, u1, hi, lo);
                *(uint32_t*)(ph + dd + 64) = hi;
                *(uint32_t*)(pl + dd + 64) = lo;
            }
        }
    }
}

// ---------------------------------------------------------------------------
// Causal flash attention on tensor cores (bf16x3).
// BM=128 (8 warps x 16 rows), BN=64, HD=128, 256 threads.
// Q hi/lo resident in SMEM; K/V hi/lo double-buffered cp.async.
// Row pitch 136 bf16 (272B = 17 x 16B chunks -> conflict-free ldmatrix).
// ---------------------------------------------------------------------------
#define AP    136
#define APB   272
#define QSZ   (128 * APB)       // 34816
#define KSZ   (64 * APB)        // 17408
#define ATTN_SMEM2 (2 * QSZ + 2 * 4 * KSZ)   // 208896

__global__ __launch_bounds__(256, 1)
void attn_mma()
{
    extern __shared__ char smc[];
    const uint32_t sb = smem_u32(smc);
    const int tid = threadIdx.x;
    const int wid = tid >> 5;
    const int lid = tid & 31;
    const int bh  = blockIdx.y;
    const int qb  = (int)gridDim.x - 1 - (int)blockIdx.x;  // big blocks first
    const int q0  = qb * 128;
    const int ntiles = 2 * qb + 2;

    const __nv_bfloat16* qh_g = g_qh + ((size_t)bh * Tz + q0) * HDz;
    const __nv_bfloat16* ql_g = g_ql + ((size_t)bh * Tz + q0) * HDz;
    const __nv_bfloat16* kh_g = g_kh + (size_t)bh * Tz * HDz;
    const __nv_bfloat16* kl_g = g_kl + (size_t)bh * Tz * HDz;
    const __nv_bfloat16* vh_g = g_vh + (size_t)bh * Tz * HDz;
    const __nv_bfloat16* vl_g = g_vl + (size_t)bh * Tz * HDz;

    const uint32_t sQh = sb;
    const uint32_t sQl = sb + QSZ;
    const uint32_t sStage = sb + 2 * QSZ;

#pragma unroll
    for (int i = 0; i < 8; ++i) {
        int cc = i * 256 + tid;
        int row = cc >> 4, col = cc & 15;
        CP16(sQh + row * APB + col * 16, qh_g + (size_t)row * HDz + col * 8);
    }
#pragma unroll
    for (int i = 0; i < 8; ++i) {
        int cc = i * 256 + tid;
        int row = cc >> 4, col = cc & 15;
        CP16(sQl + row * APB + col * 16, ql_g + (size_t)row * HDz + col * 8);
    }
    CP_COMMIT();

    auto load_stage = [&](int stage, int j0) {
        const uint32_t base = sStage + stage * (4 * KSZ);
        const __nv_bfloat16* gp0 = kh_g + (size_t)j0 * HDz;
        const __nv_bfloat16* gp1 = kl_g + (size_t)j0 * HDz;
        const __nv_bfloat16* gp2 = vh_g + (size_t)j0 * HDz;
        const __nv_bfloat16* gp3 = vl_g + (size_t)j0 * HDz;
#pragma unroll
        for (int i = 0; i < 4; ++i) {
            int cc = i * 256 + tid;
            int row = cc >> 4, col = cc & 15;
            uint32_t so = (uint32_t)(row * APB + col * 16);
            size_t go = (size_t)row * HDz + col * 8;
            CP16(base + so,           gp0 + go);
            CP16(base + KSZ + so,     gp1 + go);
            CP16(base + 2*KSZ + so,   gp2 + go);
            CP16(base + 3*KSZ + so,   gp3 + go);
        }
    };

    load_stage(0, 0);
    CP_COMMIT();

    const int qq = lid >> 3;
    const int r8 = lid & 7;
    const int g  = lid >> 2;
    const int t4 = lid & 3;
    const uint32_t qa_off  = (uint32_t)((wid * 16 + (qq & 1) * 8 + r8) * APB);
    const uint32_t ka_row  = (uint32_t)(((qq >> 1) * 8 + r8) * APB);
    const uint32_t va_off  = (uint32_t)((((lid >> 3) & 1) * 8 + (lid & 7)) * APB
                                        + (lid >> 4) * 16);

    float m0v = -1e30f, m1v = -1e30f, l0v = 0.f, l1v = 0.f;
    float o[16][4];
#pragma unroll
    for (int i = 0; i < 16; i++)
#pragma unroll
        for (int j = 0; j < 4; j++) o[i][j] = 0.f;

    for (int kt = 0; kt < ntiles; ++kt) {
        if (kt + 1 < ntiles) {
            load_stage((kt + 1) & 1, (kt + 1) * 64);
            CP_COMMIT();
            CP_WAIT(1);
        } else {
            CP_WAIT(0);
        }
        __syncthreads();

        const uint32_t sK  = sStage + (kt & 1) * (4 * KSZ);
        const uint32_t sKh = sK;
        const uint32_t sKl = sK + KSZ;
        const uint32_t sVh = sK + 2 * KSZ;
        const uint32_t sVl = sK + 3 * KSZ;

        const bool active = !(kt == ntiles - 1 && wid < 4);
        if (active) {
            float sf[8][4];
#pragma unroll
            for (int i = 0; i < 8; i++)
#pragma unroll
                for (int j = 0; j < 4; j++) sf[i][j] = 0.f;

#pragma unroll
            for (int kk = 0; kk < 8; ++kk) {
                const uint32_t acol = (uint32_t)((kk * 2 + (qq >> 1)) * 16);
                const uint32_t kcol = (uint32_t)((kk * 2 + (qq & 1)) * 16);
                uint32_t ah0,ah1,ah2,ah3, al0,al1,al2,al3;
                LDSM4(ah0,ah1,ah2,ah3, sQh + qa_off + acol);
                LDSM4(al0,al1,al2,al3, sQl + qa_off + acol);
#pragma unroll
                for (int h2 = 0; h2 < 2; ++h2) {
                    uint32_t b0h[4], b1h[4], b0l[4], b1l[4];
                    const uint32_t r0 = (uint32_t)((2*h2) * 16 * APB);
                    const uint32_t r1 = (uint32_t)((2*h2 + 1) * 16 * APB);
                    LDSM4(b0h[0],b0h[1],b0h[2],b0h[3], sKh + ka_row + r0 + kcol);
                    LDSM4(b1h[0],b1h[1],b1h[2],b1h[3], sKh + ka_row + r1 + kcol);
                    LDSM4(b0l[0],b0l[1],b0l[2],b0l[3], sKl + ka_row + r0 + kcol);
                    LDSM4(b1l[0],b1l[1],b1l[2],b1l[3], sKl + ka_row + r1 + kcol);
                    MMA4(sf[4*h2+0], ah0,ah1,ah2,ah3, b0h[0], b0h[1]);
                    MMA4(sf[4*h2+1], ah0,ah1,ah2,ah3, b0h[2], b0h[3]);
                    MMA4(sf[4*h2+2], ah0,ah1,ah2,ah3, b1h[0], b1h[1]);
                    MMA4(sf[4*h2+3], ah0,ah1,ah2,ah3, b1h[2], b1h[3]);
                    MMA4(sf[4*h2+0], al0,al1,al2,al3, b0h[0], b0h[1]);
                    MMA4(sf[4*h2+1], al0,al1,al2,al3, b0h[2], b0h[3]);
                    MMA4(sf[4*h2+2], al0,al1,al2,al3, b1h[0], b1h[1]);
                    MMA4(sf[4*h2+3], al0,al1,al2,al3, b1h[2], b1h[3]);
                    MMA4(sf[4*h2+0], ah0,ah1,ah2,ah3, b0l[0], b0l[1]);
                    MMA4(sf[4*h2+1], ah0,ah1,ah2,ah3, b0l[2], b0l[3]);
                    MMA4(sf[4*h2+2], ah0,ah1,ah2,ah3, b1l[0], b1l[1]);
                    MMA4(sf[4*h2+3], ah0,ah1,ah2,ah3, b1l[2], b1l[3]);
                }
            }

            if (kt == ntiles - 2) {
                if (wid < 4) {
                    const int i0 = wid * 16 + g;
                    const int i1 = i0 + 8;
#pragma unroll
                    for (int ns = 0; ns < 8; ++ns) {
                        const int jc = ns * 8 + t4 * 2;
                        if (jc     > i0) sf[ns][0] = -1e30f;
                        if (jc + 1 > i0) sf[ns][1] = -1e30f;
                        if (jc     > i1) sf[ns][2] = -1e30f;
                        if (jc + 1 > i1) sf[ns][3] = -1e30f;
                    }
                }
            } else if (kt == ntiles - 1) {
                const int i0 = wid * 16 + g - 64;
                const int i1 = i0 + 8;
#pragma unroll
                for (int ns = 0; ns < 8; ++ns) {
                    const int jc = ns * 8 + t4 * 2;
                    if (jc     > i0) sf[ns][0] = -1e30f;
                    if (jc + 1 > i0) sf[ns][1] = -1e30f;
                    if (jc     > i1) sf[ns][2] = -1e30f;
                    if (jc + 1 > i1) sf[ns][3] = -1e30f;
                }
            }

            float rm0 = -1e30f, rm1 = -1e30f;
#pragma unroll
            for (int ns = 0; ns < 8; ++ns) {
                rm0 = fmaxf(rm0, fmaxf(sf[ns][0], sf[ns][1]));
                rm1 = fmaxf(rm1, fmaxf(sf[ns][2], sf[ns][3]));
            }
            rm0 = fmaxf(rm0, __shfl_xor_sync(0xffffffffu, rm0, 1));
            rm0 = fmaxf(rm0, __shfl_xor_sync(0xffffffffu, rm0, 2));
            rm1 = fmaxf(rm1, __shfl_xor_sync(0xffffffffu, rm1, 1));
            rm1 = fmaxf(rm1, __shfl_xor_sync(0xffffffffu, rm1, 2));
            const float mn0 = fmaxf(m0v, rm0);
            const float mn1 = fmaxf(m1v, rm1);
            const float corr0 = __expf(m0v - mn0);
            const float corr1 = __expf(m1v - mn1);
            m0v = mn0; m1v = mn1;
            float rs0 = 0.f, rs1 = 0.f;
#pragma unroll
            for (int ns = 0; ns < 8; ++ns) {
                float p0 = __expf(sf[ns][0] - mn0);
                float p1 = __expf(sf[ns][1] - mn0);
                float p2 = __expf(sf[ns][2] - mn1);
                float p3 = __expf(sf[ns][3] - mn1);
                sf[ns][0] = p0; sf[ns][1] = p1; sf[ns][2] = p2; sf[ns][3] = p3;
                rs0 += p0 + p1; rs1 += p2 + p3;
            }
            rs0 += __shfl_xor_sync(0xffffffffu, rs0, 1);
            rs0 += __shfl_xor_sync(0xffffffffu, rs0, 2);
            rs1 += __shfl_xor_sync(0xffffffffu, rs1, 1);
            rs1 += __shfl_xor_sync(0xffffffffu, rs1, 2);
            l0v = l0v * corr0 + rs0;
            l1v = l1v * corr1 + rs1;
#pragma unroll
            for (int ns = 0; ns < 16; ++ns) {
                o[ns][0] *= corr0; o[ns][1] *= corr0;
                o[ns][2] *= corr1; o[ns][3] *= corr1;
            }

            uint32_t pah[4][4], pal[4][4];
#pragma unroll
            for (int kk = 0; kk < 4; ++kk) {
                split2(sf[2*kk][0],   sf[2*kk][1],   pah[kk][0], pal[kk][0]);
                split2(sf[2*kk][2],   sf[2*kk][3],   pah[kk][1], pal[kk][1]);
                split2(sf[2*kk+1][0], sf[2*kk+1][1], pah[kk][2], pal[kk][2]);
                split2(sf[2*kk+1][2], sf[2*kk+1][3], pah[kk][3], pal[kk][3]);
            }

#pragma unroll
            for (int kk = 0; kk < 4; ++kk) {
                const uint32_t vrow = (uint32_t)(kk * 16 * APB) + va_off;
#pragma unroll
                for (int dp = 0; dp < 4; ++dp) {
                    uint32_t v0h[4], v1h[4], v0l[4], v1l[4];
                    LDSM4T(v0h[0],v0h[1],v0h[2],v0h[3], sVh + vrow + dp*64);
                    LDSM4T(v1h[0],v1h[1],v1h[2],v1h[3], sVh + vrow + dp*64 + 32);
                    LDSM4T(v0l[0],v0l[1],v0l[2],v0l[3], sVl + vrow + dp*64);
                    LDSM4T(v1l[0],v1l[1],v1l[2],v1l[3], sVl + vrow + dp*64 + 32);
                    MMA4(o[4*dp+0], pah[kk][0],pah[kk][1],pah[kk][2],pah[kk][3], v0h[0], v0h[1]);
                    MMA4(o[4*dp+1], pah[kk][0],pah[kk][1],pah[kk][2],pah[kk][3], v0h[2], v0h[3]);
                    MMA4(o[4*dp+2], pah[kk][0],pah[kk][1],pah[kk][2],pah[kk][3], v1h[0], v1h[1]);
                    MMA4(o[4*dp+3], pah[kk][0],pah[kk][1],pah[kk][2],pah[kk][3], v1h[2], v1h[3]);
                    MMA4(o[4*dp+0], pal[kk][0],pal[kk][1],pal[kk][2],pal[kk][3], v0h[0], v0h[1]);
                    MMA4(o[4*dp+1], pal[kk][0],pal[kk][1],pal[kk][2],pal[kk][3], v0h[2], v0h[3]);
                    MMA4(o[4*dp+2], pal[kk][0],pal[kk][1],pal[kk][2],pal[kk][3], v1h[0], v1h[1]);
                    MMA4(o[4*dp+3], pal[kk][0],pal[kk][1],pal[kk][2],pal[kk][3], v1h[2], v1h[3]);
                    MMA4(o[4*dp+0], pah[kk][0],pah[kk][1],pah[kk][2],pah[kk][3], v0l[0], v0l[1]);
                    MMA4(o[4*dp+1], pah[kk][0],pah[kk][1],pah[kk][2],pah[kk][3], v0l[2], v0l[3]);
                    MMA4(o[4*dp+2], pah[kk][0],pah[kk][1],pah[kk][2],pah[kk][3], v1l[0], v1l[1]);
                    MMA4(o[4*dp+3], pah[kk][0],pah[kk][1],pah[kk][2],pah[kk][3], v1l[2], v1l[3]);
                }
            }
        }
        __syncthreads();
    }

    const int b  = bh >> 4;
    const int hh = bh & 15;
    const float inv0 = 1.f / l0v;
    const float inv1 = 1.f / l1v;
    const size_t rb0 = ((size_t)b * Tz + q0 + wid * 16 + g) * Dz + hh * HDz;
    const size_t rb1 = rb0 + (size_t)8 * Dz;
#pragma unroll
    for (int ns = 0; ns < 16; ++ns) {
        const int dcol = ns * 8 + t4 * 2;
        uint32_t hi, lo;
        split2(o[ns][0] * inv0, o[ns][1] * inv0, hi, lo);
        *(uint32_t*)(g_oh + rb0 + dcol) = hi;
        *(uint32_t*)(g_ol + rb0 + dcol) = lo;
        split2(o[ns][2] * inv1, o[ns][3] * inv1, hi, lo);
        *(uint32_t*)(g_oh + rb1 + dcol) = hi;
        *(uint32_t*)(g_ol + rb1 + dcol) = lo;
    }
}

// ---------------------------------------------------------------------------
extern "C" void kernel_launch(void* const* d_in, const int* in_sizes, int n_in,
                              void* d_out, int out_size)
{
    const float* x     = (const float*)d_in[0];
    const float* cosT  = (const float*)d_in[1];
    const float* sinT  = (const float*)d_in[2];
    const float* w_qkv = (const float*)d_in[3];
    const float* w_out = (const float*)d_in[4];
    float* out = (float*)d_out;

    cudaFuncSetAttribute(mma_gemm<0>,
                         cudaFuncAttributeMaxDynamicSharedMemorySize, GSMEM);
    cudaFuncSetAttribute(mma_gemm<1>,
                         cudaFuncAttributeMaxDynamicSharedMemorySize, GSMEM);
    cudaFuncSetAttribute(attn_mma,
                         cudaFuncAttributeMaxDynamicSharedMemorySize, ATTN_SMEM2);

    // 0. Split inputs to bf16 hi/lo
    split_kernel<0><<<(Mz * Dz) / 1024, 256>>>(x);
    split_kernel<1><<<(3 * Dz * Dz) / 1024, 256>>>(w_qkv);
    split_kernel<2><<<(Dz * Dz) / 1024, 256>>>(w_out);

    // 1. QKV projection (bf16x3, 4-stage single-sync pipeline) + fused RoPE
    mma_gemm<0><<<dim3(48, 64), 256, GSMEM>>>(nullptr, cosT, sinT);

    // 2. Causal flash attention (bf16x3 tensor cores) -> o bf16 hi/lo
    attn_mma<<<dim3(Tz / 128, BHz), 256, ATTN_SMEM2>>>();

    // 3. Output projection (bf16x3, 4-stage single-sync pipeline)
    mma_gemm<1><<<dim3(16, 64), 256, GSMEM>>>(out, nullptr, nullptr);
}

// round 10
// speedup vs baseline: 1.3928x; 1.2737x over previous
#include <cuda_runtime.h>
#include <cuda_bf16.h>
#include <cuda_fp16.h>
#include <math_constants.h>
#include <cstdint>

// Problem constants
#define Bz  4
#define Tz  2048
#define Dz  2048
#define Hz  16
#define HDz 128
#define BHz (Bz*Hz)          // 64
#define Mz  (Bz*Tz)          // 8192

// ---------------------------------------------------------------------------
// Global scratch (device globals: allocation-free per harness rules)
// ---------------------------------------------------------------------------
// Attention operands: bf16 hi/lo (3-term path, proven accuracy)
__device__ __nv_bfloat16 g_qh[(size_t)BHz * Tz * HDz];
__device__ __nv_bfloat16 g_ql[(size_t)BHz * Tz * HDz];
__device__ __nv_bfloat16 g_kh[(size_t)BHz * Tz * HDz];
__device__ __nv_bfloat16 g_kl[(size_t)BHz * Tz * HDz];
__device__ __nv_bfloat16 g_vh[(size_t)BHz * Tz * HDz];
__device__ __nv_bfloat16 g_vl[(size_t)BHz * Tz * HDz];

// GEMM operands: fp16 hi/lo (2-term path: (Ah+Al)*Bh)
__device__ __half g_xh [(size_t)Mz * Dz];
__device__ __half g_xl [(size_t)Mz * Dz];
__device__ __half g_wqh[(size_t)3 * Dz * Dz];
__device__ __half g_woh[(size_t)Dz * Dz];
__device__ __half g_oh [(size_t)Mz * Dz];   // attention out hi/lo
__device__ __half g_ol [(size_t)Mz * Dz];

// ---------------------------------------------------------------------------
// PTX helpers (base sm_100 — NO 'a'-gated instructions)
// ---------------------------------------------------------------------------
__device__ __forceinline__ uint32_t smem_u32(const void* p) {
    uint32_t a;
    asm("{ .reg .u64 t; cvta.to.shared.u64 t, %1; cvt.u32.u64 %0, t; }"
        : "=r"(a) : "l"(p));
    return a;
}

#define CP16(saddr, gptr) \
    asm volatile("cp.async.cg.shared.global [%0], [%1], 16;" \
                 :: "r"(saddr), "l"(gptr) : "memory")
#define CP_COMMIT() asm volatile("cp.async.commit_group;" ::: "memory")
#define CP_WAIT(n)  asm volatile("cp.async.wait_group %0;" :: "n"(n) : "memory")

#define LDSM4(r0, r1, r2, r3, a) \
    asm volatile("ldmatrix.sync.aligned.m8n8.x4.shared.b16 {%0,%1,%2,%3}, [%4];" \
                 : "=r"(r0), "=r"(r1), "=r"(r2), "=r"(r3) : "r"(a))
#define LDSM4T(r0, r1, r2, r3, a) \
    asm volatile("ldmatrix.sync.aligned.m8n8.x4.trans.shared.b16 {%0,%1,%2,%3}, [%4];" \
                 : "=r"(r0), "=r"(r1), "=r"(r2), "=r"(r3) : "r"(a))

// bf16 mma (attention)
#define MMA4(d, a0, a1, a2, a3, b0, b1) \
    asm volatile("mma.sync.aligned.m16n8k16.row.col.f32.bf16.bf16.f32 " \
                 "{%0,%1,%2,%3}, {%4,%5,%6,%7}, {%8,%9}, {%0,%1,%2,%3};" \
                 : "+f"((d)[0]), "+f"((d)[1]), "+f"((d)[2]), "+f"((d)[3]) \
                 : "r"(a0), "r"(a1), "r"(a2), "r"(a3), "r"(b0), "r"(b1))

// fp16 mma (projection GEMMs)
#define MMAH(d, a, b) \
    asm volatile("mma.sync.aligned.m16n8k16.row.col.f32.f16.f16.f32 " \
                 "{%0,%1,%2,%3}, {%4,%5,%6,%7}, {%8,%9}, {%0,%1,%2,%3};" \
                 : "+f"((d)[0]), "+f"((d)[1]), "+f"((d)[2]), "+f"((d)[3]) \
                 : "r"((a)[0]), "r"((a)[1]), "r"((a)[2]), "r"((a)[3]), \
                   "r"((b)[0]), "r"((b)[1]))

// Split pair of floats into packed bf16 hi + bf16 lo (residual)
__device__ __forceinline__ void split2(float x, float y, uint32_t& hi, uint32_t& lo) {
    __nv_bfloat16 hx = __float2bfloat16_rn(x);
    __nv_bfloat16 hy = __float2bfloat16_rn(y);
    __nv_bfloat162 H; H.x = hx; H.y = hy;
    hi = *(uint32_t*)&H;
    __nv_bfloat162 L;
    L.x = __float2bfloat16_rn(x - __bfloat162float(hx));
    L.y = __float2bfloat16_rn(y - __bfloat162float(hy));
    lo = *(uint32_t*)&L;
}

// Split pair of floats into packed fp16 hi + fp16 lo (residual)
__device__ __forceinline__ void split2h(float x, float y, uint32_t& hi, uint32_t& lo) {
    __half hx = __float2half_rn(x);
    __half hy = __float2half_rn(y);
    __half2 H; H.x = hx; H.y = hy;
    hi = *(uint32_t*)&H;
    __half2 L;
    L.x = __float2half_rn(x - __half2float(hx));
    L.y = __float2half_rn(y - __half2float(hy));
    lo = *(uint32_t*)&L;
}

// ---------------------------------------------------------------------------
// Split fp32 -> fp16.  W=0: x -> hi+lo.  W=1: w_qkv -> hi only.
// W=2: w_out -> hi only.
// ---------------------------------------------------------------------------
template<int W>
__global__ void split_kernel(const float* __restrict__ src, size_t n)
{
    size_t i = ((size_t)blockIdx.x * 256 + threadIdx.x) * 4;
    if (i >= n) return;
    float4 v = *(const float4*)(src + i);
    if (W == 0) {
        uint32_t h0, l0, h1, l1;
        split2h(v.x, v.y, h0, l0);
        split2h(v.z, v.w, h1, l1);
        *(uint32_t*)(g_xh + i)     = h0;
        *(uint32_t*)(g_xh + i + 2) = h1;
        *(uint32_t*)(g_xl + i)     = l0;
        *(uint32_t*)(g_xl + i + 2) = l1;
    } else {
        __half* hi = (W == 1) ? g_wqh : g_woh;
        __half2 H0; H0.x = __float2half_rn(v.x); H0.y = __float2half_rn(v.y);
        __half2 H1; H1.x = __float2half_rn(v.z); H1.y = __float2half_rn(v.w);
        *(__half2*)(hi + i)     = H0;
        *(__half2*)(hi + i + 2) = H1;
    }
}

// ---------------------------------------------------------------------------
// fp16 2-term tensor-core GEMM.  C = (Ah+Al) * Bh^T.  128x128 CTA tile,
// 8 warps (2x4), warp tile 64x32, K-chunk 32, 3-stage cp.async pipeline
// (R5 structure: wait(2) / sync / compute / sync / load / commit), 1 CTA/SM.
// RPITCH=80 (5x16B chunks/row: conflict-free ldmatrix without swizzle).
// MODE 0: A=x, B=w_qkv; epilogue: q,k -> fused RoPE + bf16 hi/lo split;
//         v -> bf16 hi/lo.
// MODE 1: A=g_oh/g_ol, B=w_out; epilogue writes C (fp32).
// ---------------------------------------------------------------------------
#define RPITCH   80
#define SBUF     (128 * RPITCH)          // 10240
#define STAGEB   (3 * SBUF)              // 30720: Ah, Al, Bh
#define NSTAGE   3
#define GSMEM    (NSTAGE * STAGEB)       // 92160 (epilogue Sf needs 67584)

template<int MODE>
__global__ __launch_bounds__(256, 1)
void mma_gemm(float* __restrict__ C,
              const float* __restrict__ cosT,
              const float* __restrict__ sinT)
{
    extern __shared__ char smc[];
    const uint32_t sb = smem_u32(smc);
    const int tid = threadIdx.x;
    const int wid = tid >> 5;
    const int lid = tid & 31;
    const int wm  = wid & 1;          // 0..1  (64 rows each)
    const int wn  = wid >> 1;         // 0..3  (32 cols each)
    const int m0  = blockIdx.y * 128;
    const int n0  = blockIdx.x * 128;

    const __half* Ah = ((MODE == 0) ? g_xh  : g_oh ) + (size_t)m0 * 2048;
    const __half* Al = ((MODE == 0) ? g_xl  : g_ol ) + (size_t)m0 * 2048;
    const __half* Bh = ((MODE == 0) ? g_wqh : g_woh) + (size_t)n0 * 2048;

    // cp.async thread mapping: row = tid>>1, two 16B chunks per thread
    const int crow = tid >> 1;
    const int cc0  = (tid & 1) * 2;
    const uint32_t soff = (uint32_t)(crow * RPITCH + cc0 * 16);

    auto load_chunk = [&](uint32_t st, int kc) {
        const size_t gi = (size_t)crow * 2048 + kc * 32 + cc0 * 8;
        CP16(st + soff,                Ah + gi);
        CP16(st + soff + 16,           Ah + gi + 8);
        CP16(st + SBUF + soff,         Al + gi);
        CP16(st + SBUF + soff + 16,    Al + gi + 8);
        CP16(st + 2*SBUF + soff,       Bh + gi);
        CP16(st + 2*SBUF + soff + 16,  Bh + gi + 8);
    };

    float d[4][4][4];
#pragma unroll
    for (int i = 0; i < 4; i++)
#pragma unroll
        for (int j = 0; j < 4; j++)
#pragma unroll
            for (int k = 0; k < 4; k++) d[i][j][k] = 0.f;

    // Prologue: fill 3 stages
#pragma unroll
    for (int s = 0; s < NSTAGE; s++) {
        load_chunk(sb + s * STAGEB, s);
        CP_COMMIT();
    }

    const int q  = lid >> 3;
    const int r8 = lid & 7;
    const int arow = wm * 64 + (q & 1) * 8 + r8;
    const int bfr  = q >> 1;
    const int bch  = q & 1;
    const int brow0 = wn * 32 + bfr * 8 + r8;

    for (int c = 0; c < 64; ++c) {
        CP_WAIT(2);
        __syncthreads();
        const uint32_t st  = sb + (c % NSTAGE) * STAGEB;
        const uint32_t sA  = st;
        const uint32_t sAl = st + SBUF;
        const uint32_t sB  = st + 2 * SBUF;

#pragma unroll
        for (int kk = 0; kk < 2; ++kk) {
            const int ck = kk * 2;
            uint32_t ah[4][4], al[4][4], bh[4][2];
            const uint32_t aoff = (uint32_t)(arow * RPITCH + (ck + (q >> 1)) * 16);
#pragma unroll
            for (int mi = 0; mi < 4; ++mi)
                LDSM4(ah[mi][0], ah[mi][1], ah[mi][2], ah[mi][3],
                      sA + aoff + mi * 16 * RPITCH);
#pragma unroll
            for (int mi = 0; mi < 4; ++mi)
                LDSM4(al[mi][0], al[mi][1], al[mi][2], al[mi][3],
                      sAl + aoff + mi * 16 * RPITCH);

            const uint32_t boff = (uint32_t)(brow0 * RPITCH + (ck + bch) * 16);
            {
                uint32_t t0,t1,t2,t3;
                LDSM4(t0,t1,t2,t3, sB + boff);
                bh[0][0]=t0; bh[0][1]=t1; bh[1][0]=t2; bh[1][1]=t3;
                LDSM4(t0,t1,t2,t3, sB + boff + 16 * RPITCH);
                bh[2][0]=t0; bh[2][1]=t1; bh[3][0]=t2; bh[3][1]=t3;
            }
#pragma unroll
            for (int mi = 0; mi < 4; ++mi)
#pragma unroll
                for (int ni = 0; ni < 4; ++ni)
                    MMAH(d[mi][ni], ah[mi], bh[ni]);
#pragma unroll
            for (int mi = 0; mi < 4; ++mi)
#pragma unroll
                for (int ni = 0; ni < 4; ++ni)
                    MMAH(d[mi][ni], al[mi], bh[ni]);
        }
        __syncthreads();

        const int nc = c + NSTAGE;
        if (nc < 64)
            load_chunk(sb + (c % NSTAGE) * STAGEB, nc);
        CP_COMMIT();
    }

    CP_WAIT(0);
    __syncthreads();

    // Stage fp32 tile in SMEM (pitch 132), then coalesced writers
    float* Sf = (float*)smc;
#pragma unroll
    for (int mi = 0; mi < 4; ++mi) {
        const int r0 = wm * 64 + mi * 16 + (lid >> 2);
#pragma unroll
        for (int ni = 0; ni < 4; ++ni) {
            const int c0 = wn * 32 + ni * 8 + (lid & 3) * 2;
            Sf[r0 * 132 + c0]           = d[mi][ni][0];
            Sf[r0 * 132 + c0 + 1]       = d[mi][ni][1];
            Sf[(r0 + 8) * 132 + c0]     = d[mi][ni][2];
            Sf[(r0 + 8) * 132 + c0 + 1] = d[mi][ni][3];
        }
    }
    __syncthreads();

    if (MODE == 1) {
#pragma unroll
        for (int rr = 0; rr < 16; ++rr) {
            const int row = wid * 16 + rr;
            float4 v = *(const float4*)&Sf[row * 132 + lid * 4];
            *(float4*)(C + (size_t)(m0 + row) * 2048 + n0 + lid * 4) = v;
        }
    } else {
        const int qmode = n0 >> 11;              // 0:q 1:k 2:v
        const int h     = (n0 & 2047) >> 7;
        const int b     = m0 >> 11;
        const int t0    = m0 & 2047;
        const int bhx   = b * Hz + h;
        if (qmode == 2) {
            __nv_bfloat16* dh = g_vh + ((size_t)bhx * Tz + t0) * HDz;
            __nv_bfloat16* dl = g_vl + ((size_t)bhx * Tz + t0) * HDz;
#pragma unroll
            for (int rr = 0; rr < 16; ++rr) {
                const int row = wid * 16 + rr;
                float4 v = *(const float4*)&Sf[row * 132 + lid * 4];
                uint32_t h0, l0, h1, l1;
                split2(v.x, v.y, h0, l0);
                split2(v.z, v.w, h1, l1);
                *(uint32_t*)(dh + (size_t)row * HDz + lid * 4)     = h0;
                *(uint32_t*)(dh + (size_t)row * HDz + lid * 4 + 2) = h1;
                *(uint32_t*)(dl + (size_t)row * HDz + lid * 4)     = l0;
                *(uint32_t*)(dl + (size_t)row * HDz + lid * 4 + 2) = l1;
            }
        } else {
            // Fused RoPE: rotate pairs (d, d+64), scale q, split to bf16 hi/lo
            const bool isq = (qmode == 0);
            __nv_bfloat16* dh = (isq ? g_qh : g_kh) + ((size_t)bhx * Tz + t0) * HDz;
            __nv_bfloat16* dl = (isq ? g_ql : g_kl) + ((size_t)bhx * Tz + t0) * HDz;
            const int row = tid >> 1;
            const int db  = (tid & 1) * 32;
            const int t   = t0 + row;
            const float sc = isq ? 0.08838834764831845f : 1.0f;
            const float* crow_ = cosT + t * HDz + db;
            const float* srow_ = sinT + t * HDz + db;
            const float* Sr = Sf + row * 132 + db;
            __nv_bfloat16* ph = dh + (size_t)row * HDz + db;
            __nv_bfloat16* pl = dl + (size_t)row * HDz + db;
#pragma unroll
            for (int dd = 0; dd < 32; dd += 2) {
                float c0 = crow_[dd], c1 = crow_[dd + 1];
                float s0 = srow_[dd], s1 = srow_[dd + 1];
                float x0 = Sr[dd],      x1 = Sr[dd + 1];
                float y0 = Sr[dd + 64], y1 = Sr[dd + 65];
                float r0 = (x0 * c0 - y0 * s0) * sc;
                float r1 = (x1 * c1 - y1 * s1) * sc;
                float u0 = (y0 * c0 + x0 * s0) * sc;
                float u1 = (y1 * c1 + x1 * s1) * sc;
                uint32_t hi, lo;
                split2(r0, r1, hi, lo);
                *(uint32_t*)(ph + dd)      = hi;
                *(uint32_t*)(pl + dd)      = lo;
                split2(u0, u1, hi, lo);
                *(uint32_t*)(ph + dd + 64) = hi;
                *(uint32_t*)(pl + dd + 64) = lo;
            }
        }
    }
}

// ---------------------------------------------------------------------------
// Causal flash attention on tensor cores (bf16x3).
// BM=128 (8 warps x 16 rows), BN=64, HD=128, 256 threads.
// Q hi/lo resident in SMEM; K/V hi/lo double-buffered cp.async.
// Row pitch 136 bf16 (272B = 17 x 16B chunks -> conflict-free ldmatrix).
// Output written as fp16 hi/lo for the fp16 2-term out-projection.
// ---------------------------------------------------------------------------
#define AP    136
#define APB   272
#define QSZ   (128 * APB)       // 34816
#define KSZ   (64 * APB)        // 17408
#define ATTN_SMEM2 (2 * QSZ + 2 * 4 * KSZ)   // 208896

__global__ __launch_bounds__(256, 1)
void attn_mma()
{
    extern __shared__ char smc[];
    const uint32_t sb = smem_u32(smc);
    const int tid = threadIdx.x;
    const int wid = tid >> 5;
    const int lid = tid & 31;
    const int bh  = blockIdx.y;
    const int qb  = (int)gridDim.x - 1 - (int)blockIdx.x;  // big blocks first
    const int q0  = qb * 128;
    const int ntiles = 2 * qb + 2;

    const __nv_bfloat16* qh_g = g_qh + ((size_t)bh * Tz + q0) * HDz;
    const __nv_bfloat16* ql_g = g_ql + ((size_t)bh * Tz + q0) * HDz;
    const __nv_bfloat16* kh_g = g_kh + (size_t)bh * Tz * HDz;
    const __nv_bfloat16* kl_g = g_kl + (size_t)bh * Tz * HDz;
    const __nv_bfloat16* vh_g = g_vh + (size_t)bh * Tz * HDz;
    const __nv_bfloat16* vl_g = g_vl + (size_t)bh * Tz * HDz;

    const uint32_t sQh = sb;
    const uint32_t sQl = sb + QSZ;
    const uint32_t sStage = sb + 2 * QSZ;

#pragma unroll
    for (int i = 0; i < 8; ++i) {
        int cc = i * 256 + tid;
        int row = cc >> 4, col = cc & 15;
        CP16(sQh + row * APB + col * 16, qh_g + (size_t)row * HDz + col * 8);
    }
#pragma unroll
    for (int i = 0; i < 8; ++i) {
        int cc = i * 256 + tid;
        int row = cc >> 4, col = cc & 15;
        CP16(sQl + row * APB + col * 16, ql_g + (size_t)row * HDz + col * 8);
    }
    CP_COMMIT();

    auto load_stage = [&](int stage, int j0) {
        const uint32_t base = sStage + stage * (4 * KSZ);
        const __nv_bfloat16* gp0 = kh_g + (size_t)j0 * HDz;
        const __nv_bfloat16* gp1 = kl_g + (size_t)j0 * HDz;
        const __nv_bfloat16* gp2 = vh_g + (size_t)j0 * HDz;
        const __nv_bfloat16* gp3 = vl_g + (size_t)j0 * HDz;
#pragma unroll
        for (int i = 0; i < 4; ++i) {
            int cc = i * 256 + tid;
            int row = cc >> 4, col = cc & 15;
            uint32_t so = (uint32_t)(row * APB + col * 16);
            size_t go = (size_t)row * HDz + col * 8;
            CP16(base + so,           gp0 + go);
            CP16(base + KSZ + so,     gp1 + go);
            CP16(base + 2*KSZ + so,   gp2 + go);
            CP16(base + 3*KSZ + so,   gp3 + go);
        }
    };

    load_stage(0, 0);
    CP_COMMIT();

    const int qq = lid >> 3;
    const int r8 = lid & 7;
    const int g  = lid >> 2;
    const int t4 = lid & 3;
    const uint32_t qa_off  = (uint32_t)((wid * 16 + (qq & 1) * 8 + r8) * APB);
    const uint32_t ka_row  = (uint32_t)(((qq >> 1) * 8 + r8) * APB);
    const uint32_t va_off  = (uint32_t)((((lid >> 3) & 1) * 8 + (lid & 7)) * APB
                                        + (lid >> 4) * 16);

    float m0v = -1e30f, m1v = -1e30f, l0v = 0.f, l1v = 0.f;
    float o[16][4];
#pragma unroll
    for (int i = 0; i < 16; i++)
#pragma unroll
        for (int j = 0; j < 4; j++) o[i][j] = 0.f;

    for (int kt = 0; kt < ntiles; ++kt) {
        if (kt + 1 < ntiles) {
            load_stage((kt + 1) & 1, (kt + 1) * 64);
            CP_COMMIT();
            CP_WAIT(1);
        } else {
            CP_WAIT(0);
        }
        __syncthreads();

        const uint32_t sK  = sStage + (kt & 1) * (4 * KSZ);
        const uint32_t sKh = sK;
        const uint32_t sKl = sK + KSZ;
        const uint32_t sVh = sK + 2 * KSZ;
        const uint32_t sVl = sK + 3 * KSZ;

        const bool active = !(kt == ntiles - 1 && wid < 4);
        if (active) {
            float sf[8][4];
#pragma unroll
            for (int i = 0; i < 8; i++)
#pragma unroll
                for (int j = 0; j < 4; j++) sf[i][j] = 0.f;

#pragma unroll
            for (int kk = 0; kk < 8; ++kk) {
                const uint32_t acol = (uint32_t)((kk * 2 + (qq >> 1)) * 16);
                const uint32_t kcol = (uint32_t)((kk * 2 + (qq & 1)) * 16);
                uint32_t ah0,ah1,ah2,ah3, al0,al1,al2,al3;
                LDSM4(ah0,ah1,ah2,ah3, sQh + qa_off + acol);
                LDSM4(al0,al1,al2,al3, sQl + qa_off + acol);
#pragma unroll
                for (int h2 = 0; h2 < 2; ++h2) {
                    uint32_t b0h[4], b1h[4], b0l[4], b1l[4];
                    const uint32_t r0 = (uint32_t)((2*h2) * 16 * APB);
                    const uint32_t r1 = (uint32_t)((2*h2 + 1) * 16 * APB);
                    LDSM4(b0h[0],b0h[1],b0h[2],b0h[3], sKh + ka_row + r0 + kcol);
                    LDSM4(b1h[0],b1h[1],b1h[2],b1h[3], sKh + ka_row + r1 + kcol);
                    LDSM4(b0l[0],b0l[1],b0l[2],b0l[3], sKl + ka_row + r0 + kcol);
                    LDSM4(b1l[0],b1l[1],b1l[2],b1l[3], sKl + ka_row + r1 + kcol);
                    MMA4(sf[4*h2+0], ah0,ah1,ah2,ah3, b0h[0], b0h[1]);
                    MMA4(sf[4*h2+1], ah0,ah1,ah2,ah3, b0h[2], b0h[3]);
                    MMA4(sf[4*h2+2], ah0,ah1,ah2,ah3, b1h[0], b1h[1]);
                    MMA4(sf[4*h2+3], ah0,ah1,ah2,ah3, b1h[2], b1h[3]);
                    MMA4(sf[4*h2+0], al0,al1,al2,al3, b0h[0], b0h[1]);
                    MMA4(sf[4*h2+1], al0,al1,al2,al3, b0h[2], b0h[3]);
                    MMA4(sf[4*h2+2], al0,al1,al2,al3, b1h[0], b1h[1]);
                    MMA4(sf[4*h2+3], al0,al1,al2,al3, b1h[2], b1h[3]);
                    MMA4(sf[4*h2+0], ah0,ah1,ah2,ah3, b0l[0], b0l[1]);
                    MMA4(sf[4*h2+1], ah0,ah1,ah2,ah3, b0l[2], b0l[3]);
                    MMA4(sf[4*h2+2], ah0,ah1,ah2,ah3, b1l[0], b1l[1]);
                    MMA4(sf[4*h2+3], ah0,ah1,ah2,ah3, b1l[2], b1l[3]);
                }
            }

            if (kt == ntiles - 2) {
                if (wid < 4) {
                    const int i0 = wid * 16 + g;
                    const int i1 = i0 + 8;
#pragma unroll
                    for (int ns = 0; ns < 8; ++ns) {
                        const int jc = ns * 8 + t4 * 2;
                        if (jc     > i0) sf[ns][0] = -1e30f;
                        if (jc + 1 > i0) sf[ns][1] = -1e30f;
                        if (jc     > i1) sf[ns][2] = -1e30f;
                        if (jc + 1 > i1) sf[ns][3] = -1e30f;
                    }
                }
            } else if (kt == ntiles - 1) {
                const int i0 = wid * 16 + g - 64;
                const int i1 = i0 + 8;
#pragma unroll
                for (int ns = 0; ns < 8; ++ns) {
                    const int jc = ns * 8 + t4 * 2;
                    if (jc     > i0) sf[ns][0] = -1e30f;
                    if (jc + 1 > i0) sf[ns][1] = -1e30f;
                    if (jc     > i1) sf[ns][2] = -1e30f;
                    if (jc + 1 > i1) sf[ns][3] = -1e30f;
                }
            }

            float rm0 = -1e30f, rm1 = -1e30f;
#pragma unroll
            for (int ns = 0; ns < 8; ++ns) {
                rm0 = fmaxf(rm0, fmaxf(sf[ns][0], sf[ns][1]));
                rm1 = fmaxf(rm1, fmaxf(sf[ns][2], sf[ns][3]));
            }
            rm0 = fmaxf(rm0, __shfl_xor_sync(0xffffffffu, rm0, 1));
            rm0 = fmaxf(rm0, __shfl_xor_sync(0xffffffffu, rm0, 2));
            rm1 = fmaxf(rm1, __shfl_xor_sync(0xffffffffu, rm1, 1));
            rm1 = fmaxf(rm1, __shfl_xor_sync(0xffffffffu, rm1, 2));
            const float mn0 = fmaxf(m0v, rm0);
            const float mn1 = fmaxf(m1v, rm1);
            const float corr0 = __expf(m0v - mn0);
            const float corr1 = __expf(m1v - mn1);
            m0v = mn0; m1v = mn1;
            float rs0 = 0.f, rs1 = 0.f;
#pragma unroll
            for (int ns = 0; ns < 8; ++ns) {
                float p0 = __expf(sf[ns][0] - mn0);
                float p1 = __expf(sf[ns][1] - mn0);
                float p2 = __expf(sf[ns][2] - mn1);
                float p3 = __expf(sf[ns][3] - mn1);
                sf[ns][0] = p0; sf[ns][1] = p1; sf[ns][2] = p2; sf[ns][3] = p3;
                rs0 += p0 + p1; rs1 += p2 + p3;
            }
            rs0 += __shfl_xor_sync(0xffffffffu, rs0, 1);
            rs0 += __shfl_xor_sync(0xffffffffu, rs0, 2);
            rs1 += __shfl_xor_sync(0xffffffffu, rs1, 1);
            rs1 += __shfl_xor_sync(0xffffffffu, rs1, 2);
            l0v = l0v * corr0 + rs0;
            l1v = l1v * corr1 + rs1;
#pragma unroll
            for (int ns = 0; ns < 16; ++ns) {
                o[ns][0] *= corr0; o[ns][1] *= corr0;
                o[ns][2] *= corr1; o[ns][3] *= corr1;
            }

            uint32_t pah[4][4], pal[4][4];
#pragma unroll
            for (int kk = 0; kk < 4; ++kk) {
                split2(sf[2*kk][0],   sf[2*kk][1],   pah[kk][0], pal[kk][0]);
                split2(sf[2*kk][2],   sf[2*kk][3],   pah[kk][1], pal[kk][1]);
                split2(sf[2*kk+1][0], sf[2*kk+1][1], pah[kk][2], pal[kk][2]);
                split2(sf[2*kk+1][2], sf[2*kk+1][3], pah[kk][3], pal[kk][3]);
            }

#pragma unroll
            for (int kk = 0; kk < 4; ++kk) {
                const uint32_t vrow = (uint32_t)(kk * 16 * APB) + va_off;
#pragma unroll
                for (int dp = 0; dp < 4; ++dp) {
                    uint32_t v0h[4], v1h[4], v0l[4], v1l[4];
                    LDSM4T(v0h[0],v0h[1],v0h[2],v0h[3], sVh + vrow + dp*64);
                    LDSM4T(v1h[0],v1h[1],v1h[2],v1h[3], sVh + vrow + dp*64 + 32);
                    LDSM4T(v0l[0],v0l[1],v0l[2],v0l[3], sVl + vrow + dp*64);
                    LDSM4T(v1l[0],v1l[1],v1l[2],v1l[3], sVl + vrow + dp*64 + 32);
                    MMA4(o[4*dp+0], pah[kk][0],pah[kk][1],pah[kk][2],pah[kk][3], v0h[0], v0h[1]);
                    MMA4(o[4*dp+1], pah[kk][0],pah[kk][1],pah[kk][2],pah[kk][3], v0h[2], v0h[3]);
                    MMA4(o[4*dp+2], pah[kk][0],pah[kk][1],pah[kk][2],pah[kk][3], v1h[0], v1h[1]);
                    MMA4(o[4*dp+3], pah[kk][0],pah[kk][1],pah[kk][2],pah[kk][3], v1h[2], v1h[3]);
                    MMA4(o[4*dp+0], pal[kk][0],pal[kk][1],pal[kk][2],pal[kk][3], v0h[0], v0h[1]);
                    MMA4(o[4*dp+1], pal[kk][0],pal[kk][1],pal[kk][2],pal[kk][3], v0h[2], v0h[3]);
                    MMA4(o[4*dp+2], pal[kk][0],pal[kk][1],pal[kk][2],pal[kk][3], v1h[0], v1h[1]);
                    MMA4(o[4*dp+3], pal[kk][0],pal[kk][1],pal[kk][2],pal[kk][3], v1h[2], v1h[3]);
                    MMA4(o[4*dp+0], pah[kk][0],pah[kk][1],pah[kk][2],pah[kk][3], v0l[0], v0l[1]);
                    MMA4(o[4*dp+1], pah[kk][0],pah[kk][1],pah[kk][2],pah[kk][3], v0l[2], v0l[3]);
                    MMA4(o[4*dp+2], pah[kk][0],pah[kk][1],pah[kk][2],pah[kk][3], v1l[0], v1l[1]);
                    MMA4(o[4*dp+3], pah[kk][0],pah[kk][1],pah[kk][2],pah[kk][3], v1l[2], v1l[3]);
                }
            }
        }
        __syncthreads();
    }

    // Finalize + store fp16 hi/lo (input to the fp16 2-term out-projection)
    const int b  = bh >> 4;
    const int hh = bh & 15;
    const float inv0 = 1.f / l0v;
    const float inv1 = 1.f / l1v;
    const size_t rb0 = ((size_t)b * Tz + q0 + wid * 16 + g) * Dz + hh * HDz;
    const size_t rb1 = rb0 + (size_t)8 * Dz;
#pragma unroll
    for (int ns = 0; ns < 16; ++ns) {
        const int dcol = ns * 8 + t4 * 2;
        uint32_t hi, lo;
        split2h(o[ns][0] * inv0, o[ns][1] * inv0, hi, lo);
        *(uint32_t*)(g_oh + rb0 + dcol) = hi;
        *(uint32_t*)(g_ol + rb0 + dcol) = lo;
        split2h(o[ns][2] * inv1, o[ns][3] * inv1, hi, lo);
        *(uint32_t*)(g_oh + rb1 + dcol) = hi;
        *(uint32_t*)(g_ol + rb1 + dcol) = lo;
    }
}

// ---------------------------------------------------------------------------
extern "C" void kernel_launch(void* const* d_in, const int* in_sizes, int n_in,
                              void* d_out, int out_size)
{
    const float* x     = (const float*)d_in[0];
    const float* cosT  = (const float*)d_in[1];
    const float* sinT  = (const float*)d_in[2];
    const float* w_qkv = (const float*)d_in[3];
    const float* w_out = (const float*)d_in[4];
    float* out = (float*)d_out;

    cudaFuncSetAttribute(mma_gemm<0>,
                         cudaFuncAttributeMaxDynamicSharedMemorySize, GSMEM);
    cudaFuncSetAttribute(mma_gemm<1>,
                         cudaFuncAttributeMaxDynamicSharedMemorySize, GSMEM);
    cudaFuncSetAttribute(attn_mma,
                         cudaFuncAttributeMaxDynamicSharedMemorySize, ATTN_SMEM2);

    // 0. Split inputs to fp16 (x: hi+lo; weights: hi only)
    split_kernel<0><<<(Mz * Dz) / 1024, 256>>>(x, (size_t)Mz * Dz);
    split_kernel<1><<<(3 * Dz * Dz) / 1024, 256>>>(w_qkv, (size_t)3 * Dz * Dz);
    split_kernel<2><<<(Dz * Dz) / 1024, 256>>>(w_out, (size_t)Dz * Dz);

    // 1. QKV projection (fp16 2-term) + fused RoPE/scale/bf16-split epilogue
    mma_gemm<0><<<dim3(48, 64), 256, GSMEM>>>(nullptr, cosT, sinT);

    // 2. Causal flash attention (bf16x3 tensor cores) -> o fp16 hi/lo
    attn_mma<<<dim3(Tz / 128, BHz), 256, ATTN_SMEM2>>>();

    // 3. Output projection (fp16 2-term)
    mma_gemm<1><<<dim3(16, 64), 256, GSMEM>>>(out, nullptr, nullptr);
}

// round 11
// speedup vs baseline: 1.5243x; 1.0944x over previous
#include <cuda_runtime.h>
#include <cuda_bf16.h>
#include <cuda_fp16.h>
#include <math_constants.h>
#include <cstdint>

// Problem constants
#define Bz  4
#define Tz  2048
#define Dz  2048
#define Hz  16
#define HDz 128
#define BHz (Bz*Hz)          // 64
#define Mz  (Bz*Tz)          // 8192

// ---------------------------------------------------------------------------
// Global scratch (device globals: allocation-free per harness rules)
// ---------------------------------------------------------------------------
// Attention operands (fp16): Q hi/lo, K hi only, V hi/lo
__device__ __half g_qh[(size_t)BHz * Tz * HDz];
__device__ __half g_ql[(size_t)BHz * Tz * HDz];
__device__ __half g_kh[(size_t)BHz * Tz * HDz];
__device__ __half g_vh[(size_t)BHz * Tz * HDz];
__device__ __half g_vl[(size_t)BHz * Tz * HDz];

// GEMM operands: fp16 hi/lo (2-term path: (Ah+Al)*Bh)
__device__ __half g_xh [(size_t)Mz * Dz];
__device__ __half g_xl [(size_t)Mz * Dz];
__device__ __half g_wqh[(size_t)3 * Dz * Dz];
__device__ __half g_woh[(size_t)Dz * Dz];
__device__ __half g_oh [(size_t)Mz * Dz];   // attention out hi/lo
__device__ __half g_ol [(size_t)Mz * Dz];

// ---------------------------------------------------------------------------
// PTX helpers (base sm_100 — NO 'a'-gated instructions)
// ---------------------------------------------------------------------------
__device__ __forceinline__ uint32_t smem_u32(const void* p) {
    uint32_t a;
    asm("{ .reg .u64 t; cvta.to.shared.u64 t, %1; cvt.u32.u64 %0, t; }"
        : "=r"(a) : "l"(p));
    return a;
}

#define CP16(saddr, gptr) \
    asm volatile("cp.async.cg.shared.global [%0], [%1], 16;" \
                 :: "r"(saddr), "l"(gptr) : "memory")
#define CP_COMMIT() asm volatile("cp.async.commit_group;" ::: "memory")
#define CP_WAIT(n)  asm volatile("cp.async.wait_group %0;" :: "n"(n) : "memory")

#define LDSM4(r0, r1, r2, r3, a) \
    asm volatile("ldmatrix.sync.aligned.m8n8.x4.shared.b16 {%0,%1,%2,%3}, [%4];" \
                 : "=r"(r0), "=r"(r1), "=r"(r2), "=r"(r3) : "r"(a))
#define LDSM4T(r0, r1, r2, r3, a) \
    asm volatile("ldmatrix.sync.aligned.m8n8.x4.trans.shared.b16 {%0,%1,%2,%3}, [%4];" \
                 : "=r"(r0), "=r"(r1), "=r"(r2), "=r"(r3) : "r"(a))

// fp16 mma, array A-frag form (projection GEMMs)
#define MMAH(d, a, b) \
    asm volatile("mma.sync.aligned.m16n8k16.row.col.f32.f16.f16.f32 " \
                 "{%0,%1,%2,%3}, {%4,%5,%6,%7}, {%8,%9}, {%0,%1,%2,%3};" \
                 : "+f"((d)[0]), "+f"((d)[1]), "+f"((d)[2]), "+f"((d)[3]) \
                 : "r"((a)[0]), "r"((a)[1]), "r"((a)[2]), "r"((a)[3]), \
                   "r"((b)[0]), "r"((b)[1]))

// fp16 mma, scalar-frag form (attention)
#define MMAH4(d, a0, a1, a2, a3, b0, b1) \
    asm volatile("mma.sync.aligned.m16n8k16.row.col.f32.f16.f16.f32 " \
                 "{%0,%1,%2,%3}, {%4,%5,%6,%7}, {%8,%9}, {%0,%1,%2,%3};" \
                 : "+f"((d)[0]), "+f"((d)[1]), "+f"((d)[2]), "+f"((d)[3]) \
                 : "r"(a0), "r"(a1), "r"(a2), "r"(a3), "r"(b0), "r"(b1))

// Split pair of floats into packed fp16 hi + fp16 lo (residual)
__device__ __forceinline__ void split2h(float x, float y, uint32_t& hi, uint32_t& lo) {
    __half hx = __float2half_rn(x);
    __half hy = __float2half_rn(y);
    __half2 H; H.x = hx; H.y = hy;
    hi = *(uint32_t*)&H;
    __half2 L;
    L.x = __float2half_rn(x - __half2float(hx));
    L.y = __float2half_rn(y - __half2float(hy));
    lo = *(uint32_t*)&L;
}

// Pack pair of floats into fp16x2 (hi only)
__device__ __forceinline__ uint32_t pack2h(float x, float y) {
    __half2 H; H.x = __float2half_rn(x); H.y = __float2half_rn(y);
    return *(uint32_t*)&H;
}

// ---------------------------------------------------------------------------
// Split fp32 -> fp16.  W=0: x -> hi+lo.  W=1: w_qkv -> hi only.
// W=2: w_out -> hi only.
// ---------------------------------------------------------------------------
template<int W>
__global__ void split_kernel(const float* __restrict__ src, size_t n)
{
    size_t i = ((size_t)blockIdx.x * 256 + threadIdx.x) * 4;
    if (i >= n) return;
    float4 v = *(const float4*)(src + i);
    if (W == 0) {
        uint32_t h0, l0, h1, l1;
        split2h(v.x, v.y, h0, l0);
        split2h(v.z, v.w, h1, l1);
        *(uint32_t*)(g_xh + i)     = h0;
        *(uint32_t*)(g_xh + i + 2) = h1;
        *(uint32_t*)(g_xl + i)     = l0;
        *(uint32_t*)(g_xl + i + 2) = l1;
    } else {
        __half* hi = (W == 1) ? g_wqh : g_woh;
        *(uint32_t*)(hi + i)     = pack2h(v.x, v.y);
        *(uint32_t*)(hi + i + 2) = pack2h(v.z, v.w);
    }
}

// ---------------------------------------------------------------------------
// fp16 2-term tensor-core GEMM.  C = (Ah+Al) * Bh^T.  128x128 CTA tile,
// 8 warps (2x4), warp tile 64x32, K-chunk 32, 3-stage cp.async pipeline,
// 1 CTA/SM.  RPITCH=80 (conflict-free ldmatrix without swizzle).
// MODE 0: A=x, B=w_qkv; epilogue: q -> RoPE+scale fp16 hi/lo; k -> RoPE fp16
//         hi only; v -> fp16 hi/lo.
// MODE 1: A=g_oh/g_ol, B=w_out; epilogue writes C (fp32).
// ---------------------------------------------------------------------------
#define RPITCH   80
#define SBUF     (128 * RPITCH)          // 10240
#define STAGEB   (3 * SBUF)              // 30720: Ah, Al, Bh
#define NSTAGE   3
#define GSMEM    (NSTAGE * STAGEB)       // 92160 (epilogue Sf needs 67584)

template<int MODE>
__global__ __launch_bounds__(256, 1)
void mma_gemm(float* __restrict__ C,
              const float* __restrict__ cosT,
              const float* __restrict__ sinT)
{
    extern __shared__ char smc[];
    const uint32_t sb = smem_u32(smc);
    const int tid = threadIdx.x;
    const int wid = tid >> 5;
    const int lid = tid & 31;
    const int wm  = wid & 1;          // 0..1  (64 rows each)
    const int wn  = wid >> 1;         // 0..3  (32 cols each)
    const int m0  = blockIdx.y * 128;
    const int n0  = blockIdx.x * 128;

    const __half* Ah = ((MODE == 0) ? g_xh  : g_oh ) + (size_t)m0 * 2048;
    const __half* Al = ((MODE == 0) ? g_xl  : g_ol ) + (size_t)m0 * 2048;
    const __half* Bh = ((MODE == 0) ? g_wqh : g_woh) + (size_t)n0 * 2048;

    const int crow = tid >> 1;
    const int cc0  = (tid & 1) * 2;
    const uint32_t soff = (uint32_t)(crow * RPITCH + cc0 * 16);

    auto load_chunk = [&](uint32_t st, int kc) {
        const size_t gi = (size_t)crow * 2048 + kc * 32 + cc0 * 8;
        CP16(st + soff,                Ah + gi);
        CP16(st + soff + 16,           Ah + gi + 8);
        CP16(st + SBUF + soff,         Al + gi);
        CP16(st + SBUF + soff + 16,    Al + gi + 8);
        CP16(st + 2*SBUF + soff,       Bh + gi);
        CP16(st + 2*SBUF + soff + 16,  Bh + gi + 8);
    };

    float d[4][4][4];
#pragma unroll
    for (int i = 0; i < 4; i++)
#pragma unroll
        for (int j = 0; j < 4; j++)
#pragma unroll
            for (int k = 0; k < 4; k++) d[i][j][k] = 0.f;

#pragma unroll
    for (int s = 0; s < NSTAGE; s++) {
        load_chunk(sb + s * STAGEB, s);
        CP_COMMIT();
    }

    const int q  = lid >> 3;
    const int r8 = lid & 7;
    const int arow = wm * 64 + (q & 1) * 8 + r8;
    const int bfr  = q >> 1;
    const int bch  = q & 1;
    const int brow0 = wn * 32 + bfr * 8 + r8;

    for (int c = 0; c < 64; ++c) {
        CP_WAIT(2);
        __syncthreads();
        const uint32_t st  = sb + (c % NSTAGE) * STAGEB;
        const uint32_t sA  = st;
        const uint32_t sAl = st + SBUF;
        const uint32_t sB  = st + 2 * SBUF;

#pragma unroll
        for (int kk = 0; kk < 2; ++kk) {
            const int ck = kk * 2;
            uint32_t ah[4][4], al[4][4], bh[4][2];
            const uint32_t aoff = (uint32_t)(arow * RPITCH + (ck + (q >> 1)) * 16);
#pragma unroll
            for (int mi = 0; mi < 4; ++mi)
                LDSM4(ah[mi][0], ah[mi][1], ah[mi][2], ah[mi][3],
                      sA + aoff + mi * 16 * RPITCH);
#pragma unroll
            for (int mi = 0; mi < 4; ++mi)
                LDSM4(al[mi][0], al[mi][1], al[mi][2], al[mi][3],
                      sAl + aoff + mi * 16 * RPITCH);

            const uint32_t boff = (uint32_t)(brow0 * RPITCH + (ck + bch) * 16);
            {
                uint32_t t0,t1,t2,t3;
                LDSM4(t0,t1,t2,t3, sB + boff);
                bh[0][0]=t0; bh[0][1]=t1; bh[1][0]=t2; bh[1][1]=t3;
                LDSM4(t0,t1,t2,t3, sB + boff + 16 * RPITCH);
                bh[2][0]=t0; bh[2][1]=t1; bh[3][0]=t2; bh[3][1]=t3;
            }
#pragma unroll
            for (int mi = 0; mi < 4; ++mi)
#pragma unroll
                for (int ni = 0; ni < 4; ++ni)
                    MMAH(d[mi][ni], ah[mi], bh[ni]);
#pragma unroll
            for (int mi = 0; mi < 4; ++mi)
#pragma unroll
                for (int ni = 0; ni < 4; ++ni)
                    MMAH(d[mi][ni], al[mi], bh[ni]);
        }
        __syncthreads();

        const int nc = c + NSTAGE;
        if (nc < 64)
            load_chunk(sb + (c % NSTAGE) * STAGEB, nc);
        CP_COMMIT();
    }

    CP_WAIT(0);
    __syncthreads();

    // Stage fp32 tile in SMEM (pitch 132), then coalesced writers
    float* Sf = (float*)smc;
#pragma unroll
    for (int mi = 0; mi < 4; ++mi) {
        const int r0 = wm * 64 + mi * 16 + (lid >> 2);
#pragma unroll
        for (int ni = 0; ni < 4; ++ni) {
            const int c0 = wn * 32 + ni * 8 + (lid & 3) * 2;
            Sf[r0 * 132 + c0]           = d[mi][ni][0];
            Sf[r0 * 132 + c0 + 1]       = d[mi][ni][1];
            Sf[(r0 + 8) * 132 + c0]     = d[mi][ni][2];
            Sf[(r0 + 8) * 132 + c0 + 1] = d[mi][ni][3];
        }
    }
    __syncthreads();

    if (MODE == 1) {
#pragma unroll
        for (int rr = 0; rr < 16; ++rr) {
            const int row = wid * 16 + rr;
            float4 v = *(const float4*)&Sf[row * 132 + lid * 4];
            *(float4*)(C + (size_t)(m0 + row) * 2048 + n0 + lid * 4) = v;
        }
    } else {
        const int qmode = n0 >> 11;              // 0:q 1:k 2:v
        const int h     = (n0 & 2047) >> 7;
        const int b     = m0 >> 11;
        const int t0    = m0 & 2047;
        const int bhx   = b * Hz + h;
        if (qmode == 2) {
            __half* dh = g_vh + ((size_t)bhx * Tz + t0) * HDz;
            __half* dl = g_vl + ((size_t)bhx * Tz + t0) * HDz;
#pragma unroll
            for (int rr = 0; rr < 16; ++rr) {
                const int row = wid * 16 + rr;
                float4 v = *(const float4*)&Sf[row * 132 + lid * 4];
                uint32_t h0, l0, h1, l1;
                split2h(v.x, v.y, h0, l0);
                split2h(v.z, v.w, h1, l1);
                *(uint32_t*)(dh + (size_t)row * HDz + lid * 4)     = h0;
                *(uint32_t*)(dh + (size_t)row * HDz + lid * 4 + 2) = h1;
                *(uint32_t*)(dl + (size_t)row * HDz + lid * 4)     = l0;
                *(uint32_t*)(dl + (size_t)row * HDz + lid * 4 + 2) = l1;
            }
        } else {
            // Fused RoPE: rotate pairs (d, d+64); q: scale + hi/lo; k: hi only
            const bool isq = (qmode == 0);
            __half* dh = (isq ? g_qh : g_kh) + ((size_t)bhx * Tz + t0) * HDz;
            __half* dl = g_ql + ((size_t)bhx * Tz + t0) * HDz;   // used iff isq
            const int row = tid >> 1;
            const int db  = (tid & 1) * 32;
            const int t   = t0 + row;
            const float sc = isq ? 0.08838834764831845f : 1.0f;
            const float* crow_ = cosT + t * HDz + db;
            const float* srow_ = sinT + t * HDz + db;
            const float* Sr = Sf + row * 132 + db;
            __half* ph = dh + (size_t)row * HDz + db;
            __half* pl = dl + (size_t)row * HDz + db;
#pragma unroll
            for (int dd = 0; dd < 32; dd += 2) {
                float c0 = crow_[dd], c1 = crow_[dd + 1];
                float s0 = srow_[dd], s1 = srow_[dd + 1];
                float x0 = Sr[dd],      x1 = Sr[dd + 1];
                float y0 = Sr[dd + 64], y1 = Sr[dd + 65];
                float r0 = (x0 * c0 - y0 * s0) * sc;
                float r1 = (x1 * c1 - y1 * s1) * sc;
                float u0 = (y0 * c0 + x0 * s0) * sc;
                float u1 = (y1 * c1 + x1 * s1) * sc;
                if (isq) {
                    uint32_t hi, lo;
                    split2h(r0, r1, hi, lo);
                    *(uint32_t*)(ph + dd)      = hi;
                    *(uint32_t*)(pl + dd)      = lo;
                    split2h(u0, u1, hi, lo);
                    *(uint32_t*)(ph + dd + 64) = hi;
                    *(uint32_t*)(pl + dd + 64) = lo;
                } else {
                    *(uint32_t*)(ph + dd)      = pack2h(r0, r1);
                    *(uint32_t*)(ph + dd + 64) = pack2h(u0, u1);
                }
            }
        }
    }
}

// ---------------------------------------------------------------------------
// Causal flash attention on tensor cores (fp16 2-term).
// S = (Qh+Ql)*Kh^T;  O += Ph*(Vh+Vl).
// BM=128 (8 warps x 16 rows), BN=64, HD=128, 256 threads.
// Q hi/lo resident in SMEM; {Kh, Vh, Vl} double-buffered cp.async.
// Row pitch 136 fp16 (272B = 17 x 16B chunks -> conflict-free ldmatrix).
// Output written as fp16 hi/lo for the fp16 2-term out-projection.
// ---------------------------------------------------------------------------
#define APB   272
#define QSZ   (128 * APB)       // 34816
#define KSZ   (64 * APB)        // 17408
#define ATTN_SMEM2 (2 * QSZ + 2 * 3 * KSZ)   // 174080

__global__ __launch_bounds__(256, 1)
void attn_mma()
{
    extern __shared__ char smc[];
    const uint32_t sb = smem_u32(smc);
    const int tid = threadIdx.x;
    const int wid = tid >> 5;
    const int lid = tid & 31;
    const int bh  = blockIdx.y;
    const int qb  = (int)gridDim.x - 1 - (int)blockIdx.x;  // big blocks first
    const int q0  = qb * 128;
    const int ntiles = 2 * qb + 2;

    const __half* qh_g = g_qh + ((size_t)bh * Tz + q0) * HDz;
    const __half* ql_g = g_ql + ((size_t)bh * Tz + q0) * HDz;
    const __half* kh_g = g_kh + (size_t)bh * Tz * HDz;
    const __half* vh_g = g_vh + (size_t)bh * Tz * HDz;
    const __half* vl_g = g_vl + (size_t)bh * Tz * HDz;

    const uint32_t sQh = sb;
    const uint32_t sQl = sb + QSZ;
    const uint32_t sStage = sb + 2 * QSZ;

#pragma unroll
    for (int i = 0; i < 8; ++i) {
        int cc = i * 256 + tid;
        int row = cc >> 4, col = cc & 15;
        CP16(sQh + row * APB + col * 16, qh_g + (size_t)row * HDz + col * 8);
    }
#pragma unroll
    for (int i = 0; i < 8; ++i) {
        int cc = i * 256 + tid;
        int row = cc >> 4, col = cc & 15;
        CP16(sQl + row * APB + col * 16, ql_g + (size_t)row * HDz + col * 8);
    }
    CP_COMMIT();

    auto load_stage = [&](int stage, int j0) {
        const uint32_t base = sStage + stage * (3 * KSZ);
        const __half* gp0 = kh_g + (size_t)j0 * HDz;
        const __half* gp1 = vh_g + (size_t)j0 * HDz;
        const __half* gp2 = vl_g + (size_t)j0 * HDz;
#pragma unroll
        for (int i = 0; i < 4; ++i) {
            int cc = i * 256 + tid;
            int row = cc >> 4, col = cc & 15;
            uint32_t so = (uint32_t)(row * APB + col * 16);
            size_t go = (size_t)row * HDz + col * 8;
            CP16(base + so,           gp0 + go);
            CP16(base + KSZ + so,     gp1 + go);
            CP16(base + 2*KSZ + so,   gp2 + go);
        }
    };

    load_stage(0, 0);
    CP_COMMIT();

    const int qq = lid >> 3;
    const int r8 = lid & 7;
    const int g  = lid >> 2;
    const int t4 = lid & 3;
    const uint32_t qa_off  = (uint32_t)((wid * 16 + (qq & 1) * 8 + r8) * APB);
    const uint32_t ka_row  = (uint32_t)(((qq >> 1) * 8 + r8) * APB);
    const uint32_t va_off  = (uint32_t)((((lid >> 3) & 1) * 8 + (lid & 7)) * APB
                                        + (lid >> 4) * 16);

    float m0v = -1e30f, m1v = -1e30f, l0v = 0.f, l1v = 0.f;
    float o[16][4];
#pragma unroll
    for (int i = 0; i < 16; i++)
#pragma unroll
        for (int j = 0; j < 4; j++) o[i][j] = 0.f;

    for (int kt = 0; kt < ntiles; ++kt) {
        if (kt + 1 < ntiles) {
            load_stage((kt + 1) & 1, (kt + 1) * 64);
            CP_COMMIT();
            CP_WAIT(1);
        } else {
            CP_WAIT(0);
        }
        __syncthreads();

        const uint32_t sK  = sStage + (kt & 1) * (3 * KSZ);
        const uint32_t sKh = sK;
        const uint32_t sVh = sK + KSZ;
        const uint32_t sVl = sK + 2 * KSZ;

        const bool active = !(kt == ntiles - 1 && wid < 4);
        if (active) {
            // ---- S = (Qh+Ql) Kh^T ----
            float sf[8][4];
#pragma unroll
            for (int i = 0; i < 8; i++)
#pragma unroll
                for (int j = 0; j < 4; j++) sf[i][j] = 0.f;

#pragma unroll
            for (int kk = 0; kk < 8; ++kk) {
                const uint32_t acol = (uint32_t)((kk * 2 + (qq >> 1)) * 16);
                const uint32_t kcol = (uint32_t)((kk * 2 + (qq & 1)) * 16);
                uint32_t ah0,ah1,ah2,ah3, al0,al1,al2,al3;
                LDSM4(ah0,ah1,ah2,ah3, sQh + qa_off + acol);
                LDSM4(al0,al1,al2,al3, sQl + qa_off + acol);
#pragma unroll
                for (int h2 = 0; h2 < 2; ++h2) {
                    uint32_t b0h[4], b1h[4];
                    const uint32_t r0 = (uint32_t)((2*h2) * 16 * APB);
                    const uint32_t r1 = (uint32_t)((2*h2 + 1) * 16 * APB);
                    LDSM4(b0h[0],b0h[1],b0h[2],b0h[3], sKh + ka_row + r0 + kcol);
                    LDSM4(b1h[0],b1h[1],b1h[2],b1h[3], sKh + ka_row + r1 + kcol);
                    MMAH4(sf[4*h2+0], ah0,ah1,ah2,ah3, b0h[0], b0h[1]);
                    MMAH4(sf[4*h2+1], ah0,ah1,ah2,ah3, b0h[2], b0h[3]);
                    MMAH4(sf[4*h2+2], ah0,ah1,ah2,ah3, b1h[0], b1h[1]);
                    MMAH4(sf[4*h2+3], ah0,ah1,ah2,ah3, b1h[2], b1h[3]);
                    MMAH4(sf[4*h2+0], al0,al1,al2,al3, b0h[0], b0h[1]);
                    MMAH4(sf[4*h2+1], al0,al1,al2,al3, b0h[2], b0h[3]);
                    MMAH4(sf[4*h2+2], al0,al1,al2,al3, b1h[0], b1h[1]);
                    MMAH4(sf[4*h2+3], al0,al1,al2,al3, b1h[2], b1h[3]);
                }
            }

            // ---- causal mask ----
            if (kt == ntiles - 2) {
                if (wid < 4) {
                    const int i0 = wid * 16 + g;
                    const int i1 = i0 + 8;
#pragma unroll
                    for (int ns = 0; ns < 8; ++ns) {
                        const int jc = ns * 8 + t4 * 2;
                        if (jc     > i0) sf[ns][0] = -1e30f;
                        if (jc + 1 > i0) sf[ns][1] = -1e30f;
                        if (jc     > i1) sf[ns][2] = -1e30f;
                        if (jc + 1 > i1) sf[ns][3] = -1e30f;
                    }
                }
            } else if (kt == ntiles - 1) {
                const int i0 = wid * 16 + g - 64;
                const int i1 = i0 + 8;
#pragma unroll
                for (int ns = 0; ns < 8; ++ns) {
                    const int jc = ns * 8 + t4 * 2;
                    if (jc     > i0) sf[ns][0] = -1e30f;
                    if (jc + 1 > i0) sf[ns][1] = -1e30f;
                    if (jc     > i1) sf[ns][2] = -1e30f;
                    if (jc + 1 > i1) sf[ns][3] = -1e30f;
                }
            }

            // ---- online softmax ----
            float rm0 = -1e30f, rm1 = -1e30f;
#pragma unroll
            for (int ns = 0; ns < 8; ++ns) {
                rm0 = fmaxf(rm0, fmaxf(sf[ns][0], sf[ns][1]));
                rm1 = fmaxf(rm1, fmaxf(sf[ns][2], sf[ns][3]));
            }
            rm0 = fmaxf(rm0, __shfl_xor_sync(0xffffffffu, rm0, 1));
            rm0 = fmaxf(rm0, __shfl_xor_sync(0xffffffffu, rm0, 2));
            rm1 = fmaxf(rm1, __shfl_xor_sync(0xffffffffu, rm1, 1));
            rm1 = fmaxf(rm1, __shfl_xor_sync(0xffffffffu, rm1, 2));
            const float mn0 = fmaxf(m0v, rm0);
            const float mn1 = fmaxf(m1v, rm1);
            const float corr0 = __expf(m0v - mn0);
            const float corr1 = __expf(m1v - mn1);
            m0v = mn0; m1v = mn1;
            float rs0 = 0.f, rs1 = 0.f;
#pragma unroll
            for (int ns = 0; ns < 8; ++ns) {
                float p0 = __expf(sf[ns][0] - mn0);
                float p1 = __expf(sf[ns][1] - mn0);
                float p2 = __expf(sf[ns][2] - mn1);
                float p3 = __expf(sf[ns][3] - mn1);
                sf[ns][0] = p0; sf[ns][1] = p1; sf[ns][2] = p2; sf[ns][3] = p3;
                rs0 += p0 + p1; rs1 += p2 + p3;
            }
            rs0 += __shfl_xor_sync(0xffffffffu, rs0, 1);
            rs0 += __shfl_xor_sync(0xffffffffu, rs0, 2);
            rs1 += __shfl_xor_sync(0xffffffffu, rs1, 1);
            rs1 += __shfl_xor_sync(0xffffffffu, rs1, 2);
            l0v = l0v * corr0 + rs0;
            l1v = l1v * corr1 + rs1;
#pragma unroll
            for (int ns = 0; ns < 16; ++ns) {
                o[ns][0] *= corr0; o[ns][1] *= corr0;
                o[ns][2] *= corr1; o[ns][3] *= corr1;
            }

            // ---- P fragments (fp16 hi only; P in [0,1]) ----
            uint32_t pah[4][4];
#pragma unroll
            for (int kk = 0; kk < 4; ++kk) {
                pah[kk][0] = pack2h(sf[2*kk][0],   sf[2*kk][1]);
                pah[kk][1] = pack2h(sf[2*kk][2],   sf[2*kk][3]);
                pah[kk][2] = pack2h(sf[2*kk+1][0], sf[2*kk+1][1]);
                pah[kk][3] = pack2h(sf[2*kk+1][2], sf[2*kk+1][3]);
            }

            // ---- O += Ph (Vh + Vl) ----
#pragma unroll
            for (int kk = 0; kk < 4; ++kk) {
                const uint32_t vrow = (uint32_t)(kk * 16 * APB) + va_off;
#pragma unroll
                for (int dp = 0; dp < 4; ++dp) {
                    uint32_t v0h[4], v1h[4], v0l[4], v1l[4];
                    LDSM4T(v0h[0],v0h[1],v0h[2],v0h[3], sVh + vrow + dp*64);
                    LDSM4T(v1h[0],v1h[1],v1h[2],v1h[3], sVh + vrow + dp*64 + 32);
                    LDSM4T(v0l[0],v0l[1],v0l[2],v0l[3], sVl + vrow + dp*64);
                    LDSM4T(v1l[0],v1l[1],v1l[2],v1l[3], sVl + vrow + dp*64 + 32);
                    MMAH4(o[4*dp+0], pah[kk][0],pah[kk][1],pah[kk][2],pah[kk][3], v0h[0], v0h[1]);
                    MMAH4(o[4*dp+1], pah[kk][0],pah[kk][1],pah[kk][2],pah[kk][3], v0h[2], v0h[3]);
                    MMAH4(o[4*dp+2], pah[kk][0],pah[kk][1],pah[kk][2],pah[kk][3], v1h[0], v1h[1]);
                    MMAH4(o[4*dp+3], pah[kk][0],pah[kk][1],pah[kk][2],pah[kk][3], v1h[2], v1h[3]);
                    MMAH4(o[4*dp+0], pah[kk][0],pah[kk][1],pah[kk][2],pah[kk][3], v0l[0], v0l[1]);
                    MMAH4(o[4*dp+1], pah[kk][0],pah[kk][1],pah[kk][2],pah[kk][3], v0l[2], v0l[3]);
                    MMAH4(o[4*dp+2], pah[kk][0],pah[kk][1],pah[kk][2],pah[kk][3], v1l[0], v1l[1]);
                    MMAH4(o[4*dp+3], pah[kk][0],pah[kk][1],pah[kk][2],pah[kk][3], v1l[2], v1l[3]);
                }
            }
        }
        __syncthreads();
    }

    // Finalize + store fp16 hi/lo (input to the fp16 2-term out-projection)
    const int b  = bh >> 4;
    const int hh = bh & 15;
    const float inv0 = 1.f / l0v;
    const float inv1 = 1.f / l1v;
    const size_t rb0 = ((size_t)b * Tz + q0 + wid * 16 + g) * Dz + hh * HDz;
    const size_t rb1 = rb0 + (size_t)8 * Dz;
#pragma unroll
    for (int ns = 0; ns < 16; ++ns) {
        const int dcol = ns * 8 + t4 * 2;
        uint32_t hi, lo;
        split2h(o[ns][0] * inv0, o[ns][1] * inv0, hi, lo);
        *(uint32_t*)(g_oh + rb0 + dcol) = hi;
        *(uint32_t*)(g_ol + rb0 + dcol) = lo;
        split2h(o[ns][2] * inv1, o[ns][3] * inv1, hi, lo);
        *(uint32_t*)(g_oh + rb1 + dcol) = hi;
        *(uint32_t*)(g_ol + rb1 + dcol) = lo;
    }
}

// ---------------------------------------------------------------------------
extern "C" void kernel_launch(void* const* d_in, const int* in_sizes, int n_in,
                              void* d_out, int out_size)
{
    const float* x     = (const float*)d_in[0];
    const float* cosT  = (const float*)d_in[1];
    const float* sinT  = (const float*)d_in[2];
    const float* w_qkv = (const float*)d_in[3];
    const float* w_out = (const float*)d_in[4];
    float* out = (float*)d_out;

    cudaFuncSetAttribute(mma_gemm<0>,
                         cudaFuncAttributeMaxDynamicSharedMemorySize, GSMEM);
    cudaFuncSetAttribute(mma_gemm<1>,
                         cudaFuncAttributeMaxDynamicSharedMemorySize, GSMEM);
    cudaFuncSetAttribute(attn_mma,
                         cudaFuncAttributeMaxDynamicSharedMemorySize, ATTN_SMEM2);

    // 0. Split inputs to fp16 (x: hi+lo; weights: hi only)
    split_kernel<0><<<(Mz * Dz) / 1024, 256>>>(x, (size_t)Mz * Dz);
    split_kernel<1><<<(3 * Dz * Dz) / 1024, 256>>>(w_qkv, (size_t)3 * Dz * Dz);
    split_kernel<2><<<(Dz * Dz) / 1024, 256>>>(w_out, (size_t)Dz * Dz);

    // 1. QKV projection (fp16 2-term) + fused RoPE epilogue
    mma_gemm<0><<<dim3(48, 64), 256, GSMEM>>>(nullptr, cosT, sinT);

    // 2. Causal flash attention (fp16 2-term tensor cores) -> o fp16 hi/lo
    attn_mma<<<dim3(Tz / 128, BHz), 256, ATTN_SMEM2>>>();

    // 3. Output projection (fp16 2-term)
    mma_gemm<1><<<dim3(16, 64), 256, GSMEM>>>(out, nullptr, nullptr);
}

// round 12
// speedup vs baseline: 2.1230x; 1.3928x over previous
#include <cuda_runtime.h>
#include <cuda_bf16.h>
#include <cuda_fp16.h>
#include <math_constants.h>
#include <cstdint>

// Problem constants
#define Bz  4
#define Tz  2048
#define Dz  2048
#define Hz  16
#define HDz 128
#define BHz (Bz*Hz)          // 64
#define Mz  (Bz*Tz)          // 8192

// ---------------------------------------------------------------------------
// Global scratch (device globals: allocation-free per harness rules)
// ---------------------------------------------------------------------------
// Attention operands (fp16): Q hi/lo, K hi only, V hi/lo
__device__ __half g_qh[(size_t)BHz * Tz * HDz];
__device__ __half g_ql[(size_t)BHz * Tz * HDz];
__device__ __half g_kh[(size_t)BHz * Tz * HDz];
__device__ __half g_vh[(size_t)BHz * Tz * HDz];
__device__ __half g_vl[(size_t)BHz * Tz * HDz];

// GEMM operands: fp16 hi only (1-term path: Ah*Bh)
__device__ __half g_xh [(size_t)Mz * Dz];
__device__ __half g_wqh[(size_t)3 * Dz * Dz];
__device__ __half g_woh[(size_t)Dz * Dz];
__device__ __half g_oh [(size_t)Mz * Dz];   // attention out (fp16)

// ---------------------------------------------------------------------------
// PTX helpers (base sm_100 — NO 'a'-gated instructions)
// ---------------------------------------------------------------------------
__device__ __forceinline__ uint32_t smem_u32(const void* p) {
    uint32_t a;
    asm("{ .reg .u64 t; cvta.to.shared.u64 t, %1; cvt.u32.u64 %0, t; }"
        : "=r"(a) : "l"(p));
    return a;
}

#define CP16(saddr, gptr) \
    asm volatile("cp.async.cg.shared.global [%0], [%1], 16;" \
                 :: "r"(saddr), "l"(gptr) : "memory")
#define CP_COMMIT() asm volatile("cp.async.commit_group;" ::: "memory")
#define CP_WAIT(n)  asm volatile("cp.async.wait_group %0;" :: "n"(n) : "memory")

#define LDSM4(r0, r1, r2, r3, a) \
    asm volatile("ldmatrix.sync.aligned.m8n8.x4.shared.b16 {%0,%1,%2,%3}, [%4];" \
                 : "=r"(r0), "=r"(r1), "=r"(r2), "=r"(r3) : "r"(a))
#define LDSM4T(r0, r1, r2, r3, a) \
    asm volatile("ldmatrix.sync.aligned.m8n8.x4.trans.shared.b16 {%0,%1,%2,%3}, [%4];" \
                 : "=r"(r0), "=r"(r1), "=r"(r2), "=r"(r3) : "r"(a))

// fp16 mma, array A-frag form (projection GEMMs)
#define MMAH(d, a, b) \
    asm volatile("mma.sync.aligned.m16n8k16.row.col.f32.f16.f16.f32 " \
                 "{%0,%1,%2,%3}, {%4,%5,%6,%7}, {%8,%9}, {%0,%1,%2,%3};" \
                 : "+f"((d)[0]), "+f"((d)[1]), "+f"((d)[2]), "+f"((d)[3]) \
                 : "r"((a)[0]), "r"((a)[1]), "r"((a)[2]), "r"((a)[3]), \
                   "r"((b)[0]), "r"((b)[1]))

// fp16 mma, scalar-frag form (attention)
#define MMAH4(d, a0, a1, a2, a3, b0, b1) \
    asm volatile("mma.sync.aligned.m16n8k16.row.col.f32.f16.f16.f32 " \
                 "{%0,%1,%2,%3}, {%4,%5,%6,%7}, {%8,%9}, {%0,%1,%2,%3};" \
                 : "+f"((d)[0]), "+f"((d)[1]), "+f"((d)[2]), "+f"((d)[3]) \
                 : "r"(a0), "r"(a1), "r"(a2), "r"(a3), "r"(b0), "r"(b1))

// Split pair of floats into packed fp16 hi + fp16 lo (residual)
__device__ __forceinline__ void split2h(float x, float y, uint32_t& hi, uint32_t& lo) {
    __half hx = __float2half_rn(x);
    __half hy = __float2half_rn(y);
    __half2 H; H.x = hx; H.y = hy;
    hi = *(uint32_t*)&H;
    __half2 L;
    L.x = __float2half_rn(x - __half2float(hx));
    L.y = __float2half_rn(y - __half2float(hy));
    lo = *(uint32_t*)&L;
}

// Pack pair of floats into fp16x2 (hi only)
__device__ __forceinline__ uint32_t pack2h(float x, float y) {
    __half2 H; H.x = __float2half_rn(x); H.y = __float2half_rn(y);
    return *(uint32_t*)&H;
}

// ---------------------------------------------------------------------------
// Convert fp32 -> fp16 (hi only).  W=0: x, W=1: w_qkv, W=2: w_out.
// ---------------------------------------------------------------------------
template<int W>
__global__ void split_kernel(const float* __restrict__ src, size_t n)
{
    size_t i = ((size_t)blockIdx.x * 256 + threadIdx.x) * 4;
    if (i >= n) return;
    float4 v = *(const float4*)(src + i);
    __half* hi = (W == 0) ? g_xh : ((W == 1) ? g_wqh : g_woh);
    *(uint32_t*)(hi + i)     = pack2h(v.x, v.y);
    *(uint32_t*)(hi + i + 2) = pack2h(v.z, v.w);
}

// ---------------------------------------------------------------------------
// fp16 1-term tensor-core GEMM.  C = Ah * Bh^T.  128x128 CTA tile,
// 8 warps (2x4), warp tile 64x32, K-chunk 32, 3-stage cp.async pipeline,
// 1 CTA/SM.  RPITCH=80 (conflict-free ldmatrix without swizzle).
// MODE 0: A=x, B=w_qkv; epilogue: q -> RoPE+scale fp16 hi/lo; k -> RoPE fp16
//         hi only; v -> fp16 hi/lo.
// MODE 1: A=g_oh, B=w_out; epilogue writes C (fp32).
// ---------------------------------------------------------------------------
#define RPITCH   80
#define SBUF     (128 * RPITCH)          // 10240
#define STAGEB   (2 * SBUF)              // 20480: Ah, Bh
#define NSTAGE   3
#define GSMEM    67584                   // epilogue Sf (128x132 fp32) dominates

template<int MODE>
__global__ __launch_bounds__(256, 1)
void mma_gemm(float* __restrict__ C,
              const float* __restrict__ cosT,
              const float* __restrict__ sinT)
{
    extern __shared__ char smc[];
    const uint32_t sb = smem_u32(smc);
    const int tid = threadIdx.x;
    const int wid = tid >> 5;
    const int lid = tid & 31;
    const int wm  = wid & 1;          // 0..1  (64 rows each)
    const int wn  = wid >> 1;         // 0..3  (32 cols each)
    const int m0  = blockIdx.y * 128;
    const int n0  = blockIdx.x * 128;

    const __half* Ah = ((MODE == 0) ? g_xh  : g_oh ) + (size_t)m0 * 2048;
    const __half* Bh = ((MODE == 0) ? g_wqh : g_woh) + (size_t)n0 * 2048;

    const int crow = tid >> 1;
    const int cc0  = (tid & 1) * 2;
    const uint32_t soff = (uint32_t)(crow * RPITCH + cc0 * 16);

    auto load_chunk = [&](uint32_t st, int kc) {
        const size_t gi = (size_t)crow * 2048 + kc * 32 + cc0 * 8;
        CP16(st + soff,                Ah + gi);
        CP16(st + soff + 16,           Ah + gi + 8);
        CP16(st + SBUF + soff,         Bh + gi);
        CP16(st + SBUF + soff + 16,    Bh + gi + 8);
    };

    float d[4][4][4];
#pragma unroll
    for (int i = 0; i < 4; i++)
#pragma unroll
        for (int j = 0; j < 4; j++)
#pragma unroll
            for (int k = 0; k < 4; k++) d[i][j][k] = 0.f;

#pragma unroll
    for (int s = 0; s < NSTAGE; s++) {
        load_chunk(sb + s * STAGEB, s);
        CP_COMMIT();
    }

    const int q  = lid >> 3;
    const int r8 = lid & 7;
    const int arow = wm * 64 + (q & 1) * 8 + r8;
    const int bfr  = q >> 1;
    const int bch  = q & 1;
    const int brow0 = wn * 32 + bfr * 8 + r8;

    for (int c = 0; c < 64; ++c) {
        CP_WAIT(2);
        __syncthreads();
        const uint32_t st  = sb + (c % NSTAGE) * STAGEB;
        const uint32_t sA  = st;
        const uint32_t sB  = st + SBUF;

#pragma unroll
        for (int kk = 0; kk < 2; ++kk) {
            const int ck = kk * 2;
            uint32_t ah[4][4], bh[4][2];
            const uint32_t aoff = (uint32_t)(arow * RPITCH + (ck + (q >> 1)) * 16);
#pragma unroll
            for (int mi = 0; mi < 4; ++mi)
                LDSM4(ah[mi][0], ah[mi][1], ah[mi][2], ah[mi][3],
                      sA + aoff + mi * 16 * RPITCH);

            const uint32_t boff = (uint32_t)(brow0 * RPITCH + (ck + bch) * 16);
            {
                uint32_t t0,t1,t2,t3;
                LDSM4(t0,t1,t2,t3, sB + boff);
                bh[0][0]=t0; bh[0][1]=t1; bh[1][0]=t2; bh[1][1]=t3;
                LDSM4(t0,t1,t2,t3, sB + boff + 16 * RPITCH);
                bh[2][0]=t0; bh[2][1]=t1; bh[3][0]=t2; bh[3][1]=t3;
            }
#pragma unroll
            for (int mi = 0; mi < 4; ++mi)
#pragma unroll
                for (int ni = 0; ni < 4; ++ni)
                    MMAH(d[mi][ni], ah[mi], bh[ni]);
        }
        __syncthreads();

        const int nc = c + NSTAGE;
        if (nc < 64)
            load_chunk(sb + (c % NSTAGE) * STAGEB, nc);
        CP_COMMIT();
    }

    CP_WAIT(0);
    __syncthreads();

    // Stage fp32 tile in SMEM (pitch 132), then coalesced writers
    float* Sf = (float*)smc;
#pragma unroll
    for (int mi = 0; mi < 4; ++mi) {
        const int r0 = wm * 64 + mi * 16 + (lid >> 2);
#pragma unroll
        for (int ni = 0; ni < 4; ++ni) {
            const int c0 = wn * 32 + ni * 8 + (lid & 3) * 2;
            Sf[r0 * 132 + c0]           = d[mi][ni][0];
            Sf[r0 * 132 + c0 + 1]       = d[mi][ni][1];
            Sf[(r0 + 8) * 132 + c0]     = d[mi][ni][2];
            Sf[(r0 + 8) * 132 + c0 + 1] = d[mi][ni][3];
        }
    }
    __syncthreads();

    if (MODE == 1) {
#pragma unroll
        for (int rr = 0; rr < 16; ++rr) {
            const int row = wid * 16 + rr;
            float4 v = *(const float4*)&Sf[row * 132 + lid * 4];
            *(float4*)(C + (size_t)(m0 + row) * 2048 + n0 + lid * 4) = v;
        }
    } else {
        const int qmode = n0 >> 11;              // 0:q 1:k 2:v
        const int h     = (n0 & 2047) >> 7;
        const int b     = m0 >> 11;
        const int t0    = m0 & 2047;
        const int bhx   = b * Hz + h;
        if (qmode == 2) {
            __half* dh = g_vh + ((size_t)bhx * Tz + t0) * HDz;
            __half* dl = g_vl + ((size_t)bhx * Tz + t0) * HDz;
#pragma unroll
            for (int rr = 0; rr < 16; ++rr) {
                const int row = wid * 16 + rr;
                float4 v = *(const float4*)&Sf[row * 132 + lid * 4];
                uint32_t h0, l0, h1, l1;
                split2h(v.x, v.y, h0, l0);
                split2h(v.z, v.w, h1, l1);
                *(uint32_t*)(dh + (size_t)row * HDz + lid * 4)     = h0;
                *(uint32_t*)(dh + (size_t)row * HDz + lid * 4 + 2) = h1;
                *(uint32_t*)(dl + (size_t)row * HDz + lid * 4)     = l0;
                *(uint32_t*)(dl + (size_t)row * HDz + lid * 4 + 2) = l1;
            }
        } else {
            // Fused RoPE: rotate pairs (d, d+64); q: scale + hi/lo; k: hi only
            const bool isq = (qmode == 0);
            __half* dh = (isq ? g_qh : g_kh) + ((size_t)bhx * Tz + t0) * HDz;
            __half* dl = g_ql + ((size_t)bhx * Tz + t0) * HDz;   // used iff isq
            const int row = tid >> 1;
            const int db  = (tid & 1) * 32;
            const int t   = t0 + row;
            const float sc = isq ? 0.08838834764831845f : 1.0f;
            const float* crow_ = cosT + t * HDz + db;
            const float* srow_ = sinT + t * HDz + db;
            const float* Sr = Sf + row * 132 + db;
            __half* ph = dh + (size_t)row * HDz + db;
            __half* pl = dl + (size_t)row * HDz + db;
#pragma unroll
            for (int dd = 0; dd < 32; dd += 2) {
                float c0 = crow_[dd], c1 = crow_[dd + 1];
                float s0 = srow_[dd], s1 = srow_[dd + 1];
                float x0 = Sr[dd],      x1 = Sr[dd + 1];
                float y0 = Sr[dd + 64], y1 = Sr[dd + 65];
                float r0 = (x0 * c0 - y0 * s0) * sc;
                float r1 = (x1 * c1 - y1 * s1) * sc;
                float u0 = (y0 * c0 + x0 * s0) * sc;
                float u1 = (y1 * c1 + x1 * s1) * sc;
                if (isq) {
                    uint32_t hi, lo;
                    split2h(r0, r1, hi, lo);
                    *(uint32_t*)(ph + dd)      = hi;
                    *(uint32_t*)(pl + dd)      = lo;
                    split2h(u0, u1, hi, lo);
                    *(uint32_t*)(ph + dd + 64) = hi;
                    *(uint32_t*)(pl + dd + 64) = lo;
                } else {
                    *(uint32_t*)(ph + dd)      = pack2h(r0, r1);
                    *(uint32_t*)(ph + dd + 64) = pack2h(u0, u1);
                }
            }
        }
    }
}

// ---------------------------------------------------------------------------
// Causal flash attention on tensor cores (fp16 2-term).
// S = (Qh+Ql)*Kh^T;  O += Ph*(Vh+Vl).
// BM=128 (8 warps x 16 rows), BN=64, HD=128, 256 threads.
// Q hi/lo resident in SMEM; {Kh, Vh, Vl} double-buffered cp.async.
// Row pitch 136 fp16 (272B = 17 x 16B chunks -> conflict-free ldmatrix).
// Output written as fp16 (hi only) for the fp16 1-term out-projection.
// ---------------------------------------------------------------------------
#define APB   272
#define QSZ   (128 * APB)       // 34816
#define KSZ   (64 * APB)        // 17408
#define ATTN_SMEM2 (2 * QSZ + 2 * 3 * KSZ)   // 174080

__global__ __launch_bounds__(256, 1)
void attn_mma()
{
    extern __shared__ char smc[];
    const uint32_t sb = smem_u32(smc);
    const int tid = threadIdx.x;
    const int wid = tid >> 5;
    const int lid = tid & 31;
    const int bh  = blockIdx.y;
    const int qb  = (int)gridDim.x - 1 - (int)blockIdx.x;  // big blocks first
    const int q0  = qb * 128;
    const int ntiles = 2 * qb + 2;

    const __half* qh_g = g_qh + ((size_t)bh * Tz + q0) * HDz;
    const __half* ql_g = g_ql + ((size_t)bh * Tz + q0) * HDz;
    const __half* kh_g = g_kh + (size_t)bh * Tz * HDz;
    const __half* vh_g = g_vh + (size_t)bh * Tz * HDz;
    const __half* vl_g = g_vl + (size_t)bh * Tz * HDz;

    const uint32_t sQh = sb;
    const uint32_t sQl = sb + QSZ;
    const uint32_t sStage = sb + 2 * QSZ;

#pragma unroll
    for (int i = 0; i < 8; ++i) {
        int cc = i * 256 + tid;
        int row = cc >> 4, col = cc & 15;
        CP16(sQh + row * APB + col * 16, qh_g + (size_t)row * HDz + col * 8);
    }
#pragma unroll
    for (int i = 0; i < 8; ++i) {
        int cc = i * 256 + tid;
        int row = cc >> 4, col = cc & 15;
        CP16(sQl + row * APB + col * 16, ql_g + (size_t)row * HDz + col * 8);
    }
    CP_COMMIT();

    auto load_stage = [&](int stage, int j0) {
        const uint32_t base = sStage + stage * (3 * KSZ);
        const __half* gp0 = kh_g + (size_t)j0 * HDz;
        const __half* gp1 = vh_g + (size_t)j0 * HDz;
        const __half* gp2 = vl_g + (size_t)j0 * HDz;
#pragma unroll
        for (int i = 0; i < 4; ++i) {
            int cc = i * 256 + tid;
            int row = cc >> 4, col = cc & 15;
            uint32_t so = (uint32_t)(row * APB + col * 16);
            size_t go = (size_t)row * HDz + col * 8;
            CP16(base + so,           gp0 + go);
            CP16(base + KSZ + so,     gp1 + go);
            CP16(base + 2*KSZ + so,   gp2 + go);
        }
    };

    load_stage(0, 0);
    CP_COMMIT();

    const int qq = lid >> 3;
    const int r8 = lid & 7;
    const int g  = lid >> 2;
    const int t4 = lid & 3;
    const uint32_t qa_off  = (uint32_t)((wid * 16 + (qq & 1) * 8 + r8) * APB);
    const uint32_t ka_row  = (uint32_t)(((qq >> 1) * 8 + r8) * APB);
    const uint32_t va_off  = (uint32_t)((((lid >> 3) & 1) * 8 + (lid & 7)) * APB
                                        + (lid >> 4) * 16);

    float m0v = -1e30f, m1v = -1e30f, l0v = 0.f, l1v = 0.f;
    float o[16][4];
#pragma unroll
    for (int i = 0; i < 16; i++)
#pragma unroll
        for (int j = 0; j < 4; j++) o[i][j] = 0.f;

    for (int kt = 0; kt < ntiles; ++kt) {
        if (kt + 1 < ntiles) {
            load_stage((kt + 1) & 1, (kt + 1) * 64);
            CP_COMMIT();
            CP_WAIT(1);
        } else {
            CP_WAIT(0);
        }
        __syncthreads();

        const uint32_t sK  = sStage + (kt & 1) * (3 * KSZ);
        const uint32_t sKh = sK;
        const uint32_t sVh = sK + KSZ;
        const uint32_t sVl = sK + 2 * KSZ;

        const bool active = !(kt == ntiles - 1 && wid < 4);
        if (active) {
            // ---- S = (Qh+Ql) Kh^T ----
            float sf[8][4];
#pragma unroll
            for (int i = 0; i < 8; i++)
#pragma unroll
                for (int j = 0; j < 4; j++) sf[i][j] = 0.f;

#pragma unroll
            for (int kk = 0; kk < 8; ++kk) {
                const uint32_t acol = (uint32_t)((kk * 2 + (qq >> 1)) * 16);
                const uint32_t kcol = (uint32_t)((kk * 2 + (qq & 1)) * 16);
                uint32_t ah0,ah1,ah2,ah3, al0,al1,al2,al3;
                LDSM4(ah0,ah1,ah2,ah3, sQh + qa_off + acol);
                LDSM4(al0,al1,al2,al3, sQl + qa_off + acol);
#pragma unroll
                for (int h2 = 0; h2 < 2; ++h2) {
                    uint32_t b0h[4], b1h[4];
                    const uint32_t r0 = (uint32_t)((2*h2) * 16 * APB);
                    const uint32_t r1 = (uint32_t)((2*h2 + 1) * 16 * APB);
                    LDSM4(b0h[0],b0h[1],b0h[2],b0h[3], sKh + ka_row + r0 + kcol);
                    LDSM4(b1h[0],b1h[1],b1h[2],b1h[3], sKh + ka_row + r1 + kcol);
                    MMAH4(sf[4*h2+0], ah0,ah1,ah2,ah3, b0h[0], b0h[1]);
                    MMAH4(sf[4*h2+1], ah0,ah1,ah2,ah3, b0h[2], b0h[3]);
                    MMAH4(sf[4*h2+2], ah0,ah1,ah2,ah3, b1h[0], b1h[1]);
                    MMAH4(sf[4*h2+3], ah0,ah1,ah2,ah3, b1h[2], b1h[3]);
                    MMAH4(sf[4*h2+0], al0,al1,al2,al3, b0h[0], b0h[1]);
                    MMAH4(sf[4*h2+1], al0,al1,al2,al3, b0h[2], b0h[3]);
                    MMAH4(sf[4*h2+2], al0,al1,al2,al3, b1h[0], b1h[1]);
                    MMAH4(sf[4*h2+3], al0,al1,al2,al3, b1h[2], b1h[3]);
                }
            }

            // ---- causal mask ----
            if (kt == ntiles - 2) {
                if (wid < 4) {
                    const int i0 = wid * 16 + g;
                    const int i1 = i0 + 8;
#pragma unroll
                    for (int ns = 0; ns < 8; ++ns) {
                        const int jc = ns * 8 + t4 * 2;
                        if (jc     > i0) sf[ns][0] = -1e30f;
                        if (jc + 1 > i0) sf[ns][1] = -1e30f;
                        if (jc     > i1) sf[ns][2] = -1e30f;
                        if (jc + 1 > i1) sf[ns][3] = -1e30f;
                    }
                }
            } else if (kt == ntiles - 1) {
                const int i0 = wid * 16 + g - 64;
                const int i1 = i0 + 8;
#pragma unroll
                for (int ns = 0; ns < 8; ++ns) {
                    const int jc = ns * 8 + t4 * 2;
                    if (jc     > i0) sf[ns][0] = -1e30f;
                    if (jc + 1 > i0) sf[ns][1] = -1e30f;
                    if (jc     > i1) sf[ns][2] = -1e30f;
                    if (jc + 1 > i1) sf[ns][3] = -1e30f;
                }
            }

            // ---- online softmax ----
            float rm0 = -1e30f, rm1 = -1e30f;
#pragma unroll
            for (int ns = 0; ns < 8; ++ns) {
                rm0 = fmaxf(rm0, fmaxf(sf[ns][0], sf[ns][1]));
                rm1 = fmaxf(rm1, fmaxf(sf[ns][2], sf[ns][3]));
            }
            rm0 = fmaxf(rm0, __shfl_xor_sync(0xffffffffu, rm0, 1));
            rm0 = fmaxf(rm0, __shfl_xor_sync(0xffffffffu, rm0, 2));
            rm1 = fmaxf(rm1, __shfl_xor_sync(0xffffffffu, rm1, 1));
            rm1 = fmaxf(rm1, __shfl_xor_sync(0xffffffffu, rm1, 2));
            const float mn0 = fmaxf(m0v, rm0);
            const float mn1 = fmaxf(m1v, rm1);
            const float corr0 = __expf(m0v - mn0);
            const float corr1 = __expf(m1v - mn1);
            m0v = mn0; m1v = mn1;
            float rs0 = 0.f, rs1 = 0.f;
#pragma unroll
            for (int ns = 0; ns < 8; ++ns) {
                float p0 = __expf(sf[ns][0] - mn0);
                float p1 = __expf(sf[ns][1] - mn0);
                float p2 = __expf(sf[ns][2] - mn1);
                float p3 = __expf(sf[ns][3] - mn1);
                sf[ns][0] = p0; sf[ns][1] = p1; sf[ns][2] = p2; sf[ns][3] = p3;
                rs0 += p0 + p1; rs1 += p2 + p3;
            }
            rs0 += __shfl_xor_sync(0xffffffffu, rs0, 1);
            rs0 += __shfl_xor_sync(0xffffffffu, rs0, 2);
            rs1 += __shfl_xor_sync(0xffffffffu, rs1, 1);
            rs1 += __shfl_xor_sync(0xffffffffu, rs1, 2);
            l0v = l0v * corr0 + rs0;
            l1v = l1v * corr1 + rs1;
#pragma unroll
            for (int ns = 0; ns < 16; ++ns) {
                o[ns][0] *= corr0; o[ns][1] *= corr0;
                o[ns][2] *= corr1; o[ns][3] *= corr1;
            }

            // ---- P fragments (fp16 hi only; P in [0,1]) ----
            uint32_t pah[4][4];
#pragma unroll
            for (int kk = 0; kk < 4; ++kk) {
                pah[kk][0] = pack2h(sf[2*kk][0],   sf[2*kk][1]);
                pah[kk][1] = pack2h(sf[2*kk][2],   sf[2*kk][3]);
                pah[kk][2] = pack2h(sf[2*kk+1][0], sf[2*kk+1][1]);
                pah[kk][3] = pack2h(sf[2*kk+1][2], sf[2*kk+1][3]);
            }

            // ---- O += Ph (Vh + Vl) ----
#pragma unroll
            for (int kk = 0; kk < 4; ++kk) {
                const uint32_t vrow = (uint32_t)(kk * 16 * APB) + va_off;
#pragma unroll
                for (int dp = 0; dp < 4; ++dp) {
                    uint32_t v0h[4], v1h[4], v0l[4], v1l[4];
                    LDSM4T(v0h[0],v0h[1],v0h[2],v0h[3], sVh + vrow + dp*64);
                    LDSM4T(v1h[0],v1h[1],v1h[2],v1h[3], sVh + vrow + dp*64 + 32);
                    LDSM4T(v0l[0],v0l[1],v0l[2],v0l[3], sVl + vrow + dp*64);
                    LDSM4T(v1l[0],v1l[1],v1l[2],v1l[3], sVl + vrow + dp*64 + 32);
                    MMAH4(o[4*dp+0], pah[kk][0],pah[kk][1],pah[kk][2],pah[kk][3], v0h[0], v0h[1]);
                    MMAH4(o[4*dp+1], pah[kk][0],pah[kk][1],pah[kk][2],pah[kk][3], v0h[2], v0h[3]);
                    MMAH4(o[4*dp+2], pah[kk][0],pah[kk][1],pah[kk][2],pah[kk][3], v1h[0], v1h[1]);
                    MMAH4(o[4*dp+3], pah[kk][0],pah[kk][1],pah[kk][2],pah[kk][3], v1h[2], v1h[3]);
                    MMAH4(o[4*dp+0], pah[kk][0],pah[kk][1],pah[kk][2],pah[kk][3], v0l[0], v0l[1]);
                    MMAH4(o[4*dp+1], pah[kk][0],pah[kk][1],pah[kk][2],pah[kk][3], v0l[2], v0l[3]);
                    MMAH4(o[4*dp+2], pah[kk][0],pah[kk][1],pah[kk][2],pah[kk][3], v1l[0], v1l[1]);
                    MMAH4(o[4*dp+3], pah[kk][0],pah[kk][1],pah[kk][2],pah[kk][3], v1l[2], v1l[3]);
                }
            }
        }
        __syncthreads();
    }

    // Finalize + store fp16 (hi only) for the fp16 1-term out-projection
    const int b  = bh >> 4;
    const int hh = bh & 15;
    const float inv0 = 1.f / l0v;
    const float inv1 = 1.f / l1v;
    const size_t rb0 = ((size_t)b * Tz + q0 + wid * 16 + g) * Dz + hh * HDz;
    const size_t rb1 = rb0 + (size_t)8 * Dz;
#pragma unroll
    for (int ns = 0; ns < 16; ++ns) {
        const int dcol = ns * 8 + t4 * 2;
        *(uint32_t*)(g_oh + rb0 + dcol) = pack2h(o[ns][0] * inv0, o[ns][1] * inv0);
        *(uint32_t*)(g_oh + rb1 + dcol) = pack2h(o[ns][2] * inv1, o[ns][3] * inv1);
    }
}

// ---------------------------------------------------------------------------
extern "C" void kernel_launch(void* const* d_in, const int* in_sizes, int n_in,
                              void* d_out, int out_size)
{
    const float* x     = (const float*)d_in[0];
    const float* cosT  = (const float*)d_in[1];
    const float* sinT  = (const float*)d_in[2];
    const float* w_qkv = (const float*)d_in[3];
    const float* w_out = (const float*)d_in[4];
    float* out = (float*)d_out;

    cudaFuncSetAttribute(mma_gemm<0>,
                         cudaFuncAttributeMaxDynamicSharedMemorySize, GSMEM);
    cudaFuncSetAttribute(mma_gemm<1>,
                         cudaFuncAttributeMaxDynamicSharedMemorySize, GSMEM);
    cudaFuncSetAttribute(attn_mma,
                         cudaFuncAttributeMaxDynamicSharedMemorySize, ATTN_SMEM2);

    // 0. Convert inputs to fp16 (hi only)
    split_kernel<0><<<(Mz * Dz) / 1024, 256>>>(x, (size_t)Mz * Dz);
    split_kernel<1><<<(3 * Dz * Dz) / 1024, 256>>>(w_qkv, (size_t)3 * Dz * Dz);
    split_kernel<2><<<(Dz * Dz) / 1024, 256>>>(w_out, (size_t)Dz * Dz);

    // 1. QKV projection (fp16 1-term) + fused RoPE epilogue
    mma_gemm<0><<<dim3(48, 64), 256, GSMEM>>>(nullptr, cosT, sinT);

    // 2. Causal flash attention (fp16 2-term tensor cores) -> o fp16
    attn_mma<<<dim3(Tz / 128, BHz), 256, ATTN_SMEM2>>>();

    // 3. Output projection (fp16 1-term)
    mma_gemm<1><<<dim3(16, 64), 256, GSMEM>>>(out, nullptr, nullptr);
}

// round 13
// speedup vs baseline: 2.3401x; 1.1023x over previous
#include <cuda_runtime.h>
#include <cuda_bf16.h>
#include <cuda_fp16.h>
#include <math_constants.h>
#include <cstdint>

// Problem constants
#define Bz  4
#define Tz  2048
#define Dz  2048
#define Hz  16
#define HDz 128
#define BHz (Bz*Hz)          // 64
#define Mz  (Bz*Tz)          // 8192

// ---------------------------------------------------------------------------
// Global scratch (device globals: allocation-free per harness rules)
// ---------------------------------------------------------------------------
// Attention operands (fp16): Q hi/lo, K hi only, V hi/lo
__device__ __half g_qh[(size_t)BHz * Tz * HDz];
__device__ __half g_ql[(size_t)BHz * Tz * HDz];
__device__ __half g_kh[(size_t)BHz * Tz * HDz];
__device__ __half g_vh[(size_t)BHz * Tz * HDz];
__device__ __half g_vl[(size_t)BHz * Tz * HDz];

// GEMM operands: fp16 hi only (1-term path: Ah*Bh)
__device__ __half g_xh [(size_t)Mz * Dz];
__device__ __half g_wqh[(size_t)3 * Dz * Dz];
__device__ __half g_woh[(size_t)Dz * Dz];
__device__ __half g_oh [(size_t)Mz * Dz];   // attention out (fp16)

// ---------------------------------------------------------------------------
// PTX helpers (base sm_100 — NO 'a'-gated instructions)
// ---------------------------------------------------------------------------
__device__ __forceinline__ uint32_t smem_u32(const void* p) {
    uint32_t a;
    asm("{ .reg .u64 t; cvta.to.shared.u64 t, %1; cvt.u32.u64 %0, t; }"
        : "=r"(a) : "l"(p));
    return a;
}

#define CP16(saddr, gptr) \
    asm volatile("cp.async.cg.shared.global [%0], [%1], 16;" \
                 :: "r"(saddr), "l"(gptr) : "memory")
#define CP_COMMIT() asm volatile("cp.async.commit_group;" ::: "memory")
#define CP_WAIT(n)  asm volatile("cp.async.wait_group %0;" :: "n"(n) : "memory")

#define LDSM4(r0, r1, r2, r3, a) \
    asm volatile("ldmatrix.sync.aligned.m8n8.x4.shared.b16 {%0,%1,%2,%3}, [%4];" \
                 : "=r"(r0), "=r"(r1), "=r"(r2), "=r"(r3) : "r"(a))
#define LDSM4T(r0, r1, r2, r3, a) \
    asm volatile("ldmatrix.sync.aligned.m8n8.x4.trans.shared.b16 {%0,%1,%2,%3}, [%4];" \
                 : "=r"(r0), "=r"(r1), "=r"(r2), "=r"(r3) : "r"(a))

// fp16 mma, array A-frag form (projection GEMMs)
#define MMAH(d, a, b) \
    asm volatile("mma.sync.aligned.m16n8k16.row.col.f32.f16.f16.f32 " \
                 "{%0,%1,%2,%3}, {%4,%5,%6,%7}, {%8,%9}, {%0,%1,%2,%3};" \
                 : "+f"((d)[0]), "+f"((d)[1]), "+f"((d)[2]), "+f"((d)[3]) \
                 : "r"((a)[0]), "r"((a)[1]), "r"((a)[2]), "r"((a)[3]), \
                   "r"((b)[0]), "r"((b)[1]))

// fp16 mma, scalar-frag form (attention)
#define MMAH4(d, a0, a1, a2, a3, b0, b1) \
    asm volatile("mma.sync.aligned.m16n8k16.row.col.f32.f16.f16.f32 " \
                 "{%0,%1,%2,%3}, {%4,%5,%6,%7}, {%8,%9}, {%0,%1,%2,%3};" \
                 : "+f"((d)[0]), "+f"((d)[1]), "+f"((d)[2]), "+f"((d)[3]) \
                 : "r"(a0), "r"(a1), "r"(a2), "r"(a3), "r"(b0), "r"(b1))

// Split pair of floats into packed fp16 hi + fp16 lo (residual)
__device__ __forceinline__ void split2h(float x, float y, uint32_t& hi, uint32_t& lo) {
    __half hx = __float2half_rn(x);
    __half hy = __float2half_rn(y);
    __half2 H; H.x = hx; H.y = hy;
    hi = *(uint32_t*)&H;
    __half2 L;
    L.x = __float2half_rn(x - __half2float(hx));
    L.y = __float2half_rn(y - __half2float(hy));
    lo = *(uint32_t*)&L;
}

// Pack pair of floats into fp16x2 (hi only)
__device__ __forceinline__ uint32_t pack2h(float x, float y) {
    __half2 H; H.x = __float2half_rn(x); H.y = __float2half_rn(y);
    return *(uint32_t*)&H;
}

// ---------------------------------------------------------------------------
// Convert fp32 -> fp16 (hi only).  W=0: x, W=1: w_qkv, W=2: w_out.
// ---------------------------------------------------------------------------
template<int W>
__global__ void split_kernel(const float* __restrict__ src, size_t n)
{
    size_t i = ((size_t)blockIdx.x * 256 + threadIdx.x) * 4;
    if (i >= n) return;
    float4 v = *(const float4*)(src + i);
    __half* hi = (W == 0) ? g_xh : ((W == 1) ? g_wqh : g_woh);
    *(uint32_t*)(hi + i)     = pack2h(v.x, v.y);
    *(uint32_t*)(hi + i + 2) = pack2h(v.z, v.w);
}

// ---------------------------------------------------------------------------
// fp16 1-term tensor-core GEMM.  C = Ah * Bh^T.  128x128 CTA tile,
// 8 warps (2x4), warp tile 64x32, K-chunk 32, 3-stage cp.async pipeline,
// 2 CTAs/SM (light smem traffic in the 1-term regime; peer CTA hides
// barrier/ldsm latency).  RPITCH=80 (conflict-free ldmatrix, no swizzle).
// MODE 0: A=x, B=w_qkv; epilogue: q -> RoPE+scale fp16 hi/lo; k -> RoPE fp16
//         hi only; v -> fp16 hi/lo.
// MODE 1: A=g_oh, B=w_out; epilogue writes C (fp32).
// ---------------------------------------------------------------------------
#define RPITCH   80
#define SBUF     (128 * RPITCH)          // 10240
#define STAGEB   (2 * SBUF)              // 20480: Ah, Bh
#define NSTAGE   3
#define GSMEM    67584                   // epilogue Sf (128x132 fp32) dominates

template<int MODE>
__global__ __launch_bounds__(256, 2)
void mma_gemm(float* __restrict__ C,
              const float* __restrict__ cosT,
              const float* __restrict__ sinT)
{
    extern __shared__ char smc[];
    const uint32_t sb = smem_u32(smc);
    const int tid = threadIdx.x;
    const int wid = tid >> 5;
    const int lid = tid & 31;
    const int wm  = wid & 1;          // 0..1  (64 rows each)
    const int wn  = wid >> 1;         // 0..3  (32 cols each)
    const int m0  = blockIdx.y * 128;
    const int n0  = blockIdx.x * 128;

    const __half* Ah = ((MODE == 0) ? g_xh  : g_oh ) + (size_t)m0 * 2048;
    const __half* Bh = ((MODE == 0) ? g_wqh : g_woh) + (size_t)n0 * 2048;

    const int crow = tid >> 1;
    const int cc0  = (tid & 1) * 2;
    const uint32_t soff = (uint32_t)(crow * RPITCH + cc0 * 16);

    auto load_chunk = [&](uint32_t st, int kc) {
        const size_t gi = (size_t)crow * 2048 + kc * 32 + cc0 * 8;
        CP16(st + soff,                Ah + gi);
        CP16(st + soff + 16,           Ah + gi + 8);
        CP16(st + SBUF + soff,         Bh + gi);
        CP16(st + SBUF + soff + 16,    Bh + gi + 8);
    };

    float d[4][4][4];
#pragma unroll
    for (int i = 0; i < 4; i++)
#pragma unroll
        for (int j = 0; j < 4; j++)
#pragma unroll
            for (int k = 0; k < 4; k++) d[i][j][k] = 0.f;

#pragma unroll
    for (int s = 0; s < NSTAGE; s++) {
        load_chunk(sb + s * STAGEB, s);
        CP_COMMIT();
    }

    const int q  = lid >> 3;
    const int r8 = lid & 7;
    const int arow = wm * 64 + (q & 1) * 8 + r8;
    const int bfr  = q >> 1;
    const int bch  = q & 1;
    const int brow0 = wn * 32 + bfr * 8 + r8;

    for (int c = 0; c < 64; ++c) {
        CP_WAIT(2);
        __syncthreads();
        const uint32_t st  = sb + (c % NSTAGE) * STAGEB;
        const uint32_t sA  = st;
        const uint32_t sB  = st + SBUF;

#pragma unroll
        for (int kk = 0; kk < 2; ++kk) {
            const int ck = kk * 2;
            uint32_t ah[4][4], bh[4][2];
            const uint32_t aoff = (uint32_t)(arow * RPITCH + (ck + (q >> 1)) * 16);
#pragma unroll
            for (int mi = 0; mi < 4; ++mi)
                LDSM4(ah[mi][0], ah[mi][1], ah[mi][2], ah[mi][3],
                      sA + aoff + mi * 16 * RPITCH);

            const uint32_t boff = (uint32_t)(brow0 * RPITCH + (ck + bch) * 16);
            {
                uint32_t t0,t1,t2,t3;
                LDSM4(t0,t1,t2,t3, sB + boff);
                bh[0][0]=t0; bh[0][1]=t1; bh[1][0]=t2; bh[1][1]=t3;
                LDSM4(t0,t1,t2,t3, sB + boff + 16 * RPITCH);
                bh[2][0]=t0; bh[2][1]=t1; bh[3][0]=t2; bh[3][1]=t3;
            }
#pragma unroll
            for (int mi = 0; mi < 4; ++mi)
#pragma unroll
                for (int ni = 0; ni < 4; ++ni)
                    MMAH(d[mi][ni], ah[mi], bh[ni]);
        }
        __syncthreads();

        const int nc = c + NSTAGE;
        if (nc < 64)
            load_chunk(sb + (c % NSTAGE) * STAGEB, nc);
        CP_COMMIT();
    }

    CP_WAIT(0);
    __syncthreads();

    // Stage fp32 tile in SMEM (pitch 132), then coalesced writers
    float* Sf = (float*)smc;
#pragma unroll
    for (int mi = 0; mi < 4; ++mi) {
        const int r0 = wm * 64 + mi * 16 + (lid >> 2);
#pragma unroll
        for (int ni = 0; ni < 4; ++ni) {
            const int c0 = wn * 32 + ni * 8 + (lid & 3) * 2;
            Sf[r0 * 132 + c0]           = d[mi][ni][0];
            Sf[r0 * 132 + c0 + 1]       = d[mi][ni][1];
            Sf[(r0 + 8) * 132 + c0]     = d[mi][ni][2];
            Sf[(r0 + 8) * 132 + c0 + 1] = d[mi][ni][3];
        }
    }
    __syncthreads();

    if (MODE == 1) {
#pragma unroll
        for (int rr = 0; rr < 16; ++rr) {
            const int row = wid * 16 + rr;
            float4 v = *(const float4*)&Sf[row * 132 + lid * 4];
            *(float4*)(C + (size_t)(m0 + row) * 2048 + n0 + lid * 4) = v;
        }
    } else {
        const int qmode = n0 >> 11;              // 0:q 1:k 2:v
        const int h     = (n0 & 2047) >> 7;
        const int b     = m0 >> 11;
        const int t0    = m0 & 2047;
        const int bhx   = b * Hz + h;
        if (qmode == 2) {
            __half* dh = g_vh + ((size_t)bhx * Tz + t0) * HDz;
            __half* dl = g_vl + ((size_t)bhx * Tz + t0) * HDz;
#pragma unroll
            for (int rr = 0; rr < 16; ++rr) {
                const int row = wid * 16 + rr;
                float4 v = *(const float4*)&Sf[row * 132 + lid * 4];
                uint32_t h0, l0, h1, l1;
                split2h(v.x, v.y, h0, l0);
                split2h(v.z, v.w, h1, l1);
                *(uint32_t*)(dh + (size_t)row * HDz + lid * 4)     = h0;
                *(uint32_t*)(dh + (size_t)row * HDz + lid * 4 + 2) = h1;
                *(uint32_t*)(dl + (size_t)row * HDz + lid * 4)     = l0;
                *(uint32_t*)(dl + (size_t)row * HDz + lid * 4 + 2) = l1;
            }
        } else {
            // Fused RoPE: rotate pairs (d, d+64); q: scale + hi/lo; k: hi only
            const bool isq = (qmode == 0);
            __half* dh = (isq ? g_qh : g_kh) + ((size_t)bhx * Tz + t0) * HDz;
            __half* dl = g_ql + ((size_t)bhx * Tz + t0) * HDz;   // used iff isq
            const int row = tid >> 1;
            const int db  = (tid & 1) * 32;
            const int t   = t0 + row;
            const float sc = isq ? 0.08838834764831845f : 1.0f;
            const float* crow_ = cosT + t * HDz + db;
            const float* srow_ = sinT + t * HDz + db;
            const float* Sr = Sf + row * 132 + db;
            __half* ph = dh + (size_t)row * HDz + db;
            __half* pl = dl + (size_t)row * HDz + db;
#pragma unroll
            for (int dd = 0; dd < 32; dd += 2) {
                float c0 = crow_[dd], c1 = crow_[dd + 1];
                float s0 = srow_[dd], s1 = srow_[dd + 1];
                float x0 = Sr[dd],      x1 = Sr[dd + 1];
                float y0 = Sr[dd + 64], y1 = Sr[dd + 65];
                float r0 = (x0 * c0 - y0 * s0) * sc;
                float r1 = (x1 * c1 - y1 * s1) * sc;
                float u0 = (y0 * c0 + x0 * s0) * sc;
                float u1 = (y1 * c1 + x1 * s1) * sc;
                if (isq) {
                    uint32_t hi, lo;
                    split2h(r0, r1, hi, lo);
                    *(uint32_t*)(ph + dd)      = hi;
                    *(uint32_t*)(pl + dd)      = lo;
                    split2h(u0, u1, hi, lo);
                    *(uint32_t*)(ph + dd + 64) = hi;
                    *(uint32_t*)(pl + dd + 64) = lo;
                } else {
                    *(uint32_t*)(ph + dd)      = pack2h(r0, r1);
                    *(uint32_t*)(ph + dd + 64) = pack2h(u0, u1);
                }
            }
        }
    }
}

// ---------------------------------------------------------------------------
// Causal flash attention on tensor cores (fp16 2-term).
// S = (Qh+Ql)*Kh^T;  O += Ph*(Vh+Vl).
// BM=128 (8 warps x 16 rows), BN=64, HD=128, 256 threads.
// Q hi/lo resident in SMEM; {Kh, Vh, Vl} double-buffered cp.async.
// Row pitch 136 fp16 (272B = 17 x 16B chunks -> conflict-free ldmatrix).
// Output written as fp16 (hi only) for the fp16 1-term out-projection.
// ---------------------------------------------------------------------------
#define APB   272
#define QSZ   (128 * APB)       // 34816
#define KSZ   (64 * APB)        // 17408
#define ATTN_SMEM2 (2 * QSZ + 2 * 3 * KSZ)   // 174080

__global__ __launch_bounds__(256, 1)
void attn_mma()
{
    extern __shared__ char smc[];
    const uint32_t sb = smem_u32(smc);
    const int tid = threadIdx.x;
    const int wid = tid >> 5;
    const int lid = tid & 31;
    const int bh  = blockIdx.y;
    const int qb  = (int)gridDim.x - 1 - (int)blockIdx.x;  // big blocks first
    const int q0  = qb * 128;
    const int ntiles = 2 * qb + 2;

    const __half* qh_g = g_qh + ((size_t)bh * Tz + q0) * HDz;
    const __half* ql_g = g_ql + ((size_t)bh * Tz + q0) * HDz;
    const __half* kh_g = g_kh + (size_t)bh * Tz * HDz;
    const __half* vh_g = g_vh + (size_t)bh * Tz * HDz;
    const __half* vl_g = g_vl + (size_t)bh * Tz * HDz;

    const uint32_t sQh = sb;
    const uint32_t sQl = sb + QSZ;
    const uint32_t sStage = sb + 2 * QSZ;

#pragma unroll
    for (int i = 0; i < 8; ++i) {
        int cc = i * 256 + tid;
        int row = cc >> 4, col = cc & 15;
        CP16(sQh + row * APB + col * 16, qh_g + (size_t)row * HDz + col * 8);
    }
#pragma unroll
    for (int i = 0; i < 8; ++i) {
        int cc = i * 256 + tid;
        int row = cc >> 4, col = cc & 15;
        CP16(sQl + row * APB + col * 16, ql_g + (size_t)row * HDz + col * 8);
    }
    CP_COMMIT();

    auto load_stage = [&](int stage, int j0) {
        const uint32_t base = sStage + stage * (3 * KSZ);
        const __half* gp0 = kh_g + (size_t)j0 * HDz;
        const __half* gp1 = vh_g + (size_t)j0 * HDz;
        const __half* gp2 = vl_g + (size_t)j0 * HDz;
#pragma unroll
        for (int i = 0; i < 4; ++i) {
            int cc = i * 256 + tid;
            int row = cc >> 4, col = cc & 15;
            uint32_t so = (uint32_t)(row * APB + col * 16);
            size_t go = (size_t)row * HDz + col * 8;
            CP16(base + so,           gp0 + go);
            CP16(base + KSZ + so,     gp1 + go);
            CP16(base + 2*KSZ + so,   gp2 + go);
        }
    };

    load_stage(0, 0);
    CP_COMMIT();

    const int qq = lid >> 3;
    const int r8 = lid & 7;
    const int g  = lid >> 2;
    const int t4 = lid & 3;
    const uint32_t qa_off  = (uint32_t)((wid * 16 + (qq & 1) * 8 + r8) * APB);
    const uint32_t ka_row  = (uint32_t)(((qq >> 1) * 8 + r8) * APB);
    const uint32_t va_off  = (uint32_t)((((lid >> 3) & 1) * 8 + (lid & 7)) * APB
                                        + (lid >> 4) * 16);

    float m0v = -1e30f, m1v = -1e30f, l0v = 0.f, l1v = 0.f;
    float o[16][4];
#pragma unroll
    for (int i = 0; i < 16; i++)
#pragma unroll
        for (int j = 0; j < 4; j++) o[i][j] = 0.f;

    for (int kt = 0; kt < ntiles; ++kt) {
        if (kt + 1 < ntiles) {
            load_stage((kt + 1) & 1, (kt + 1) * 64);
            CP_COMMIT();
            CP_WAIT(1);
        } else {
            CP_WAIT(0);
        }
        __syncthreads();

        const uint32_t sK  = sStage + (kt & 1) * (3 * KSZ);
        const uint32_t sKh = sK;
        const uint32_t sVh = sK + KSZ;
        const uint32_t sVl = sK + 2 * KSZ;

        const bool active = !(kt == ntiles - 1 && wid < 4);
        if (active) {
            // ---- S = (Qh+Ql) Kh^T ----
            float sf[8][4];
#pragma unroll
            for (int i = 0; i < 8; i++)
#pragma unroll
                for (int j = 0; j < 4; j++) sf[i][j] = 0.f;

#pragma unroll
            for (int kk = 0; kk < 8; ++kk) {
                const uint32_t acol = (uint32_t)((kk * 2 + (qq >> 1)) * 16);
                const uint32_t kcol = (uint32_t)((kk * 2 + (qq & 1)) * 16);
                uint32_t ah0,ah1,ah2,ah3, al0,al1,al2,al3;
                LDSM4(ah0,ah1,ah2,ah3, sQh + qa_off + acol);
                LDSM4(al0,al1,al2,al3, sQl + qa_off + acol);
#pragma unroll
                for (int h2 = 0; h2 < 2; ++h2) {
                    uint32_t b0h[4], b1h[4];
                    const uint32_t r0 = (uint32_t)((2*h2) * 16 * APB);
                    const uint32_t r1 = (uint32_t)((2*h2 + 1) * 16 * APB);
                    LDSM4(b0h[0],b0h[1],b0h[2],b0h[3], sKh + ka_row + r0 + kcol);
                    LDSM4(b1h[0],b1h[1],b1h[2],b1h[3], sKh + ka_row + r1 + kcol);
                    MMAH4(sf[4*h2+0], ah0,ah1,ah2,ah3, b0h[0], b0h[1]);
                    MMAH4(sf[4*h2+1], ah0,ah1,ah2,ah3, b0h[2], b0h[3]);
                    MMAH4(sf[4*h2+2], ah0,ah1,ah2,ah3, b1h[0], b1h[1]);
                    MMAH4(sf[4*h2+3], ah0,ah1,ah2,ah3, b1h[2], b1h[3]);
                    MMAH4(sf[4*h2+0], al0,al1,al2,al3, b0h[0], b0h[1]);
                    MMAH4(sf[4*h2+1], al0,al1,al2,al3, b0h[2], b0h[3]);
                    MMAH4(sf[4*h2+2], al0,al1,al2,al3, b1h[0], b1h[1]);
                    MMAH4(sf[4*h2+3], al0,al1,al2,al3, b1h[2], b1h[3]);
                }
            }

            // ---- causal mask ----
            if (kt == ntiles - 2) {
                if (wid < 4) {
                    const int i0 = wid * 16 + g;
                    const int i1 = i0 + 8;
#pragma unroll
                    for (int ns = 0; ns < 8; ++ns) {
                        const int jc = ns * 8 + t4 * 2;
                        if (jc     > i0) sf[ns][0] = -1e30f;
                        if (jc + 1 > i0) sf[ns][1] = -1e30f;
                        if (jc     > i1) sf[ns][2] = -1e30f;
                        if (jc + 1 > i1) sf[ns][3] = -1e30f;
                    }
                }
            } else if (kt == ntiles - 1) {
                const int i0 = wid * 16 + g - 64;
                const int i1 = i0 + 8;
#pragma unroll
                for (int ns = 0; ns < 8; ++ns) {
                    const int jc = ns * 8 + t4 * 2;
                    if (jc     > i0) sf[ns][0] = -1e30f;
                    if (jc + 1 > i0) sf[ns][1] = -1e30f;
                    if (jc     > i1) sf[ns][2] = -1e30f;
                    if (jc + 1 > i1) sf[ns][3] = -1e30f;
                }
            }

            // ---- online softmax ----
            float rm0 = -1e30f, rm1 = -1e30f;
#pragma unroll
            for (int ns = 0; ns < 8; ++ns) {
                rm0 = fmaxf(rm0, fmaxf(sf[ns][0], sf[ns][1]));
                rm1 = fmaxf(rm1, fmaxf(sf[ns][2], sf[ns][3]));
            }
            rm0 = fmaxf(rm0, __shfl_xor_sync(0xffffffffu, rm0, 1));
            rm0 = fmaxf(rm0, __shfl_xor_sync(0xffffffffu, rm0, 2));
            rm1 = fmaxf(rm1, __shfl_xor_sync(0xffffffffu, rm1, 1));
            rm1 = fmaxf(rm1, __shfl_xor_sync(0xffffffffu, rm1, 2));
            const float mn0 = fmaxf(m0v, rm0);
            const float mn1 = fmaxf(m1v, rm1);
            const float corr0 = __expf(m0v - mn0);
            const float corr1 = __expf(m1v - mn1);
            m0v = mn0; m1v = mn1;
            float rs0 = 0.f, rs1 = 0.f;
#pragma unroll
            for (int ns = 0; ns < 8; ++ns) {
                float p0 = __expf(sf[ns][0] - mn0);
                float p1 = __expf(sf[ns][1] - mn0);
                float p2 = __expf(sf[ns][2] - mn1);
                float p3 = __expf(sf[ns][3] - mn1);
                sf[ns][0] = p0; sf[ns][1] = p1; sf[ns][2] = p2; sf[ns][3] = p3;
                rs0 += p0 + p1; rs1 += p2 + p3;
            }
            rs0 += __shfl_xor_sync(0xffffffffu, rs0, 1);
            rs0 += __shfl_xor_sync(0xffffffffu, rs0, 2);
            rs1 += __shfl_xor_sync(0xffffffffu, rs1, 1);
            rs1 += __shfl_xor_sync(0xffffffffu, rs1, 2);
            l0v = l0v * corr0 + rs0;
            l1v = l1v * corr1 + rs1;
#pragma unroll
            for (int ns = 0; ns < 16; ++ns) {
                o[ns][0] *= corr0; o[ns][1] *= corr0;
                o[ns][2] *= corr1; o[ns][3] *= corr1;
            }

            // ---- P fragments (fp16 hi only; P in [0,1]) ----
            uint32_t pah[4][4];
#pragma unroll
            for (int kk = 0; kk < 4; ++kk) {
                pah[kk][0] = pack2h(sf[2*kk][0],   sf[2*kk][1]);
                pah[kk][1] = pack2h(sf[2*kk][2],   sf[2*kk][3]);
                pah[kk][2] = pack2h(sf[2*kk+1][0], sf[2*kk+1][1]);
                pah[kk][3] = pack2h(sf[2*kk+1][2], sf[2*kk+1][3]);
            }

            // ---- O += Ph (Vh + Vl) ----
#pragma unroll
            for (int kk = 0; kk < 4; ++kk) {
                const uint32_t vrow = (uint32_t)(kk * 16 * APB) + va_off;
#pragma unroll
                for (int dp = 0; dp < 4; ++dp) {
                    uint32_t v0h[4], v1h[4], v0l[4], v1l[4];
                    LDSM4T(v0h[0],v0h[1],v0h[2],v0h[3], sVh + vrow + dp*64);
                    LDSM4T(v1h[0],v1h[1],v1h[2],v1h[3], sVh + vrow + dp*64 + 32);
                    LDSM4T(v0l[0],v0l[1],v0l[2],v0l[3], sVl + vrow + dp*64);
                    LDSM4T(v1l[0],v1l[1],v1l[2],v1l[3], sVl + vrow + dp*64 + 32);
                    MMAH4(o[4*dp+0], pah[kk][0],pah[kk][1],pah[kk][2],pah[kk][3], v0h[0], v0h[1]);
                    MMAH4(o[4*dp+1], pah[kk][0],pah[kk][1],pah[kk][2],pah[kk][3], v0h[2], v0h[3]);
                    MMAH4(o[4*dp+2], pah[kk][0],pah[kk][1],pah[kk][2],pah[kk][3], v1h[0], v1h[1]);
                    MMAH4(o[4*dp+3], pah[kk][0],pah[kk][1],pah[kk][2],pah[kk][3], v1h[2], v1h[3]);
                    MMAH4(o[4*dp+0], pah[kk][0],pah[kk][1],pah[kk][2],pah[kk][3], v0l[0], v0l[1]);
                    MMAH4(o[4*dp+1], pah[kk][0],pah[kk][1],pah[kk][2],pah[kk][3], v0l[2], v0l[3]);
                    MMAH4(o[4*dp+2], pah[kk][0],pah[kk][1],pah[kk][2],pah[kk][3], v1l[0], v1l[1]);
                    MMAH4(o[4*dp+3], pah[kk][0],pah[kk][1],pah[kk][2],pah[kk][3], v1l[2], v1l[3]);
                }
            }
        }
        __syncthreads();
    }

    // Finalize + store fp16 (hi only) for the fp16 1-term out-projection
    const int b  = bh >> 4;
    const int hh = bh & 15;
    const float inv0 = 1.f / l0v;
    const float inv1 = 1.f / l1v;
    const size_t rb0 = ((size_t)b * Tz + q0 + wid * 16 + g) * Dz + hh * HDz;
    const size_t rb1 = rb0 + (size_t)8 * Dz;
#pragma unroll
    for (int ns = 0; ns < 16; ++ns) {
        const int dcol = ns * 8 + t4 * 2;
        *(uint32_t*)(g_oh + rb0 + dcol) = pack2h(o[ns][0] * inv0, o[ns][1] * inv0);
        *(uint32_t*)(g_oh + rb1 + dcol) = pack2h(o[ns][2] * inv1, o[ns][3] * inv1);
    }
}

// ---------------------------------------------------------------------------
extern "C" void kernel_launch(void* const* d_in, const int* in_sizes, int n_in,
                              void* d_out, int out_size)
{
    const float* x     = (const float*)d_in[0];
    const float* cosT  = (const float*)d_in[1];
    const float* sinT  = (const float*)d_in[2];
    const float* w_qkv = (const float*)d_in[3];
    const float* w_out = (const float*)d_in[4];
    float* out = (float*)d_out;

    cudaFuncSetAttribute(mma_gemm<0>,
                         cudaFuncAttributeMaxDynamicSharedMemorySize, GSMEM);
    cudaFuncSetAttribute(mma_gemm<1>,
                         cudaFuncAttributeMaxDynamicSharedMemorySize, GSMEM);
    cudaFuncSetAttribute(attn_mma,
                         cudaFuncAttributeMaxDynamicSharedMemorySize, ATTN_SMEM2);

    // 0. Convert inputs to fp16 (hi only)
    split_kernel<0><<<(Mz * Dz) / 1024, 256>>>(x, (size_t)Mz * Dz);
    split_kernel<1><<<(3 * Dz * Dz) / 1024, 256>>>(w_qkv, (size_t)3 * Dz * Dz);
    split_kernel<2><<<(Dz * Dz) / 1024, 256>>>(w_out, (size_t)Dz * Dz);

    // 1. QKV projection (fp16 1-term, 2 CTAs/SM) + fused RoPE epilogue
    mma_gemm<0><<<dim3(48, 64), 256, GSMEM>>>(nullptr, cosT, sinT);

    // 2. Causal flash attention (fp16 2-term tensor cores) -> o fp16
    attn_mma<<<dim3(Tz / 128, BHz), 256, ATTN_SMEM2>>>();

    // 3. Output projection (fp16 1-term, 2 CTAs/SM)
    mma_gemm<1><<<dim3(16, 64), 256, GSMEM>>>(out, nullptr, nullptr);
}

// round 16
// speedup vs baseline: 2.3488x; 1.0037x over previous
#include <cuda_runtime.h>
#include <cuda_bf16.h>
#include <cuda_fp16.h>
#include <math_constants.h>
#include <cstdint>

// Problem constants
#define Bz  4
#define Tz  2048
#define Dz  2048
#define Hz  16
#define HDz 128
#define BHz (Bz*Hz)          // 64
#define Mz  (Bz*Tz)          // 8192

// ---------------------------------------------------------------------------
// Global scratch (device globals: allocation-free per harness rules)
// ---------------------------------------------------------------------------
// Attention operands (fp16): Q hi/lo, K hi only, V hi/lo
__device__ __half g_qh[(size_t)BHz * Tz * HDz];
__device__ __half g_ql[(size_t)BHz * Tz * HDz];
__device__ __half g_kh[(size_t)BHz * Tz * HDz];
__device__ __half g_vh[(size_t)BHz * Tz * HDz];
__device__ __half g_vl[(size_t)BHz * Tz * HDz];

// GEMM operands: fp16 hi only (1-term path: Ah*Bh)
__device__ __half g_xh [(size_t)Mz * Dz];
__device__ __half g_wqh[(size_t)3 * Dz * Dz];
__device__ __half g_woh[(size_t)Dz * Dz];
__device__ __half g_oh [(size_t)Mz * Dz];   // attention out (fp16)

// ---------------------------------------------------------------------------
// PTX helpers (base sm_100 — NO 'a'-gated instructions)
// ---------------------------------------------------------------------------
__device__ __forceinline__ uint32_t smem_u32(const void* p) {
    uint32_t a;
    asm("{ .reg .u64 t; cvta.to.shared.u64 t, %1; cvt.u32.u64 %0, t; }"
        : "=r"(a) : "l"(p));
    return a;
}

#define CP16(saddr, gptr) \
    asm volatile("cp.async.cg.shared.global [%0], [%1], 16;" \
                 :: "r"(saddr), "l"(gptr) : "memory")
#define CP_COMMIT() asm volatile("cp.async.commit_group;" ::: "memory")
#define CP_WAIT(n)  asm volatile("cp.async.wait_group %0;" :: "n"(n) : "memory")

#define LDSM4(r0, r1, r2, r3, a) \
    asm volatile("ldmatrix.sync.aligned.m8n8.x4.shared.b16 {%0,%1,%2,%3}, [%4];" \
                 : "=r"(r0), "=r"(r1), "=r"(r2), "=r"(r3) : "r"(a))
#define LDSM4T(r0, r1, r2, r3, a) \
    asm volatile("ldmatrix.sync.aligned.m8n8.x4.trans.shared.b16 {%0,%1,%2,%3}, [%4];" \
                 : "=r"(r0), "=r"(r1), "=r"(r2), "=r"(r3) : "r"(a))

// fp16 mma, array A-frag form (projection GEMMs)
#define MMAH(d, a, b) \
    asm volatile("mma.sync.aligned.m16n8k16.row.col.f32.f16.f16.f32 " \
                 "{%0,%1,%2,%3}, {%4,%5,%6,%7}, {%8,%9}, {%0,%1,%2,%3};" \
                 : "+f"((d)[0]), "+f"((d)[1]), "+f"((d)[2]), "+f"((d)[3]) \
                 : "r"((a)[0]), "r"((a)[1]), "r"((a)[2]), "r"((a)[3]), \
                   "r"((b)[0]), "r"((b)[1]))

// fp16 mma, scalar-frag form (attention)
#define MMAH4(d, a0, a1, a2, a3, b0, b1) \
    asm volatile("mma.sync.aligned.m16n8k16.row.col.f32.f16.f16.f32 " \
                 "{%0,%1,%2,%3}, {%4,%5,%6,%7}, {%8,%9}, {%0,%1,%2,%3};" \
                 : "+f"((d)[0]), "+f"((d)[1]), "+f"((d)[2]), "+f"((d)[3]) \
                 : "r"(a0), "r"(a1), "r"(a2), "r"(a3), "r"(b0), "r"(b1))

// Split pair of floats into packed fp16 hi + fp16 lo (residual)
__device__ __forceinline__ void split2h(float x, float y, uint32_t& hi, uint32_t& lo) {
    __half hx = __float2half_rn(x);
    __half hy = __float2half_rn(y);
    __half2 H; H.x = hx; H.y = hy;
    hi = *(uint32_t*)&H;
    __half2 L;
    L.x = __float2half_rn(x - __half2float(hx));
    L.y = __float2half_rn(y - __half2float(hy));
    lo = *(uint32_t*)&L;
}

// Pack pair of floats into fp16x2 (hi only)
__device__ __forceinline__ uint32_t pack2h(float x, float y) {
    __half2 H; H.x = __float2half_rn(x); H.y = __float2half_rn(y);
    return *(uint32_t*)&H;
}

// ---------------------------------------------------------------------------
// Convert fp32 -> fp16 (hi only).  W=0: x, W=1: w_qkv, W=2: w_out.
// ---------------------------------------------------------------------------
template<int W>
__global__ void split_kernel(const float* __restrict__ src, size_t n)
{
    size_t i = ((size_t)blockIdx.x * 256 + threadIdx.x) * 4;
    if (i >= n) return;
    float4 v = *(const float4*)(src + i);
    __half* hi = (W == 0) ? g_xh : ((W == 1) ? g_wqh : g_woh);
    *(uint32_t*)(hi + i)     = pack2h(v.x, v.y);
    *(uint32_t*)(hi + i + 2) = pack2h(v.z, v.w);
}

// ---------------------------------------------------------------------------
// fp16 1-term tensor-core GEMM.  C = Ah * Bh^T.  128x128 CTA tile,
// 8 warps (2x4), warp tile 64x32, K processed in PAIRS of 32-chunks per
// synchronization (4 chunk-buffers = 2 pair-slots, pair-level double
// buffering): wait(1) / sync / consume 2 chunks / sync / prefetch pair /
// commit.  2 CTAs/SM.  RPITCH=80 (conflict-free ldmatrix, no swizzle).
// MODE 0: A=x, B=w_qkv; epilogue: q -> RoPE+scale fp16 hi/lo; k -> RoPE fp16
//         hi only; v -> fp16 hi/lo.
// MODE 1: A=g_oh, B=w_out; epilogue writes C (fp32).
// ---------------------------------------------------------------------------
#define RPITCH   80
#define SBUF     (128 * RPITCH)          // 10240
#define STAGEB   (2 * SBUF)              // 20480: Ah, Bh (one 32-chunk)
#define PAIRB    (2 * STAGEB)            // 40960: one pair-slot (2 chunks)
#define GSMEM    (2 * PAIRB)             // 81920 (epilogue Sf needs 67584)

template<int MODE>
__global__ __launch_bounds__(256, 2)
void mma_gemm(float* __restrict__ C,
              const float* __restrict__ cosT,
              const float* __restrict__ sinT)
{
    extern __shared__ char smc[];
    const uint32_t sb = smem_u32(smc);
    const int tid = threadIdx.x;
    const int wid = tid >> 5;
    const int lid = tid & 31;
    const int wm  = wid & 1;          // 0..1  (64 rows each)
    const int wn  = wid >> 1;         // 0..3  (32 cols each)
    const int m0  = blockIdx.y * 128;
    const int n0  = blockIdx.x * 128;

    const __half* Ah = ((MODE == 0) ? g_xh  : g_oh ) + (size_t)m0 * 2048;
    const __half* Bh = ((MODE == 0) ? g_wqh : g_woh) + (size_t)n0 * 2048;

    const int crow = tid >> 1;
    const int cc0  = (tid & 1) * 2;
    const uint32_t soff = (uint32_t)(crow * RPITCH + cc0 * 16);

    // Load one PAIR (chunks 2p, 2p+1) into pair-slot `slot`.
    auto load_pair = [&](int slot, int p) {
        const uint32_t st = sb + slot * PAIRB;
#pragma unroll
        for (int cc2 = 0; cc2 < 2; ++cc2) {
            const uint32_t bu = st + cc2 * STAGEB;
            const size_t gi = (size_t)crow * 2048 + (2 * p + cc2) * 32 + cc0 * 8;
            CP16(bu + soff,             Ah + gi);
            CP16(bu + soff + 16,        Ah + gi + 8);
            CP16(bu + SBUF + soff,      Bh + gi);
            CP16(bu + SBUF + soff + 16, Bh + gi + 8);
        }
    };

    float d[4][4][4];
#pragma unroll
    for (int i = 0; i < 4; i++)
#pragma unroll
        for (int j = 0; j < 4; j++)
#pragma unroll
            for (int k = 0; k < 4; k++) d[i][j][k] = 0.f;

    // Prologue: fill both pair-slots (chunks 0..3)
    load_pair(0, 0); CP_COMMIT();
    load_pair(1, 1); CP_COMMIT();

    const int q  = lid >> 3;
    const int r8 = lid & 7;
    const int arow = wm * 64 + (q & 1) * 8 + r8;
    const int bfr  = q >> 1;
    const int bch  = q & 1;
    const int brow0 = wn * 32 + bfr * 8 + r8;

    for (int p = 0; p < 32; ++p) {
        CP_WAIT(1);
        __syncthreads();
        const uint32_t ps = sb + (p & 1) * PAIRB;

#pragma unroll
        for (int cc2 = 0; cc2 < 2; ++cc2) {
            const uint32_t st = ps + cc2 * STAGEB;
            const uint32_t sA = st;
            const uint32_t sB = st + SBUF;
#pragma unroll
            for (int kk = 0; kk < 2; ++kk) {
                const int ck = kk * 2;
                uint32_t ah[4][4], bh[4][2];
                const uint32_t aoff = (uint32_t)(arow * RPITCH + (ck + (q >> 1)) * 16);
#pragma unroll
                for (int mi = 0; mi < 4; ++mi)
                    LDSM4(ah[mi][0], ah[mi][1], ah[mi][2], ah[mi][3],
                          sA + aoff + mi * 16 * RPITCH);

                const uint32_t boff = (uint32_t)(brow0 * RPITCH + (ck + bch) * 16);
                {
                    uint32_t t0,t1,t2,t3;
                    LDSM4(t0,t1,t2,t3, sB + boff);
                    bh[0][0]=t0; bh[0][1]=t1; bh[1][0]=t2; bh[1][1]=t3;
                    LDSM4(t0,t1,t2,t3, sB + boff + 16 * RPITCH);
                    bh[2][0]=t0; bh[2][1]=t1; bh[3][0]=t2; bh[3][1]=t3;
                }
#pragma unroll
                for (int mi = 0; mi < 4; ++mi)
#pragma unroll
                    for (int ni = 0; ni < 4; ++ni)
                        MMAH(d[mi][ni], ah[mi], bh[ni]);
            }
        }
        __syncthreads();

        if (p + 2 < 32)
            load_pair(p & 1, p + 2);
        CP_COMMIT();
    }

    CP_WAIT(0);
    __syncthreads();

    // Stage fp32 tile in SMEM (pitch 132), then coalesced writers
    float* Sf = (float*)smc;
#pragma unroll
    for (int mi = 0; mi < 4; ++mi) {
        const int r0 = wm * 64 + mi * 16 + (lid >> 2);
#pragma unroll
        for (int ni = 0; ni < 4; ++ni) {
            const int c0 = wn * 32 + ni * 8 + (lid & 3) * 2;
            Sf[r0 * 132 + c0]           = d[mi][ni][0];
            Sf[r0 * 132 + c0 + 1]       = d[mi][ni][1];
            Sf[(r0 + 8) * 132 + c0]     = d[mi][ni][2];
            Sf[(r0 + 8) * 132 + c0 + 1] = d[mi][ni][3];
        }
    }
    __syncthreads();

    if (MODE == 1) {
#pragma unroll
        for (int rr = 0; rr < 16; ++rr) {
            const int row = wid * 16 + rr;
            float4 v = *(const float4*)&Sf[row * 132 + lid * 4];
            *(float4*)(C + (size_t)(m0 + row) * 2048 + n0 + lid * 4) = v;
        }
    } else {
        const int qmode = n0 >> 11;              // 0:q 1:k 2:v
        const int h     = (n0 & 2047) >> 7;
        const int b     = m0 >> 11;
        const int t0    = m0 & 2047;
        const int bhx   = b * Hz + h;
        if (qmode == 2) {
            __half* dh = g_vh + ((size_t)bhx * Tz + t0) * HDz;
            __half* dl = g_vl + ((size_t)bhx * Tz + t0) * HDz;
#pragma unroll
            for (int rr = 0; rr < 16; ++rr) {
                const int row = wid * 16 + rr;
                float4 v = *(const float4*)&Sf[row * 132 + lid * 4];
                uint32_t h0, l0, h1, l1;
                split2h(v.x, v.y, h0, l0);
                split2h(v.z, v.w, h1, l1);
                *(uint32_t*)(dh + (size_t)row * HDz + lid * 4)     = h0;
                *(uint32_t*)(dh + (size_t)row * HDz + lid * 4 + 2) = h1;
                *(uint32_t*)(dl + (size_t)row * HDz + lid * 4)     = l0;
                *(uint32_t*)(dl + (size_t)row * HDz + lid * 4 + 2) = l1;
            }
        } else {
            // Fused RoPE: rotate pairs (d, d+64); q: scale + hi/lo; k: hi only
            const bool isq = (qmode == 0);
            __half* dh = (isq ? g_qh : g_kh) + ((size_t)bhx * Tz + t0) * HDz;
            __half* dl = g_ql + ((size_t)bhx * Tz + t0) * HDz;   // used iff isq
            const int row = tid >> 1;
            const int db  = (tid & 1) * 32;
            const int t   = t0 + row;
            const float sc = isq ? 0.08838834764831845f : 1.0f;
            const float* crow_ = cosT + t * HDz + db;
            const float* srow_ = sinT + t * HDz + db;
            const float* Sr = Sf + row * 132 + db;
            __half* ph = dh + (size_t)row * HDz + db;
            __half* pl = dl + (size_t)row * HDz + db;
#pragma unroll
            for (int dd = 0; dd < 32; dd += 2) {
                float c0 = crow_[dd], c1 = crow_[dd + 1];
                float s0 = srow_[dd], s1 = srow_[dd + 1];
                float x0 = Sr[dd],      x1 = Sr[dd + 1];
                float y0 = Sr[dd + 64], y1 = Sr[dd + 65];
                float r0 = (x0 * c0 - y0 * s0) * sc;
                float r1 = (x1 * c1 - y1 * s1) * sc;
                float u0 = (y0 * c0 + x0 * s0) * sc;
                float u1 = (y1 * c1 + x1 * s1) * sc;
                if (isq) {
                    uint32_t hi, lo;
                    split2h(r0, r1, hi, lo);
                    *(uint32_t*)(ph + dd)      = hi;
                    *(uint32_t*)(pl + dd)      = lo;
                    split2h(u0, u1, hi, lo);
                    *(uint32_t*)(ph + dd + 64) = hi;
                    *(uint32_t*)(pl + dd + 64) = lo;
                } else {
                    *(uint32_t*)(ph + dd)      = pack2h(r0, r1);
                    *(uint32_t*)(ph + dd + 64) = pack2h(u0, u1);
                }
            }
        }
    }
}

// ---------------------------------------------------------------------------
// Causal flash attention on tensor cores (fp16 2-term).
// S = (Qh+Ql)*Kh^T;  O += Ph*(Vh+Vl).
// BM=128 (8 warps x 16 rows), BN=64, HD=128, 256 threads.
// Q hi/lo resident in SMEM; {Kh, Vh, Vl} double-buffered cp.async.
// Row pitch 136 fp16 (272B = 17 x 16B chunks -> conflict-free ldmatrix).
// Output written as fp16 (hi only) for the fp16 1-term out-projection.
// ---------------------------------------------------------------------------
#define APB   272
#define QSZ   (128 * APB)       // 34816
#define KSZ   (64 * APB)        // 17408
#define ATTN_SMEM2 (2 * QSZ + 2 * 3 * KSZ)   // 174080

__global__ __launch_bounds__(256, 1)
void attn_mma()
{
    extern __shared__ char smc[];
    const uint32_t sb = smem_u32(smc);
    const int tid = threadIdx.x;
    const int wid = tid >> 5;
    const int lid = tid & 31;
    const int bh  = blockIdx.y;
    const int qb  = (int)gridDim.x - 1 - (int)blockIdx.x;  // big blocks first
    const int q0  = qb * 128;
    const int ntiles = 2 * qb + 2;

    const __half* qh_g = g_qh + ((size_t)bh * Tz + q0) * HDz;
    const __half* ql_g = g_ql + ((size_t)bh * Tz + q0) * HDz;
    const __half* kh_g = g_kh + (size_t)bh * Tz * HDz;
    const __half* vh_g = g_vh + (size_t)bh * Tz * HDz;
    const __half* vl_g = g_vl + (size_t)bh * Tz * HDz;

    const uint32_t sQh = sb;
    const uint32_t sQl = sb + QSZ;
    const uint32_t sStage = sb + 2 * QSZ;

#pragma unroll
    for (int i = 0; i < 8; ++i) {
        int cc = i * 256 + tid;
        int row = cc >> 4, col = cc & 15;
        CP16(sQh + row * APB + col * 16, qh_g + (size_t)row * HDz + col * 8);
    }
#pragma unroll
    for (int i = 0; i < 8; ++i) {
        int cc = i * 256 + tid;
        int row = cc >> 4, col = cc & 15;
        CP16(sQl + row * APB + col * 16, ql_g + (size_t)row * HDz + col * 8);
    }
    CP_COMMIT();

    auto load_stage = [&](int stage, int j0) {
        const uint32_t base = sStage + stage * (3 * KSZ);
        const __half* gp0 = kh_g + (size_t)j0 * HDz;
        const __half* gp1 = vh_g + (size_t)j0 * HDz;
        const __half* gp2 = vl_g + (size_t)j0 * HDz;
#pragma unroll
        for (int i = 0; i < 4; ++i) {
            int cc = i * 256 + tid;
            int row = cc >> 4, col = cc & 15;
            uint32_t so = (uint32_t)(row * APB + col * 16);
            size_t go = (size_t)row * HDz + col * 8;
            CP16(base + so,           gp0 + go);
            CP16(base + KSZ + so,     gp1 + go);
            CP16(base + 2*KSZ + so,   gp2 + go);
        }
    };

    load_stage(0, 0);
    CP_COMMIT();

    const int qq = lid >> 3;
    const int r8 = lid & 7;
    const int g  = lid >> 2;
    const int t4 = lid & 3;
    const uint32_t qa_off  = (uint32_t)((wid * 16 + (qq & 1) * 8 + r8) * APB);
    const uint32_t ka_row  = (uint32_t)(((qq >> 1) * 8 + r8) * APB);
    const uint32_t va_off  = (uint32_t)((((lid >> 3) & 1) * 8 + (lid & 7)) * APB
                                        + (lid >> 4) * 16);

    float m0v = -1e30f, m1v = -1e30f, l0v = 0.f, l1v = 0.f;
    float o[16][4];
#pragma unroll
    for (int i = 0; i < 16; i++)
#pragma unroll
        for (int j = 0; j < 4; j++) o[i][j] = 0.f;

    for (int kt = 0; kt < ntiles; ++kt) {
        if (kt + 1 < ntiles) {
            load_stage((kt + 1) & 1, (kt + 1) * 64);
            CP_COMMIT();
            CP_WAIT(1);
        } else {
            CP_WAIT(0);
        }
        __syncthreads();

        const uint32_t sK  = sStage + (kt & 1) * (3 * KSZ);
        const uint32_t sKh = sK;
        const uint32_t sVh = sK + KSZ;
        const uint32_t sVl = sK + 2 * KSZ;

        const bool active = !(kt == ntiles - 1 && wid < 4);
        if (active) {
            // ---- S = (Qh+Ql) Kh^T ----
            float sf[8][4];
#pragma unroll
            for (int i = 0; i < 8; i++)
#pragma unroll
                for (int j = 0; j < 4; j++) sf[i][j] = 0.f;

#pragma unroll
            for (int kk = 0; kk < 8; ++kk) {
                const uint32_t acol = (uint32_t)((kk * 2 + (qq >> 1)) * 16);
                const uint32_t kcol = (uint32_t)((kk * 2 + (qq & 1)) * 16);
                uint32_t ah0,ah1,ah2,ah3, al0,al1,al2,al3;
                LDSM4(ah0,ah1,ah2,ah3, sQh + qa_off + acol);
                LDSM4(al0,al1,al2,al3, sQl + qa_off + acol);
#pragma unroll
                for (int h2 = 0; h2 < 2; ++h2) {
                    uint32_t b0h[4], b1h[4];
                    const uint32_t r0 = (uint32_t)((2*h2) * 16 * APB);
                    const uint32_t r1 = (uint32_t)((2*h2 + 1) * 16 * APB);
                    LDSM4(b0h[0],b0h[1],b0h[2],b0h[3], sKh + ka_row + r0 + kcol);
                    LDSM4(b1h[0],b1h[1],b1h[2],b1h[3], sKh + ka_row + r1 + kcol);
                    MMAH4(sf[4*h2+0], ah0,ah1,ah2,ah3, b0h[0], b0h[1]);
                    MMAH4(sf[4*h2+1], ah0,ah1,ah2,ah3, b0h[2], b0h[3]);
                    MMAH4(sf[4*h2+2], ah0,ah1,ah2,ah3, b1h[0], b1h[1]);
                    MMAH4(sf[4*h2+3], ah0,ah1,ah2,ah3, b1h[2], b1h[3]);
                    MMAH4(sf[4*h2+0], al0,al1,al2,al3, b0h[0], b0h[1]);
                    MMAH4(sf[4*h2+1], al0,al1,al2,al3, b0h[2], b0h[3]);
                    MMAH4(sf[4*h2+2], al0,al1,al2,al3, b1h[0], b1h[1]);
                    MMAH4(sf[4*h2+3], al0,al1,al2,al3, b1h[2], b1h[3]);
                }
            }

            // ---- causal mask ----
            if (kt == ntiles - 2) {
                if (wid < 4) {
                    const int i0 = wid * 16 + g;
                    const int i1 = i0 + 8;
#pragma unroll
                    for (int ns = 0; ns < 8; ++ns) {
                        const int jc = ns * 8 + t4 * 2;
                        if (jc     > i0) sf[ns][0] = -1e30f;
                        if (jc + 1 > i0) sf[ns][1] = -1e30f;
                        if (jc     > i1) sf[ns][2] = -1e30f;
                        if (jc + 1 > i1) sf[ns][3] = -1e30f;
                    }
                }
            } else if (kt == ntiles - 1) {
                const int i0 = wid * 16 + g - 64;
                const int i1 = i0 + 8;
#pragma unroll
                for (int ns = 0; ns < 8; ++ns) {
                    const int jc = ns * 8 + t4 * 2;
                    if (jc     > i0) sf[ns][0] = -1e30f;
                    if (jc + 1 > i0) sf[ns][1] = -1e30f;
                    if (jc     > i1) sf[ns][2] = -1e30f;
                    if (jc + 1 > i1) sf[ns][3] = -1e30f;
                }
            }

            // ---- online softmax ----
            float rm0 = -1e30f, rm1 = -1e30f;
#pragma unroll
            for (int ns = 0; ns < 8; ++ns) {
                rm0 = fmaxf(rm0, fmaxf(sf[ns][0], sf[ns][1]));
                rm1 = fmaxf(rm1, fmaxf(sf[ns][2], sf[ns][3]));
            }
            rm0 = fmaxf(rm0, __shfl_xor_sync(0xffffffffu, rm0, 1));
            rm0 = fmaxf(rm0, __shfl_xor_sync(0xffffffffu, rm0, 2));
            rm1 = fmaxf(rm1, __shfl_xor_sync(0xffffffffu, rm1, 1));
            rm1 = fmaxf(rm1, __shfl_xor_sync(0xffffffffu, rm1, 2));
            const float mn0 = fmaxf(m0v, rm0);
            const float mn1 = fmaxf(m1v, rm1);
            const float corr0 = __expf(m0v - mn0);
            const float corr1 = __expf(m1v - mn1);
            m0v = mn0; m1v = mn1;
            float rs0 = 0.f, rs1 = 0.f;
#pragma unroll
            for (int ns = 0; ns < 8; ++ns) {
                float p0 = __expf(sf[ns][0] - mn0);
                float p1 = __expf(sf[ns][1] - mn0);
                float p2 = __expf(sf[ns][2] - mn1);
                float p3 = __expf(sf[ns][3] - mn1);
                sf[ns][0] = p0; sf[ns][1] = p1; sf[ns][2] = p2; sf[ns][3] = p3;
                rs0 += p0 + p1; rs1 += p2 + p3;
            }
            rs0 += __shfl_xor_sync(0xffffffffu, rs0, 1);
            rs0 += __shfl_xor_sync(0xffffffffu, rs0, 2);
            rs1 += __shfl_xor_sync(0xffffffffu, rs1, 1);
            rs1 += __shfl_xor_sync(0xffffffffu, rs1, 2);
            l0v = l0v * corr0 + rs0;
            l1v = l1v * corr1 + rs1;
#pragma unroll
            for (int ns = 0; ns < 16; ++ns) {
                o[ns][0] *= corr0; o[ns][1] *= corr0;
                o[ns][2] *= corr1; o[ns][3] *= corr1;
            }

            // ---- P fragments (fp16 hi only; P in [0,1]) ----
            uint32_t pah[4][4];
#pragma unroll
            for (int kk = 0; kk < 4; ++kk) {
                pah[kk][0] = pack2h(sf[2*kk][0],   sf[2*kk][1]);
                pah[kk][1] = pack2h(sf[2*kk][2],   sf[2*kk][3]);
                pah[kk][2] = pack2h(sf[2*kk+1][0], sf[2*kk+1][1]);
                pah[kk][3] = pack2h(sf[2*kk+1][2], sf[2*kk+1][3]);
            }

            // ---- O += Ph (Vh + Vl) ----
#pragma unroll
            for (int kk = 0; kk < 4; ++kk) {
                const uint32_t vrow = (uint32_t)(kk * 16 * APB) + va_off;
#pragma unroll
                for (int dp = 0; dp < 4; ++dp) {
                    uint32_t v0h[4], v1h[4], v0l[4], v1l[4];
                    LDSM4T(v0h[0],v0h[1],v0h[2],v0h[3], sVh + vrow + dp*64);
                    LDSM4T(v1h[0],v1h[1],v1h[2],v1h[3], sVh + vrow + dp*64 + 32);
                    LDSM4T(v0l[0],v0l[1],v0l[2],v0l[3], sVl + vrow + dp*64);
                    LDSM4T(v1l[0],v1l[1],v1l[2],v1l[3], sVl + vrow + dp*64 + 32);
                    MMAH4(o[4*dp+0], pah[kk][0],pah[kk][1],pah[kk][2],pah[kk][3], v0h[0], v0h[1]);
                    MMAH4(o[4*dp+1], pah[kk][0],pah[kk][1],pah[kk][2],pah[kk][3], v0h[2], v0h[3]);
                    MMAH4(o[4*dp+2], pah[kk][0],pah[kk][1],pah[kk][2],pah[kk][3], v1h[0], v1h[1]);
                    MMAH4(o[4*dp+3], pah[kk][0],pah[kk][1],pah[kk][2],pah[kk][3], v1h[2], v1h[3]);
                    MMAH4(o[4*dp+0], pah[kk][0],pah[kk][1],pah[kk][2],pah[kk][3], v0l[0], v0l[1]);
                    MMAH4(o[4*dp+1], pah[kk][0],pah[kk][1],pah[kk][2],pah[kk][3], v0l[2], v0l[3]);
                    MMAH4(o[4*dp+2], pah[kk][0],pah[kk][1],pah[kk][2],pah[kk][3], v1l[0], v1l[1]);
                    MMAH4(o[4*dp+3], pah[kk][0],pah[kk][1],pah[kk][2],pah[kk][3], v1l[2], v1l[3]);
                }
            }
        }
        __syncthreads();
    }

    // Finalize + store fp16 (hi only) for the fp16 1-term out-projection
    const int b  = bh >> 4;
    const int hh = bh & 15;
    const float inv0 = 1.f / l0v;
    const float inv1 = 1.f / l1v;
    const size_t rb0 = ((size_t)b * Tz + q0 + wid * 16 + g) * Dz + hh * HDz;
    const size_t rb1 = rb0 + (size_t)8 * Dz;
#pragma unroll
    for (int ns = 0; ns < 16; ++ns) {
        const int dcol = ns * 8 + t4 * 2;
        *(uint32_t*)(g_oh + rb0 + dcol) = pack2h(o[ns][0] * inv0, o[ns][1] * inv0);
        *(uint32_t*)(g_oh + rb1 + dcol) = pack2h(o[ns][2] * inv1, o[ns][3] * inv1);
    }
}

// ---------------------------------------------------------------------------
extern "C" void kernel_launch(void* const* d_in, const int* in_sizes, int n_in,
                              void* d_out, int out_size)
{
    const float* x     = (const float*)d_in[0];
    const float* cosT  = (const float*)d_in[1];
    const float* sinT  = (const float*)d_in[2];
    const float* w_qkv = (const float*)d_in[3];
    const float* w_out = (const float*)d_in[4];
    float* out = (float*)d_out;

    cudaFuncSetAttribute(mma_gemm<0>,
                         cudaFuncAttributeMaxDynamicSharedMemorySize, GSMEM);
    cudaFuncSetAttribute(mma_gemm<1>,
                         cudaFuncAttributeMaxDynamicSharedMemorySize, GSMEM);
    cudaFuncSetAttribute(attn_mma,
                         cudaFuncAttributeMaxDynamicSharedMemorySize, ATTN_SMEM2);

    // 0. Convert inputs to fp16 (hi only)
    split_kernel<0><<<(Mz * Dz) / 1024, 256>>>(x, (size_t)Mz * Dz);
    split_kernel<1><<<(3 * Dz * Dz) / 1024, 256>>>(w_qkv, (size_t)3 * Dz * Dz);
    split_kernel<2><<<(Dz * Dz) / 1024, 256>>>(w_out, (size_t)Dz * Dz);

    // 1. QKV projection (fp16 1-term, paired chunks, 2 CTAs/SM) + fused RoPE
    mma_gemm<0><<<dim3(48, 64), 256, GSMEM>>>(nullptr, cosT, sinT);

    // 2. Causal flash attention (fp16 2-term tensor cores) -> o fp16
    attn_mma<<<dim3(Tz / 128, BHz), 256, ATTN_SMEM2>>>();

    // 3. Output projection (fp16 1-term, paired chunks, 2 CTAs/SM)
    mma_gemm<1><<<dim3(16, 64), 256, GSMEM>>>(out, nullptr, nullptr);
}